// round 4
// baseline (speedup 1.0000x reference)
#include <cuda_runtime.h>
#include <cuda_bf16.h>

// Problem constants
#define Bc  2
#define Sc  2048
#define Dc  2048
#define Hc  16
#define HDc 128
#define QRc 12
#define Rc  2

// ---------------------------------------------------------------------------
// Device scratch (no cudaMalloc allowed). ~43 MB total.
// ---------------------------------------------------------------------------
__device__ float g_Aq[(size_t)Bc*Sc*Hc*QRc];     //  786,432
__device__ float g_Ak[(size_t)Bc*Sc*Hc*Rc];      //  131,072
__device__ float g_Av[(size_t)Bc*Sc*Hc*Rc];      //  131,072
__device__ float g_Bq[(size_t)Bc*Sc*QRc*HDc];    // 6,291,456
__device__ float g_Bk[(size_t)Bc*Sc*Rc*HDc];     // 1,048,576
__device__ float g_Bv[(size_t)Bc*Sc*Rc*HDc];     // 1,048,576
__device__ float g_q [(size_t)Bc*Sc*Hc*HDc];     // 8,388,608
__device__ float g_k [(size_t)Bc*Sc*Hc*HDc];     // 8,388,608  (b,s,h,d)
__device__ float g_v [(size_t)Bc*Sc*Hc*HDc];     // 8,388,608
__device__ float g_att[(size_t)Bc*Sc*Hc*HDc];    // 8,388,608

// ---------------------------------------------------------------------------
// Generic batched/strided SGEMM: C = A(MxK) * B(KxN), row-major w/ leading dims.
// Requirements (guaranteed by call sites): M % 128 == 0, K % 16 == 0, N % 4 == 0.
// ---------------------------------------------------------------------------
#define BM 128
#define BN 128
#define BK 16
#define TM 8
#define TN 8

__global__ __launch_bounds__(256) void sgemm_kernel(
    const float* __restrict__ A, const float* __restrict__ B, float* __restrict__ C,
    int M, int N, int K, int lda, int ldb, int ldc)
{
    int m0 = blockIdx.y * BM;
    int n0 = blockIdx.x * BN;

    __shared__ float As[BK][BM + 4];
    __shared__ float Bs[BK][BN];

    int tid = threadIdx.x;
    int tm = tid >> 4;        // 0..15
    int tn = tid & 15;        // 0..15

    float acc[TM][TN];
#pragma unroll
    for (int i = 0; i < TM; i++)
#pragma unroll
        for (int j = 0; j < TN; j++) acc[i][j] = 0.f;

    for (int kt = 0; kt < K; kt += BK) {
#pragma unroll
        for (int l = 0; l < 2; l++) {
            int v = tid + l * 256;
            // A tile: 128 rows x 16 k  (512 float4)
            int row = v >> 2, kq = (v & 3) << 2;
            float4 av = *(const float4*)(A + (size_t)(m0 + row) * lda + kt + kq);
            As[kq + 0][row] = av.x;
            As[kq + 1][row] = av.y;
            As[kq + 2][row] = av.z;
            As[kq + 3][row] = av.w;
            // B tile: 16 k x 128 n  (512 float4)
            int kk = v >> 5, nq = (v & 31) << 2;
            float4 bv = make_float4(0.f, 0.f, 0.f, 0.f);
            if (n0 + nq < N)
                bv = *(const float4*)(B + (size_t)(kt + kk) * ldb + n0 + nq);
            *(float4*)&Bs[kk][nq] = bv;
        }
        __syncthreads();

#pragma unroll
        for (int k = 0; k < BK; k++) {
            float a[TM], b[TN];
            *(float4*)&a[0] = *(const float4*)&As[k][tm * TM];
            *(float4*)&a[4] = *(const float4*)&As[k][tm * TM + 4];
            *(float4*)&b[0] = *(const float4*)&Bs[k][tn * TN];
            *(float4*)&b[4] = *(const float4*)&Bs[k][tn * TN + 4];
#pragma unroll
            for (int i = 0; i < TM; i++)
#pragma unroll
                for (int j = 0; j < TN; j++)
                    acc[i][j] += a[i] * b[j];
        }
        __syncthreads();
    }

#pragma unroll
    for (int i = 0; i < TM; i++) {
        int m = m0 + tm * TM + i;
#pragma unroll
        for (int j = 0; j < TN; j += 4) {
            int n = n0 + tn * TN + j;
            if (n + 3 < N) {
                float4 cv = make_float4(acc[i][j], acc[i][j + 1], acc[i][j + 2], acc[i][j + 3]);
                *(float4*)(C + (size_t)m * ldc + n) = cv;
            } else {
#pragma unroll
                for (int jj = 0; jj < 4; jj++)
                    if (n + jj < N) C[(size_t)m * ldc + n + jj] = acc[i][j + jj];
            }
        }
    }
}

// ---------------------------------------------------------------------------
// Interleaved RoPE in-place on a (B,S,Rdim,HD) tensor.
// ---------------------------------------------------------------------------
__global__ void rope_kernel(float* __restrict__ t,
                            const float* __restrict__ fcos,
                            const float* __restrict__ fsin,
                            int Rdim, long long total)
{
    long long idx = (long long)blockIdx.x * blockDim.x + threadIdx.x;
    if (idx >= total) return;
    int i = (int)(idx % (HDc / 2));
    long long sr = idx / (HDc / 2);           // (b,s,r) with r fastest
    long long s  = (sr / Rdim) % Sc;
    float c  = fcos[s * (HDc / 2) + i];
    float sn = fsin[s * (HDc / 2) + i];
    float* p = t + sr * HDc + 2 * i;
    float t0 = p[0], t1 = p[1];
    p[0] = t0 * c - t1 * sn;
    p[1] = t0 * sn + t1 * c;
}

// ---------------------------------------------------------------------------
// Rank combine: q = (A_q x B_q)/QR, k = (A_k x B_k)/R, v = (A_v x B_v)/R
// all outputs in (b,s,h,d) layout. One thread per (b,s,h,d).
// ---------------------------------------------------------------------------
__global__ void combine_kernel(const float* __restrict__ Aq, const float* __restrict__ Ak,
                               const float* __restrict__ Av, const float* __restrict__ Bq,
                               const float* __restrict__ Bk, const float* __restrict__ Bv,
                               float* __restrict__ q, float* __restrict__ k,
                               float* __restrict__ v)
{
    long long idx = (long long)blockIdx.x * blockDim.x + threadIdx.x;
    const long long total = (long long)Bc * Sc * Hc * HDc;
    if (idx >= total) return;
    int d = (int)(idx % HDc);
    int h = (int)((idx / HDc) % Hc);
    long long bs = idx / ((long long)HDc * Hc);

    float accq = 0.f;
#pragma unroll
    for (int r = 0; r < QRc; r++)
        accq += Aq[bs * (Hc * QRc) + h * QRc + r] * Bq[(bs * QRc + r) * HDc + d];
    q[idx] = accq * (1.0f / QRc);

    float acck = 0.f, accv = 0.f;
#pragma unroll
    for (int r = 0; r < Rc; r++) {
        acck += Ak[bs * (Hc * Rc) + h * Rc + r] * Bk[(bs * Rc + r) * HDc + d];
        accv += Av[bs * (Hc * Rc) + h * Rc + r] * Bv[(bs * Rc + r) * HDc + d];
    }
    k[idx] = acck * (1.0f / Rc);
    v[idx] = accv * (1.0f / Rc);
}

// ---------------------------------------------------------------------------
// Fused causal flash attention, fp32.
// Block: 256 threads (8 warps). Tile: 64 q-rows x 64 k-cols, HD=128.
// Warp w owns q-rows [w*8, w*8+8). Within a warp:
//   S-compute: lane owns score cols {2*lane, 2*lane+1}.
//   PV/output: lane owns head-dim cols [4*lane, 4*lane+4).
// Smem: sQ[64][128] (pre-scaled by 1/sqrt(HD)),
//       sKV: K transposed [128][66] then reused as V [64][128],
//       sS [64][66] per-warp-private rows (no cross-warp sync needed for sS).
// grid = (Sc/64, Bc*Hc); m-tile index inverted so longest blocks launch first.
// ---------------------------------------------------------------------------
#define FBM 64
#define FBN 64
#define FTHREADS 256
#define KT_LD (FBN + 2)
#define SS_LD (FBN + 2)
#define FLASH_SMEM_BYTES ((FBM*HDc + HDc*KT_LD + FBM*SS_LD) * (int)sizeof(float))

__global__ __launch_bounds__(FTHREADS) void flash_kernel(
    const float* __restrict__ q, const float* __restrict__ k,
    const float* __restrict__ v, float* __restrict__ att)
{
    extern __shared__ float fsmem[];
    float* sQ  = fsmem;                 // FBM*HDc
    float* sKV = sQ + FBM * HDc;        // HDc*KT_LD (K^T) / FBM*HDc (V)
    float* sS  = sKV + HDc * KT_LD;     // FBM*SS_LD

    int mt = gridDim.x - 1 - blockIdx.x;       // long blocks first
    int m0 = mt * FBM;
    int bh = blockIdx.y;
    int b  = bh / Hc, h = bh % Hc;

    int tid  = threadIdx.x;
    int warp = tid >> 5;
    int lane = tid & 31;
    int rowbase = warp * 8;

    const float scale = 0.08838834764831845f;  // 1/sqrt(128)

    // ---- load Q tile (pre-scaled) ----
    for (int it = tid; it < FBM * (HDc / 4); it += FTHREADS) {
        int row = it >> 5;
        int dq  = (it & 31) << 2;
        float4 val = *(const float4*)(q + (((size_t)b * Sc + m0 + row) * Hc + h) * HDc + dq);
        float* dst = sQ + row * HDc + dq;
        dst[0] = val.x * scale; dst[1] = val.y * scale;
        dst[2] = val.z * scale; dst[3] = val.w * scale;
    }

    float acc[8][4];
#pragma unroll
    for (int i = 0; i < 8; i++)
#pragma unroll
        for (int c = 0; c < 4; c++) acc[i][c] = 0.f;
    float m_i[8], l_i[8];
#pragma unroll
    for (int i = 0; i < 8; i++) { m_i[i] = -1e30f; l_i[i] = 0.f; }

    int c0 = lane * 2, c1 = lane * 2 + 1;
    int cc = lane * 4;

    int nTiles = mt + 1;                       // causal: tiles n0 <= m0
    for (int t = 0; t < nTiles; t++) {
        int n0 = t * FBN;

        __syncthreads();                       // prev PV done with sKV
        // ---- load K tile transposed: sKV[d][n] ----
        for (int it = tid; it < FBN * (HDc / 4); it += FTHREADS) {
            int n  = it >> 5;
            int dq = (it & 31) << 2;
            float4 val = *(const float4*)(k + (((size_t)b * Sc + n0 + n) * Hc + h) * HDc + dq);
            sKV[(dq + 0) * KT_LD + n] = val.x;
            sKV[(dq + 1) * KT_LD + n] = val.y;
            sKV[(dq + 2) * KT_LD + n] = val.z;
            sKV[(dq + 3) * KT_LD + n] = val.w;
        }
        __syncthreads();

        // ---- S = Qs @ K^T (warp rows x 2 lane cols) ----
        float s0[8], s1[8];
#pragma unroll
        for (int i = 0; i < 8; i++) { s0[i] = 0.f; s1[i] = 0.f; }
        for (int d0 = 0; d0 < HDc; d0 += 4) {
            float kv0[4], kv1[4];
#pragma unroll
            for (int dd = 0; dd < 4; dd++) {
                kv0[dd] = sKV[(d0 + dd) * KT_LD + c0];
                kv1[dd] = sKV[(d0 + dd) * KT_LD + c1];
            }
#pragma unroll
            for (int i = 0; i < 8; i++) {
                float4 qv = *(const float4*)(sQ + (rowbase + i) * HDc + d0);
                s0[i] += qv.x * kv0[0] + qv.y * kv0[1] + qv.z * kv0[2] + qv.w * kv0[3];
                s1[i] += qv.x * kv1[0] + qv.y * kv1[1] + qv.z * kv1[2] + qv.w * kv1[3];
            }
        }

        // ---- causal mask (only the diagonal tile needs it) ----
        if (n0 == m0) {
#pragma unroll
            for (int i = 0; i < 8; i++) {
                if (c0 > rowbase + i) s0[i] = -1e30f;
                if (c1 > rowbase + i) s1[i] = -1e30f;
            }
        }

        // ---- online softmax update + write P to sS ----
#pragma unroll
        for (int i = 0; i < 8; i++) {
            float mx = fmaxf(s0[i], s1[i]);
#pragma unroll
            for (int o = 16; o; o >>= 1) mx = fmaxf(mx, __shfl_xor_sync(0xFFFFFFFFu, mx, o));
            float mnew = fmaxf(m_i[i], mx);
            float es = __expf(m_i[i] - mnew);
            float p0 = __expf(s0[i] - mnew);
            float p1 = __expf(s1[i] - mnew);
            float ps = p0 + p1;
#pragma unroll
            for (int o = 16; o; o >>= 1) ps += __shfl_xor_sync(0xFFFFFFFFu, ps, o);
            l_i[i] = l_i[i] * es + ps;
            m_i[i] = mnew;
#pragma unroll
            for (int c = 0; c < 4; c++) acc[i][c] *= es;
            sS[(rowbase + i) * SS_LD + c0] = p0;
            sS[(rowbase + i) * SS_LD + c1] = p1;
        }

        __syncthreads();                       // done reading sKV as K
        // ---- load V tile natural layout: sKV[n][d] ----
        for (int it = tid; it < FBN * (HDc / 4); it += FTHREADS) {
            int n  = it >> 5;
            int dq = (it & 31) << 2;
            *(float4*)(sKV + n * HDc + dq) =
                *(const float4*)(v + (((size_t)b * Sc + n0 + n) * Hc + h) * HDc + dq);
        }
        __syncthreads();

        // ---- acc += P @ V ----
        for (int j = 0; j < FBN; j += 2) {
            float4 v0 = *(const float4*)(sKV + j * HDc + cc);
            float4 v1 = *(const float4*)(sKV + (j + 1) * HDc + cc);
#pragma unroll
            for (int i = 0; i < 8; i++) {
                float p0 = sS[(rowbase + i) * SS_LD + j];
                float p1 = sS[(rowbase + i) * SS_LD + j + 1];
                acc[i][0] += p0 * v0.x + p1 * v1.x;
                acc[i][1] += p0 * v0.y + p1 * v1.y;
                acc[i][2] += p0 * v0.z + p1 * v1.z;
                acc[i][3] += p0 * v0.w + p1 * v1.w;
            }
        }
    }

    // ---- normalize + write output (b,s,h,d) ----
#pragma unroll
    for (int i = 0; i < 8; i++) {
        float inv = 1.0f / l_i[i];
        float4 o = make_float4(acc[i][0] * inv, acc[i][1] * inv,
                               acc[i][2] * inv, acc[i][3] * inv);
        *(float4*)(att + (((size_t)b * Sc + m0 + rowbase + i) * Hc + h) * HDc + cc) = o;
    }
}

// ---------------------------------------------------------------------------
// Launch
// ---------------------------------------------------------------------------
static void launch_gemm(const float* A, const float* Bm, float* C,
                        int M, int N, int K, int lda, int ldb, int ldc)
{
    dim3 g((N + BN - 1) / BN, (M + BM - 1) / BM, 1);
    sgemm_kernel<<<g, 256>>>(A, Bm, C, M, N, K, lda, ldb, ldc);
}

extern "C" void kernel_launch(void* const* d_in, const int* in_sizes, int n_in,
                              void* d_out, int out_size)
{
    const float* x    = (const float*)d_in[0];
    const float* fcos = (const float*)d_in[1];
    const float* fsin = (const float*)d_in[2];
    // d_in[3] = mask (causality handled analytically)
    const float* WAq  = (const float*)d_in[4];
    const float* WAk  = (const float*)d_in[5];
    const float* WAv  = (const float*)d_in[6];
    const float* WBq  = (const float*)d_in[7];
    const float* WBk  = (const float*)d_in[8];
    const float* WBv  = (const float*)d_in[9];
    const float* Wo   = (const float*)d_in[10];
    // d_in[11] = start_pos (0)
    float* out = (float*)d_out;

    float *gAq, *gAk, *gAv, *gBq, *gBk, *gBv, *gq, *gk, *gv, *gatt;
    cudaGetSymbolAddress((void**)&gAq,  g_Aq);
    cudaGetSymbolAddress((void**)&gAk,  g_Ak);
    cudaGetSymbolAddress((void**)&gAv,  g_Av);
    cudaGetSymbolAddress((void**)&gBq,  g_Bq);
    cudaGetSymbolAddress((void**)&gBk,  g_Bk);
    cudaGetSymbolAddress((void**)&gBv,  g_Bv);
    cudaGetSymbolAddress((void**)&gq,   g_q);
    cudaGetSymbolAddress((void**)&gk,   g_k);
    cudaGetSymbolAddress((void**)&gv,   g_v);
    cudaGetSymbolAddress((void**)&gatt, g_att);

    static int smem_set = 0;
    if (!smem_set) {
        cudaFuncSetAttribute(flash_kernel,
                             cudaFuncAttributeMaxDynamicSharedMemorySize,
                             FLASH_SMEM_BYTES);
        smem_set = 1;
    }

    const int M = Bc * Sc;   // 4096

    // 1) Projections: x (M x D) @ W (D x N)
    launch_gemm(x, WAq, gAq, M, Hc * QRc,  Dc, Dc, Hc * QRc,  Hc * QRc);
    launch_gemm(x, WAk, gAk, M, Hc * Rc,   Dc, Dc, Hc * Rc,   Hc * Rc);
    launch_gemm(x, WAv, gAv, M, Hc * Rc,   Dc, Dc, Hc * Rc,   Hc * Rc);
    launch_gemm(x, WBq, gBq, M, QRc * HDc, Dc, Dc, QRc * HDc, QRc * HDc);
    launch_gemm(x, WBk, gBk, M, Rc * HDc,  Dc, Dc, Rc * HDc,  Rc * HDc);
    launch_gemm(x, WBv, gBv, M, Rc * HDc,  Dc, Dc, Rc * HDc,  Rc * HDc);

    // 2) RoPE on B_q and B_k (interleaved pairs)
    {
        long long tq = (long long)Bc * Sc * QRc * (HDc / 2);
        long long tk = (long long)Bc * Sc * Rc  * (HDc / 2);
        rope_kernel<<<(unsigned)((tq + 255) / 256), 256>>>(gBq, fcos, fsin, QRc, tq);
        rope_kernel<<<(unsigned)((tk + 255) / 256), 256>>>(gBk, fcos, fsin, Rc,  tk);
    }

    // 3) Rank combine -> q, k, v (all b,s,h,d)
    {
        long long tot = (long long)Bc * Sc * Hc * HDc;
        combine_kernel<<<(unsigned)((tot + 255) / 256), 256>>>(gAq, gAk, gAv, gBq, gBk, gBv,
                                                               gq, gk, gv);
    }

    // 4) Fused causal attention -> att (b,s,h,d)
    {
        dim3 g(Sc / FBM, Bc * Hc);
        flash_kernel<<<g, FTHREADS, FLASH_SMEM_BYTES>>>(gq, gk, gv, gatt);
    }

    // 5) Output projection: att (M x 2048) @ W_o (2048 x 2048) -> d_out
    launch_gemm(gatt, Wo, out, M, Dc, Hc * HDc, Hc * HDc, Dc, Dc);
}

// round 7
// speedup vs baseline: 2.0944x; 2.0944x over previous
#include <cuda_runtime.h>
#include <cuda_bf16.h>
#include <cstdint>

// Problem constants
#define Bc  2
#define Sc  2048
#define Dc  2048
#define Hc  16
#define HDc 128
#define QRc 12
#define Rc  2

// Fused projection column offsets: [WAq | WAk | WAv | WBq | WBk | WBv]
#define NTOT 2304
#define OAq  0
#define OAk  192
#define OAv  224
#define OBq  256
#define OBk  1792
#define OBv  2048

// ---------------------------------------------------------------------------
// Device scratch (no cudaMalloc allowed).
// ---------------------------------------------------------------------------
__device__ __nv_bfloat16 g_xh [(size_t)Bc*Sc*Dc];
__device__ __nv_bfloat16 g_xl [(size_t)Bc*Sc*Dc];
__device__ __nv_bfloat16 g_WTh[(size_t)NTOT*Dc];      // fused proj weights, [N][K]
__device__ __nv_bfloat16 g_WTl[(size_t)NTOT*Dc];
__device__ __nv_bfloat16 g_WoTh[(size_t)Dc*Dc];       // Wo^T [N][K]
__device__ __nv_bfloat16 g_WoTl[(size_t)Dc*Dc];
__device__ float g_proj[(size_t)Bc*Sc*NTOT];          // fused projection output
__device__ float g_q [(size_t)Bc*Sc*Hc*HDc];
__device__ float g_k [(size_t)Bc*Sc*Hc*HDc];
__device__ float g_v [(size_t)Bc*Sc*Hc*HDc];
__device__ float g_att[(size_t)Bc*Sc*Hc*HDc];
__device__ __nv_bfloat16 g_atth[(size_t)Bc*Sc*Hc*HDc];
__device__ __nv_bfloat16 g_attl[(size_t)Bc*Sc*Hc*HDc];

// ---------------------------------------------------------------------------
// Helpers
// ---------------------------------------------------------------------------
__device__ __forceinline__ uint32_t s2u(const void* p) {
    return (uint32_t)__cvta_generic_to_shared(p);
}
__device__ __forceinline__ void cp16(uint32_t dst, const void* src) {
    asm volatile("cp.async.cg.shared.global [%0], [%1], 16;\n"
                 :: "r"(dst), "l"(src));
}
__device__ __forceinline__ void bsplit(float f, __nv_bfloat16& h, __nv_bfloat16& l) {
    h = __float2bfloat16_rn(f);
    l = __float2bfloat16_rn(f - __bfloat162float(h));
}

// ---------------------------------------------------------------------------
// Elementwise split: fp32 -> (hi, lo) bf16. n4 = elements/4.
// ---------------------------------------------------------------------------
__global__ void split_kernel(const float* __restrict__ src,
                             __nv_bfloat16* __restrict__ hi,
                             __nv_bfloat16* __restrict__ lo, long long n4)
{
    long long i = (long long)blockIdx.x * blockDim.x + threadIdx.x;
    if (i >= n4) return;
    float4 f = ((const float4*)src)[i];
    __nv_bfloat16 h0, h1, h2, h3, l0, l1, l2, l3;
    bsplit(f.x, h0, l0); bsplit(f.y, h1, l1);
    bsplit(f.z, h2, l2); bsplit(f.w, h3, l3);
    ((__nv_bfloat162*)hi)[2*i]   = __nv_bfloat162(h0, h1);
    ((__nv_bfloat162*)hi)[2*i+1] = __nv_bfloat162(h2, h3);
    ((__nv_bfloat162*)lo)[2*i]   = __nv_bfloat162(l0, l1);
    ((__nv_bfloat162*)lo)[2*i+1] = __nv_bfloat162(l2, l3);
}

// ---------------------------------------------------------------------------
// Transpose + split: W [K][N] fp32 row-major -> T_hi/T_lo rows (rowOff+n) of
// a [*][ldt] bf16 matrix holding W^T (n-major rows of K).
// grid: (N/32, K/32), block (32, 8).
// ---------------------------------------------------------------------------
__global__ void tsplit_kernel(const float* __restrict__ W, int K, int N,
                              __nv_bfloat16* __restrict__ Th,
                              __nv_bfloat16* __restrict__ Tl,
                              int rowOff, int ldt)
{
    __shared__ float tile[32][33];
    int n0 = blockIdx.x * 32, k0 = blockIdx.y * 32;
    int tx = threadIdx.x, ty = threadIdx.y;
    for (int r = ty; r < 32; r += 8)
        tile[r][tx] = W[(size_t)(k0 + r) * N + n0 + tx];
    __syncthreads();
    for (int r = ty; r < 32; r += 8) {
        int n = n0 + r, k = k0 + tx;
        float f = tile[tx][r];
        __nv_bfloat16 h, l;
        bsplit(f, h, l);
        Th[(size_t)(rowOff + n) * ldt + k] = h;
        Tl[(size_t)(rowOff + n) * ldt + k] = l;
    }
}

// ---------------------------------------------------------------------------
// bf16x3 tensor-core GEMM: C = A(MxK) @ B^T(NxK)^T, fp32 out.
// A given as (Ah + Al), B^T as (Bh + Bl), all bf16 [rows][K] row-major.
// Computes Ah*Bh + Ah*Bl + Al*Bh (fp32 accumulate) ~ fp32-accurate.
// CTA 256 thr = 8 warps, tile 128x128, K-step 32 bf16, warp tile 64x32.
// Requirements: M%128==0, N%128==0, K%32==0.
// ---------------------------------------------------------------------------
#define GBM 128
#define GBN 128
#define GBK 32
#define LDW 20                       // smem words per row (16 data + 4 pad)
#define TW  (128 * LDW)              // words per tile
#define GSMEM_BYTES (2 * 4 * TW * 4) // 81920

#define BMMA(d, a, b) asm volatile( \
    "mma.sync.aligned.m16n8k16.row.col.f32.bf16.bf16.f32 " \
    "{%0,%1,%2,%3}, {%4,%5,%6,%7}, {%8,%9}, {%0,%1,%2,%3};" \
    : "+f"((d)[0]), "+f"((d)[1]), "+f"((d)[2]), "+f"((d)[3]) \
    : "r"((a)[0]), "r"((a)[1]), "r"((a)[2]), "r"((a)[3]), \
      "r"((b)[0]), "r"((b)[1]))

__global__ __launch_bounds__(256) void bf16x3_gemm_kernel(
    const __nv_bfloat16* __restrict__ Ah, const __nv_bfloat16* __restrict__ Al,
    const __nv_bfloat16* __restrict__ Bh, const __nv_bfloat16* __restrict__ Bl,
    float* __restrict__ C, int M, int N, int K, int ldc)
{
    extern __shared__ uint32_t gs[];

    int m0 = blockIdx.y * GBM;
    int n0 = blockIdx.x * GBN;
    int tid = threadIdx.x, warp = tid >> 5, lane = tid & 31;
    int wm = warp >> 2, wn = warp & 3;      // 2 x 4 warp grid
    int g  = lane >> 2, tg = lane & 3;

    float acc[4][4][4];
#pragma unroll
    for (int i = 0; i < 4; i++)
#pragma unroll
        for (int j = 0; j < 4; j++)
#pragma unroll
            for (int c = 0; c < 4; c++) acc[i][j][c] = 0.f;

    auto stage = [&](int kt, int buf) {
        uint32_t* base = gs + buf * 4 * TW;
        const __nv_bfloat16* srcs[4] = {Ah, Al, Bh, Bl};
#pragma unroll
        for (int t = 0; t < 4; t++) {
            const __nv_bfloat16* S = srcs[t];
            int r0 = (t < 2) ? m0 : n0;
            uint32_t* dst = base + t * TW;
#pragma unroll
            for (int l = 0; l < 2; l++) {
                int v = tid + l * 256;
                int row = v >> 2, cq = v & 3;   // 4 x 16B chunks per row
                cp16(s2u(dst + row * LDW + cq * 4),
                     S + (size_t)(r0 + row) * K + kt + cq * 8);
            }
        }
    };

    stage(0, 0);
    asm volatile("cp.async.commit_group;");

    int buf = 0;
    for (int kt = 0; kt < K; kt += GBK, buf ^= 1) {
        if (kt + GBK < K) {
            stage(kt + GBK, buf ^ 1);
            asm volatile("cp.async.commit_group;");
            asm volatile("cp.async.wait_group 1;");
        } else {
            asm volatile("cp.async.wait_group 0;");
        }
        __syncthreads();

        const uint32_t* cAh = gs + buf * 4 * TW;
        const uint32_t* cAl = cAh + TW;
        const uint32_t* cBh = cAh + 2 * TW;
        const uint32_t* cBl = cAh + 3 * TW;

#pragma unroll
        for (int ks = 0; ks < 2; ks++) {
            int kw = ks * 8;                    // word offset of this k16 step
            uint32_t ah[4][4], al[4][4], bh[4][2], bl[4][2];
#pragma unroll
            for (int i = 0; i < 4; i++) {
                int b0 = (wm * 64 + i * 16 + g) * LDW + kw + tg;
                int b1 = b0 + 8 * LDW;
                ah[i][0] = cAh[b0]; ah[i][1] = cAh[b1];
                ah[i][2] = cAh[b0 + 4]; ah[i][3] = cAh[b1 + 4];
                al[i][0] = cAl[b0]; al[i][1] = cAl[b1];
                al[i][2] = cAl[b0 + 4]; al[i][3] = cAl[b1 + 4];
            }
#pragma unroll
            for (int j = 0; j < 4; j++) {
                int bb = (wn * 32 + j * 8 + g) * LDW + kw + tg;
                bh[j][0] = cBh[bb]; bh[j][1] = cBh[bb + 4];
                bl[j][0] = cBl[bb]; bl[j][1] = cBl[bb + 4];
            }
#pragma unroll
            for (int i = 0; i < 4; i++)
#pragma unroll
                for (int j = 0; j < 4; j++) {
                    BMMA(acc[i][j], ah[i], bh[j]);
                    BMMA(acc[i][j], ah[i], bl[j]);
                    BMMA(acc[i][j], al[i], bh[j]);
                }
        }
        __syncthreads();
    }

    // epilogue: c0,c1 at (row, col..col+1); c2,c3 at (row+8, col..col+1)
#pragma unroll
    for (int i = 0; i < 4; i++) {
        int row = m0 + wm * 64 + i * 16 + g;
#pragma unroll
        for (int j = 0; j < 4; j++) {
            int col = n0 + wn * 32 + j * 8 + 2 * tg;
            *(float2*)(C + (size_t)row * ldc + col) =
                make_float2(acc[i][j][0], acc[i][j][1]);
            *(float2*)(C + (size_t)(row + 8) * ldc + col) =
                make_float2(acc[i][j][2], acc[i][j][3]);
        }
    }
}

// ---------------------------------------------------------------------------
// Interleaved RoPE in-place on a column slice of g_proj:
// element (bs, r, d) at proj[bs*NTOT + colOff + r*HDc + d].
// ---------------------------------------------------------------------------
__global__ void rope_kernel(float* __restrict__ proj, int colOff,
                            const float* __restrict__ fcos,
                            const float* __restrict__ fsin,
                            int Rdim, long long total)
{
    long long idx = (long long)blockIdx.x * blockDim.x + threadIdx.x;
    if (idx >= total) return;
    int i = (int)(idx % (HDc / 2));
    long long sr = idx / (HDc / 2);           // (bs, r) with r fastest
    long long bs = sr / Rdim;
    int r = (int)(sr % Rdim);
    long long s = bs % Sc;
    float c  = fcos[s * (HDc / 2) + i];
    float sn = fsin[s * (HDc / 2) + i];
    float* p = proj + bs * NTOT + colOff + r * HDc + 2 * i;
    float t0 = p[0], t1 = p[1];
    p[0] = t0 * c - t1 * sn;
    p[1] = t0 * sn + t1 * c;
}

// ---------------------------------------------------------------------------
// Rank combine from fused proj buffer -> q, k, v (b,s,h,d).
// ---------------------------------------------------------------------------
__global__ void combine_kernel(const float* __restrict__ proj,
                               float* __restrict__ q, float* __restrict__ k,
                               float* __restrict__ v)
{
    long long idx = (long long)blockIdx.x * blockDim.x + threadIdx.x;
    const long long total = (long long)Bc * Sc * Hc * HDc;
    if (idx >= total) return;
    int d = (int)(idx % HDc);
    int h = (int)((idx / HDc) % Hc);
    long long bs = idx / ((long long)HDc * Hc);
    const float* row = proj + bs * NTOT;

    float accq = 0.f;
#pragma unroll
    for (int r = 0; r < QRc; r++)
        accq += row[OAq + h * QRc + r] * row[OBq + r * HDc + d];
    q[idx] = accq * (1.0f / QRc);

    float acck = 0.f, accv = 0.f;
#pragma unroll
    for (int r = 0; r < Rc; r++) {
        acck += row[OAk + h * Rc + r] * row[OBk + r * HDc + d];
        accv += row[OAv + h * Rc + r] * row[OBv + r * HDc + d];
    }
    k[idx] = acck * (1.0f / Rc);
    v[idx] = accv * (1.0f / Rc);
}

// ---------------------------------------------------------------------------
// Fused causal flash attention, fp32 (validated in round 4, unchanged).
// ---------------------------------------------------------------------------
#define FBM 64
#define FBN 64
#define FTHREADS 256
#define KT_LD (FBN + 2)
#define SS_LD (FBN + 2)
#define FLASH_SMEM_BYTES ((FBM*HDc + HDc*KT_LD + FBM*SS_LD) * (int)sizeof(float))

__global__ __launch_bounds__(FTHREADS) void flash_kernel(
    const float* __restrict__ q, const float* __restrict__ k,
    const float* __restrict__ v, float* __restrict__ att)
{
    extern __shared__ float fsmem[];
    float* sQ  = fsmem;
    float* sKV = sQ + FBM * HDc;
    float* sS  = sKV + HDc * KT_LD;

    int mt = gridDim.x - 1 - blockIdx.x;
    int m0 = mt * FBM;
    int bh = blockIdx.y;
    int b  = bh / Hc, h = bh % Hc;

    int tid  = threadIdx.x;
    int warp = tid >> 5;
    int lane = tid & 31;
    int rowbase = warp * 8;

    const float scale = 0.08838834764831845f;

    for (int it = tid; it < FBM * (HDc / 4); it += FTHREADS) {
        int row = it >> 5;
        int dq  = (it & 31) << 2;
        float4 val = *(const float4*)(q + (((size_t)b * Sc + m0 + row) * Hc + h) * HDc + dq);
        float* dst = sQ + row * HDc + dq;
        dst[0] = val.x * scale; dst[1] = val.y * scale;
        dst[2] = val.z * scale; dst[3] = val.w * scale;
    }

    float acc[8][4];
#pragma unroll
    for (int i = 0; i < 8; i++)
#pragma unroll
        for (int c = 0; c < 4; c++) acc[i][c] = 0.f;
    float m_i[8], l_i[8];
#pragma unroll
    for (int i = 0; i < 8; i++) { m_i[i] = -1e30f; l_i[i] = 0.f; }

    int c0 = lane * 2, c1 = lane * 2 + 1;
    int cc = lane * 4;

    int nTiles = mt + 1;
    for (int t = 0; t < nTiles; t++) {
        int n0 = t * FBN;

        __syncthreads();
        for (int it = tid; it < FBN * (HDc / 4); it += FTHREADS) {
            int n  = it >> 5;
            int dq = (it & 31) << 2;
            float4 val = *(const float4*)(k + (((size_t)b * Sc + n0 + n) * Hc + h) * HDc + dq);
            sKV[(dq + 0) * KT_LD + n] = val.x;
            sKV[(dq + 1) * KT_LD + n] = val.y;
            sKV[(dq + 2) * KT_LD + n] = val.z;
            sKV[(dq + 3) * KT_LD + n] = val.w;
        }
        __syncthreads();

        float s0[8], s1[8];
#pragma unroll
        for (int i = 0; i < 8; i++) { s0[i] = 0.f; s1[i] = 0.f; }
        for (int d0 = 0; d0 < HDc; d0 += 4) {
            float kv0[4], kv1[4];
#pragma unroll
            for (int dd = 0; dd < 4; dd++) {
                kv0[dd] = sKV[(d0 + dd) * KT_LD + c0];
                kv1[dd] = sKV[(d0 + dd) * KT_LD + c1];
            }
#pragma unroll
            for (int i = 0; i < 8; i++) {
                float4 qv = *(const float4*)(sQ + (rowbase + i) * HDc + d0);
                s0[i] += qv.x * kv0[0] + qv.y * kv0[1] + qv.z * kv0[2] + qv.w * kv0[3];
                s1[i] += qv.x * kv1[0] + qv.y * kv1[1] + qv.z * kv1[2] + qv.w * kv1[3];
            }
        }

        if (n0 == m0) {
#pragma unroll
            for (int i = 0; i < 8; i++) {
                if (c0 > rowbase + i) s0[i] = -1e30f;
                if (c1 > rowbase + i) s1[i] = -1e30f;
            }
        }

#pragma unroll
        for (int i = 0; i < 8; i++) {
            float mx = fmaxf(s0[i], s1[i]);
#pragma unroll
            for (int o = 16; o; o >>= 1) mx = fmaxf(mx, __shfl_xor_sync(0xFFFFFFFFu, mx, o));
            float mnew = fmaxf(m_i[i], mx);
            float es = __expf(m_i[i] - mnew);
            float p0 = __expf(s0[i] - mnew);
            float p1 = __expf(s1[i] - mnew);
            float ps = p0 + p1;
#pragma unroll
            for (int o = 16; o; o >>= 1) ps += __shfl_xor_sync(0xFFFFFFFFu, ps, o);
            l_i[i] = l_i[i] * es + ps;
            m_i[i] = mnew;
#pragma unroll
            for (int c = 0; c < 4; c++) acc[i][c] *= es;
            sS[(rowbase + i) * SS_LD + c0] = p0;
            sS[(rowbase + i) * SS_LD + c1] = p1;
        }

        __syncthreads();
        for (int it = tid; it < FBN * (HDc / 4); it += FTHREADS) {
            int n  = it >> 5;
            int dq = (it & 31) << 2;
            *(float4*)(sKV + n * HDc + dq) =
                *(const float4*)(v + (((size_t)b * Sc + n0 + n) * Hc + h) * HDc + dq);
        }
        __syncthreads();

        for (int j = 0; j < FBN; j += 2) {
            float4 v0 = *(const float4*)(sKV + j * HDc + cc);
            float4 v1 = *(const float4*)(sKV + (j + 1) * HDc + cc);
#pragma unroll
            for (int i = 0; i < 8; i++) {
                float p0 = sS[(rowbase + i) * SS_LD + j];
                float p1 = sS[(rowbase + i) * SS_LD + j + 1];
                acc[i][0] += p0 * v0.x + p1 * v1.x;
                acc[i][1] += p0 * v0.y + p1 * v1.y;
                acc[i][2] += p0 * v0.z + p1 * v1.z;
                acc[i][3] += p0 * v0.w + p1 * v1.w;
            }
        }
    }

#pragma unroll
    for (int i = 0; i < 8; i++) {
        float inv = 1.0f / l_i[i];
        float4 o = make_float4(acc[i][0] * inv, acc[i][1] * inv,
                               acc[i][2] * inv, acc[i][3] * inv);
        *(float4*)(att + (((size_t)b * Sc + m0 + rowbase + i) * Hc + h) * HDc + cc) = o;
    }
}

// ---------------------------------------------------------------------------
// Launch
// ---------------------------------------------------------------------------
extern "C" void kernel_launch(void* const* d_in, const int* in_sizes, int n_in,
                              void* d_out, int out_size)
{
    const float* x    = (const float*)d_in[0];
    const float* fcos = (const float*)d_in[1];
    const float* fsin = (const float*)d_in[2];
    // d_in[3] = mask (causality handled analytically)
    const float* WAq  = (const float*)d_in[4];
    const float* WAk  = (const float*)d_in[5];
    const float* WAv  = (const float*)d_in[6];
    const float* WBq  = (const float*)d_in[7];
    const float* WBk  = (const float*)d_in[8];
    const float* WBv  = (const float*)d_in[9];
    const float* Wo   = (const float*)d_in[10];
    // d_in[11] = start_pos (0)
    float* out = (float*)d_out;

    __nv_bfloat16 *gxh, *gxl, *gWTh, *gWTl, *gWoTh, *gWoTl, *gatth, *gattl;
    float *gproj, *gq, *gk, *gv, *gatt;
    cudaGetSymbolAddress((void**)&gxh,   g_xh);
    cudaGetSymbolAddress((void**)&gxl,   g_xl);
    cudaGetSymbolAddress((void**)&gWTh,  g_WTh);
    cudaGetSymbolAddress((void**)&gWTl,  g_WTl);
    cudaGetSymbolAddress((void**)&gWoTh, g_WoTh);
    cudaGetSymbolAddress((void**)&gWoTl, g_WoTl);
    cudaGetSymbolAddress((void**)&gproj, g_proj);
    cudaGetSymbolAddress((void**)&gq,    g_q);
    cudaGetSymbolAddress((void**)&gk,    g_k);
    cudaGetSymbolAddress((void**)&gv,    g_v);
    cudaGetSymbolAddress((void**)&gatt,  g_att);
    cudaGetSymbolAddress((void**)&gatth, g_atth);
    cudaGetSymbolAddress((void**)&gattl, g_attl);

    static int smem_set = 0;
    if (!smem_set) {
        cudaFuncSetAttribute(flash_kernel,
                             cudaFuncAttributeMaxDynamicSharedMemorySize,
                             FLASH_SMEM_BYTES);
        cudaFuncSetAttribute(bf16x3_gemm_kernel,
                             cudaFuncAttributeMaxDynamicSharedMemorySize,
                             GSMEM_BYTES);
        smem_set = 1;
    }

    const int M = Bc * Sc;   // 4096
    dim3 tsb(32, 8);

    // 0) Split x and transpose+split all weights into bf16 hi/lo
    {
        long long n4 = (long long)Bc * Sc * Dc / 4;
        split_kernel<<<(unsigned)((n4 + 255) / 256), 256>>>(x, gxh, gxl, n4);
    }
    tsplit_kernel<<<dim3(192/32,  Dc/32), tsb>>>(WAq, Dc, 192,  gWTh, gWTl, OAq, Dc);
    tsplit_kernel<<<dim3(32/32,   Dc/32), tsb>>>(WAk, Dc, 32,   gWTh, gWTl, OAk, Dc);
    tsplit_kernel<<<dim3(32/32,   Dc/32), tsb>>>(WAv, Dc, 32,   gWTh, gWTl, OAv, Dc);
    tsplit_kernel<<<dim3(1536/32, Dc/32), tsb>>>(WBq, Dc, 1536, gWTh, gWTl, OBq, Dc);
    tsplit_kernel<<<dim3(256/32,  Dc/32), tsb>>>(WBk, Dc, 256,  gWTh, gWTl, OBk, Dc);
    tsplit_kernel<<<dim3(256/32,  Dc/32), tsb>>>(WBv, Dc, 256,  gWTh, gWTl, OBv, Dc);
    tsplit_kernel<<<dim3(Dc/32,   Dc/32), tsb>>>(Wo,  Dc, Dc,   gWoTh, gWoTl, 0, Dc);

    // 1) Fused projection GEMM: x (4096 x 2048) @ Wall (2048 x 2304)
    {
        dim3 g(NTOT / GBN, M / GBM);
        bf16x3_gemm_kernel<<<g, 256, GSMEM_BYTES>>>(gxh, gxl, gWTh, gWTl,
                                                    gproj, M, NTOT, Dc, NTOT);
    }

    // 2) RoPE on B_q and B_k slices of proj
    {
        long long tq = (long long)Bc * Sc * QRc * (HDc / 2);
        long long tk = (long long)Bc * Sc * Rc  * (HDc / 2);
        rope_kernel<<<(unsigned)((tq + 255) / 256), 256>>>(gproj, OBq, fcos, fsin, QRc, tq);
        rope_kernel<<<(unsigned)((tk + 255) / 256), 256>>>(gproj, OBk, fcos, fsin, Rc,  tk);
    }

    // 3) Rank combine -> q, k, v
    {
        long long tot = (long long)Bc * Sc * Hc * HDc;
        combine_kernel<<<(unsigned)((tot + 255) / 256), 256>>>(gproj, gq, gk, gv);
    }

    // 4) Fused causal attention -> att
    {
        dim3 g(Sc / FBM, Bc * Hc);
        flash_kernel<<<g, FTHREADS, FLASH_SMEM_BYTES>>>(gq, gk, gv, gatt);
    }

    // 5) Split att, then output projection -> d_out
    {
        long long n4 = (long long)M * Dc / 4;
        split_kernel<<<(unsigned)((n4 + 255) / 256), 256>>>(gatt, gatth, gattl, n4);
        dim3 g(Dc / GBN, M / GBM);
        bf16x3_gemm_kernel<<<g, 256, GSMEM_BYTES>>>(gatth, gattl, gWoTh, gWoTl,
                                                    out, M, Dc, Dc, Dc);
    }
}

// round 9
// speedup vs baseline: 3.9120x; 1.8679x over previous
#include <cuda_runtime.h>
#include <cuda_bf16.h>
#include <cstdint>

// Problem constants
#define Bc  2
#define Sc  2048
#define Dc  2048
#define Hc  16
#define HDc 128
#define QRc 12
#define Rc  2

// Fused projection column offsets: [WAq | WAk | WAv | WBq | WBk | WBv]
#define NTOT 2304
#define OAq  0
#define OAk  192
#define OAv  224
#define OBq  256
#define OBk  1792
#define OBv  2048

// ---------------------------------------------------------------------------
// Device scratch (no cudaMalloc allowed).
// ---------------------------------------------------------------------------
__device__ __nv_bfloat16 g_xh [(size_t)Bc*Sc*Dc];
__device__ __nv_bfloat16 g_xl [(size_t)Bc*Sc*Dc];
__device__ __nv_bfloat16 g_WTh[(size_t)NTOT*Dc];
__device__ __nv_bfloat16 g_WTl[(size_t)NTOT*Dc];
__device__ __nv_bfloat16 g_WoTh[(size_t)Dc*Dc];
__device__ __nv_bfloat16 g_WoTl[(size_t)Dc*Dc];
__device__ float g_proj[(size_t)Bc*Sc*NTOT];
__device__ __nv_bfloat16 g_qh [(size_t)Bc*Sc*Hc*HDc];   // (b,s,h,d), scale folded
__device__ __nv_bfloat16 g_ql [(size_t)Bc*Sc*Hc*HDc];
__device__ __nv_bfloat16 g_kh [(size_t)Bc*Sc*Hc*HDc];
__device__ __nv_bfloat16 g_kl [(size_t)Bc*Sc*Hc*HDc];
__device__ __nv_bfloat16 g_vh [(size_t)Bc*Sc*Hc*HDc];
__device__ __nv_bfloat16 g_vl [(size_t)Bc*Sc*Hc*HDc];
__device__ __nv_bfloat16 g_vTh[(size_t)Bc*Hc*HDc*Sc];   // (b,h,d,s)
__device__ __nv_bfloat16 g_vTl[(size_t)Bc*Hc*HDc*Sc];
__device__ __nv_bfloat16 g_atth[(size_t)Bc*Sc*Hc*HDc];
__device__ __nv_bfloat16 g_attl[(size_t)Bc*Sc*Hc*HDc];

// ---------------------------------------------------------------------------
// Helpers
// ---------------------------------------------------------------------------
__device__ __forceinline__ uint32_t s2u(const void* p) {
    return (uint32_t)__cvta_generic_to_shared(p);
}
__device__ __forceinline__ void cp16(uint32_t dst, const void* src) {
    asm volatile("cp.async.cg.shared.global [%0], [%1], 16;\n"
                 :: "r"(dst), "l"(src));
}
__device__ __forceinline__ void bsplit(float f, __nv_bfloat16& h, __nv_bfloat16& l) {
    h = __float2bfloat16_rn(f);
    l = __float2bfloat16_rn(f - __bfloat162float(h));
}
__device__ __forceinline__ uint32_t packbf(float a, float b) {
    __nv_bfloat162 t = __floats2bfloat162_rn(a, b);   // x=a (low), y=b (high)
    return *(uint32_t*)&t;
}

#define BMMA(d, a, b) asm volatile( \
    "mma.sync.aligned.m16n8k16.row.col.f32.bf16.bf16.f32 " \
    "{%0,%1,%2,%3}, {%4,%5,%6,%7}, {%8,%9}, {%0,%1,%2,%3};" \
    : "+f"((d)[0]), "+f"((d)[1]), "+f"((d)[2]), "+f"((d)[3]) \
    : "r"((a)[0]), "r"((a)[1]), "r"((a)[2]), "r"((a)[3]), \
      "r"((b)[0]), "r"((b)[1]))

// ---------------------------------------------------------------------------
// Elementwise split: fp32 -> (hi, lo) bf16. n4 = elements/4.
// ---------------------------------------------------------------------------
__global__ void split_kernel(const float* __restrict__ src,
                             __nv_bfloat16* __restrict__ hi,
                             __nv_bfloat16* __restrict__ lo, long long n4)
{
    long long i = (long long)blockIdx.x * blockDim.x + threadIdx.x;
    if (i >= n4) return;
    float4 f = ((const float4*)src)[i];
    __nv_bfloat16 h0, h1, h2, h3, l0, l1, l2, l3;
    bsplit(f.x, h0, l0); bsplit(f.y, h1, l1);
    bsplit(f.z, h2, l2); bsplit(f.w, h3, l3);
    ((__nv_bfloat162*)hi)[2*i]   = __nv_bfloat162(h0, h1);
    ((__nv_bfloat162*)hi)[2*i+1] = __nv_bfloat162(h2, h3);
    ((__nv_bfloat162*)lo)[2*i]   = __nv_bfloat162(l0, l1);
    ((__nv_bfloat162*)lo)[2*i+1] = __nv_bfloat162(l2, l3);
}

// ---------------------------------------------------------------------------
// Transpose + split: W [K][N] fp32 -> bf16 hi/lo rows (rowOff+n) of [*][ldt].
// ---------------------------------------------------------------------------
__global__ void tsplit_kernel(const float* __restrict__ W, int K, int N,
                              __nv_bfloat16* __restrict__ Th,
                              __nv_bfloat16* __restrict__ Tl,
                              int rowOff, int ldt)
{
    __shared__ float tile[32][33];
    int n0 = blockIdx.x * 32, k0 = blockIdx.y * 32;
    int tx = threadIdx.x, ty = threadIdx.y;
    for (int r = ty; r < 32; r += 8)
        tile[r][tx] = W[(size_t)(k0 + r) * N + n0 + tx];
    __syncthreads();
    for (int r = ty; r < 32; r += 8) {
        int n = n0 + r, k = k0 + tx;
        float f = tile[tx][r];
        __nv_bfloat16 h, l;
        bsplit(f, h, l);
        Th[(size_t)(rowOff + n) * ldt + k] = h;
        Tl[(size_t)(rowOff + n) * ldt + k] = l;
    }
}

// ---------------------------------------------------------------------------
// bf16x3 tensor-core GEMM (validated round 7, unchanged).
// ---------------------------------------------------------------------------
#define GBM 128
#define GBN 128
#define GBK 32
#define LDW 20
#define TW  (128 * LDW)
#define GSMEM_BYTES (2 * 4 * TW * 4)

__global__ __launch_bounds__(256) void bf16x3_gemm_kernel(
    const __nv_bfloat16* __restrict__ Ah, const __nv_bfloat16* __restrict__ Al,
    const __nv_bfloat16* __restrict__ Bh, const __nv_bfloat16* __restrict__ Bl,
    float* __restrict__ C, int M, int N, int K, int ldc)
{
    extern __shared__ uint32_t gs[];

    int m0 = blockIdx.y * GBM;
    int n0 = blockIdx.x * GBN;
    int tid = threadIdx.x, warp = tid >> 5, lane = tid & 31;
    int wm = warp >> 2, wn = warp & 3;
    int g  = lane >> 2, tg = lane & 3;

    float acc[4][4][4];
#pragma unroll
    for (int i = 0; i < 4; i++)
#pragma unroll
        for (int j = 0; j < 4; j++)
#pragma unroll
            for (int c = 0; c < 4; c++) acc[i][j][c] = 0.f;

    auto stage = [&](int kt, int buf) {
        uint32_t* base = gs + buf * 4 * TW;
        const __nv_bfloat16* srcs[4] = {Ah, Al, Bh, Bl};
#pragma unroll
        for (int t = 0; t < 4; t++) {
            const __nv_bfloat16* S = srcs[t];
            int r0 = (t < 2) ? m0 : n0;
            uint32_t* dst = base + t * TW;
#pragma unroll
            for (int l = 0; l < 2; l++) {
                int v = tid + l * 256;
                int row = v >> 2, cq = v & 3;
                cp16(s2u(dst + row * LDW + cq * 4),
                     S + (size_t)(r0 + row) * K + kt + cq * 8);
            }
        }
    };

    stage(0, 0);
    asm volatile("cp.async.commit_group;");

    int buf = 0;
    for (int kt = 0; kt < K; kt += GBK, buf ^= 1) {
        if (kt + GBK < K) {
            stage(kt + GBK, buf ^ 1);
            asm volatile("cp.async.commit_group;");
            asm volatile("cp.async.wait_group 1;");
        } else {
            asm volatile("cp.async.wait_group 0;");
        }
        __syncthreads();

        const uint32_t* cAh = gs + buf * 4 * TW;
        const uint32_t* cAl = cAh + TW;
        const uint32_t* cBh = cAh + 2 * TW;
        const uint32_t* cBl = cAh + 3 * TW;

#pragma unroll
        for (int ks = 0; ks < 2; ks++) {
            int kw = ks * 8;
            uint32_t ah[4][4], al[4][4], bh[4][2], bl[4][2];
#pragma unroll
            for (int i = 0; i < 4; i++) {
                int b0 = (wm * 64 + i * 16 + g) * LDW + kw + tg;
                int b1 = b0 + 8 * LDW;
                ah[i][0] = cAh[b0]; ah[i][1] = cAh[b1];
                ah[i][2] = cAh[b0 + 4]; ah[i][3] = cAh[b1 + 4];
                al[i][0] = cAl[b0]; al[i][1] = cAl[b1];
                al[i][2] = cAl[b0 + 4]; al[i][3] = cAl[b1 + 4];
            }
#pragma unroll
            for (int j = 0; j < 4; j++) {
                int bb = (wn * 32 + j * 8 + g) * LDW + kw + tg;
                bh[j][0] = cBh[bb]; bh[j][1] = cBh[bb + 4];
                bl[j][0] = cBl[bb]; bl[j][1] = cBl[bb + 4];
            }
#pragma unroll
            for (int i = 0; i < 4; i++)
#pragma unroll
                for (int j = 0; j < 4; j++) {
                    BMMA(acc[i][j], ah[i], bh[j]);
                    BMMA(acc[i][j], ah[i], bl[j]);
                    BMMA(acc[i][j], al[i], bh[j]);
                }
        }
        __syncthreads();
    }

#pragma unroll
    for (int i = 0; i < 4; i++) {
        int row = m0 + wm * 64 + i * 16 + g;
#pragma unroll
        for (int j = 0; j < 4; j++) {
            int col = n0 + wn * 32 + j * 8 + 2 * tg;
            *(float2*)(C + (size_t)row * ldc + col) =
                make_float2(acc[i][j][0], acc[i][j][1]);
            *(float2*)(C + (size_t)(row + 8) * ldc + col) =
                make_float2(acc[i][j][2], acc[i][j][3]);
        }
    }
}

// ---------------------------------------------------------------------------
// Interleaved RoPE in-place on a column slice of g_proj.
// ---------------------------------------------------------------------------
__global__ void rope_kernel(float* __restrict__ proj, int colOff,
                            const float* __restrict__ fcos,
                            const float* __restrict__ fsin,
                            int Rdim, long long total)
{
    long long idx = (long long)blockIdx.x * blockDim.x + threadIdx.x;
    if (idx >= total) return;
    int i = (int)(idx % (HDc / 2));
    long long sr = idx / (HDc / 2);
    long long bs = sr / Rdim;
    int r = (int)(sr % Rdim);
    long long s = bs % Sc;
    float c  = fcos[s * (HDc / 2) + i];
    float sn = fsin[s * (HDc / 2) + i];
    float* p = proj + bs * NTOT + colOff + r * HDc + 2 * i;
    float t0 = p[0], t1 = p[1];
    p[0] = t0 * c - t1 * sn;
    p[1] = t0 * sn + t1 * c;
}

// ---------------------------------------------------------------------------
// Rank combine -> q,k,v in bf16 hi/lo (b,s,h,d). Scales folded into q/k/v.
// ---------------------------------------------------------------------------
__global__ void combine_kernel(const float* __restrict__ proj,
                               __nv_bfloat16* __restrict__ qh, __nv_bfloat16* __restrict__ ql,
                               __nv_bfloat16* __restrict__ kh, __nv_bfloat16* __restrict__ kl,
                               __nv_bfloat16* __restrict__ vh, __nv_bfloat16* __restrict__ vl)
{
    long long idx = (long long)blockIdx.x * blockDim.x + threadIdx.x;
    const long long total = (long long)Bc * Sc * Hc * HDc;
    if (idx >= total) return;
    int d = (int)(idx % HDc);
    int h = (int)((idx / HDc) % Hc);
    long long bs = idx / ((long long)HDc * Hc);
    const float* row = proj + bs * NTOT;

    float accq = 0.f;
#pragma unroll
    for (int r = 0; r < QRc; r++)
        accq += row[OAq + h * QRc + r] * row[OBq + r * HDc + d];
    accq *= (1.0f / QRc) * 0.08838834764831845f;   // 1/QR * 1/sqrt(HD)
    __nv_bfloat16 hh, ll;
    bsplit(accq, hh, ll); qh[idx] = hh; ql[idx] = ll;

    float acck = 0.f, accv = 0.f;
#pragma unroll
    for (int r = 0; r < Rc; r++) {
        acck += row[OAk + h * Rc + r] * row[OBk + r * HDc + d];
        accv += row[OAv + h * Rc + r] * row[OBv + r * HDc + d];
    }
    bsplit(acck * (1.0f / Rc), hh, ll); kh[idx] = hh; kl[idx] = ll;
    bsplit(accv * (1.0f / Rc), hh, ll); vh[idx] = hh; vl[idx] = ll;
}

// ---------------------------------------------------------------------------
// V transpose: (b,s,h,d) -> (b,h,d,s), bf16 hi+lo.
// ---------------------------------------------------------------------------
__global__ void vtrans_kernel(const __nv_bfloat16* __restrict__ vh,
                              const __nv_bfloat16* __restrict__ vl,
                              __nv_bfloat16* __restrict__ vTh,
                              __nv_bfloat16* __restrict__ vTl)
{
    __shared__ __nv_bfloat16 th[32][34];
    __shared__ __nv_bfloat16 tl[32][34];
    int s0 = blockIdx.x * 32, d0 = blockIdx.y * 32;
    int bh = blockIdx.z;
    int b = bh / Hc, h = bh % Hc;
    int tx = threadIdx.x, ty = threadIdx.y;
    for (int r = ty; r < 32; r += 8) {
        size_t src = (((size_t)b * Sc + s0 + r) * Hc + h) * HDc + d0 + tx;
        th[r][tx] = vh[src];
        tl[r][tx] = vl[src];
    }
    __syncthreads();
    for (int r = ty; r < 32; r += 8) {
        size_t dst = ((size_t)bh * HDc + d0 + r) * Sc + s0 + tx;
        vTh[dst] = th[tx][r];
        vTl[dst] = tl[tx][r];
    }
}

// ---------------------------------------------------------------------------
// Fused causal flash attention, bf16x3 tensor cores.
// CTA: 128 threads (4 warps). Tile 64 q-rows x 64 keys, HD=128.
// Hardened vs round 8: Q staging is fully drained (commit+wait_all+sync)
// before the mainloop, so each in-loop wait_group 0 covers exactly the
// current K/V group.
// ---------------------------------------------------------------------------
#define FLDQ 68                      // words per Q/K smem row (136 bf16)
#define FLDV 36                      // words per VT smem row (72 bf16)
#define FQW  (64 * FLDQ)             // 4352 words
#define FVW  (128 * FLDV)            // 4608 words
#define FSMEM_BYTES ((4 * FQW + 2 * FVW) * 4)   // 106496

__global__ __launch_bounds__(128) void flash_kernel(
    const __nv_bfloat16* __restrict__ qh, const __nv_bfloat16* __restrict__ ql,
    const __nv_bfloat16* __restrict__ kh, const __nv_bfloat16* __restrict__ kl,
    const __nv_bfloat16* __restrict__ vTh, const __nv_bfloat16* __restrict__ vTl,
    __nv_bfloat16* __restrict__ atth, __nv_bfloat16* __restrict__ attl)
{
    extern __shared__ uint32_t fs[];
    uint32_t* wQh = fs;
    uint32_t* wQl = wQh + FQW;
    uint32_t* wKh = wQl + FQW;
    uint32_t* wKl = wKh + FQW;
    uint32_t* wVh = wKl + FQW;
    uint32_t* wVl = wVh + FVW;

    int mt = gridDim.x - 1 - blockIdx.x;     // long blocks first
    int m0 = mt * 64;
    int bh = blockIdx.y;
    int b  = bh / Hc, h = bh % Hc;

    int tid  = threadIdx.x;
    int warp = tid >> 5, lane = tid & 31;
    int g = lane >> 2, tg = lane & 3;
    int rowbase = warp * 16;

    // ---- stage Q (once), fully drained before mainloop ----
#pragma unroll
    for (int l = 0; l < 8; l++) {
        int v = tid + l * 128;                // 1024 chunks: 64 rows x 16
        int row = v >> 4, cq = v & 15;
        size_t src = (((size_t)b * Sc + m0 + row) * Hc + h) * HDc + cq * 8;
        cp16(s2u(wQh + row * FLDQ + cq * 4), qh + src);
        cp16(s2u(wQl + row * FLDQ + cq * 4), ql + src);
    }
    asm volatile("cp.async.commit_group;");
    asm volatile("cp.async.wait_group 0;");
    __syncthreads();

    float acc[16][4];
#pragma unroll
    for (int j = 0; j < 16; j++)
#pragma unroll
        for (int c = 0; c < 4; c++) acc[j][c] = 0.f;
    float m_a = -1e30f, m_b = -1e30f, l_a = 0.f, l_b = 0.f;

    for (int t = 0; t <= mt; t++) {
        int n0 = t * 64;

        __syncthreads();                     // previous iter done with K/V smem
        // ---- stage K tile ----
#pragma unroll
        for (int l = 0; l < 8; l++) {
            int v = tid + l * 128;
            int row = v >> 4, cq = v & 15;
            size_t src = (((size_t)b * Sc + n0 + row) * Hc + h) * HDc + cq * 8;
            cp16(s2u(wKh + row * FLDQ + cq * 4), kh + src);
            cp16(s2u(wKl + row * FLDQ + cq * 4), kl + src);
        }
        // ---- stage V tile (transposed source) ----
#pragma unroll
        for (int l = 0; l < 8; l++) {
            int v = tid + l * 128;            // 1024 chunks: 128 rows x 8
            int row = v >> 3, cq = v & 7;
            size_t src = ((size_t)bh * HDc + row) * Sc + n0 + cq * 8;
            cp16(s2u(wVh + row * FLDV + cq * 4), vTh + src);
            cp16(s2u(wVl + row * FLDV + cq * 4), vTl + src);
        }
        asm volatile("cp.async.commit_group;");
        asm volatile("cp.async.wait_group 0;");
        __syncthreads();

        // ---- S = Q K^T (bf16x3), 8 n-tiles of n8 ----
        float c[8][4];
#pragma unroll
        for (int n = 0; n < 8; n++)
#pragma unroll
            for (int i = 0; i < 4; i++) c[n][i] = 0.f;

#pragma unroll
        for (int kk = 0; kk < 8; kk++) {
            uint32_t ah[4], al[4];
            int ra = (rowbase + g) * FLDQ + kk * 8 + tg;
            int rb = (rowbase + g + 8) * FLDQ + kk * 8 + tg;
            ah[0] = wQh[ra]; ah[1] = wQh[rb]; ah[2] = wQh[ra + 4]; ah[3] = wQh[rb + 4];
            al[0] = wQl[ra]; al[1] = wQl[rb]; al[2] = wQl[ra + 4]; al[3] = wQl[rb + 4];
#pragma unroll
            for (int n = 0; n < 8; n++) {
                int rk = (n * 8 + g) * FLDQ + kk * 8 + tg;
                uint32_t bhf[2] = { wKh[rk], wKh[rk + 4] };
                uint32_t blf[2] = { wKl[rk], wKl[rk + 4] };
                BMMA(c[n], ah, bhf);
                BMMA(c[n], ah, blf);
                BMMA(c[n], al, bhf);
            }
        }

        // ---- causal mask on the diagonal tile ----
        if (t == mt) {
            int ra = rowbase + g, rb = ra + 8;
#pragma unroll
            for (int n = 0; n < 8; n++) {
                int c0 = n * 8 + 2 * tg, c1 = c0 + 1;
                if (c0 > ra) c[n][0] = -1e30f;
                if (c1 > ra) c[n][1] = -1e30f;
                if (c0 > rb) c[n][2] = -1e30f;
                if (c1 > rb) c[n][3] = -1e30f;
            }
        }

        // ---- online softmax (rows g and g+8 of this warp) ----
        float mxa = -1e30f, mxb = -1e30f;
#pragma unroll
        for (int n = 0; n < 8; n++) {
            mxa = fmaxf(mxa, fmaxf(c[n][0], c[n][1]));
            mxb = fmaxf(mxb, fmaxf(c[n][2], c[n][3]));
        }
        mxa = fmaxf(mxa, __shfl_xor_sync(0xFFFFFFFFu, mxa, 1));
        mxa = fmaxf(mxa, __shfl_xor_sync(0xFFFFFFFFu, mxa, 2));
        mxb = fmaxf(mxb, __shfl_xor_sync(0xFFFFFFFFu, mxb, 1));
        mxb = fmaxf(mxb, __shfl_xor_sync(0xFFFFFFFFu, mxb, 2));

        float mna = fmaxf(m_a, mxa), mnb = fmaxf(m_b, mxb);
        float esa = __expf(m_a - mna), esb = __expf(m_b - mnb);
        m_a = mna; m_b = mnb;

        float suma = 0.f, sumb = 0.f;
#pragma unroll
        for (int n = 0; n < 8; n++) {
            c[n][0] = __expf(c[n][0] - mna);
            c[n][1] = __expf(c[n][1] - mna);
            c[n][2] = __expf(c[n][2] - mnb);
            c[n][3] = __expf(c[n][3] - mnb);
            suma += c[n][0] + c[n][1];
            sumb += c[n][2] + c[n][3];
        }
        suma += __shfl_xor_sync(0xFFFFFFFFu, suma, 1);
        suma += __shfl_xor_sync(0xFFFFFFFFu, suma, 2);
        sumb += __shfl_xor_sync(0xFFFFFFFFu, sumb, 1);
        sumb += __shfl_xor_sync(0xFFFFFFFFu, sumb, 2);
        l_a = l_a * esa + suma;
        l_b = l_b * esb + sumb;

#pragma unroll
        for (int j = 0; j < 16; j++) {
            acc[j][0] *= esa; acc[j][1] *= esa;
            acc[j][2] *= esb; acc[j][3] *= esb;
        }

        // ---- PV: P (register repack) @ V, 16 hd n-tiles, 4 key k-chunks ----
#pragma unroll
        for (int kc = 0; kc < 4; kc++) {
            float p0 = c[2*kc][0],   p1 = c[2*kc][1];
            float p2 = c[2*kc][2],   p3 = c[2*kc][3];
            float p4 = c[2*kc+1][0], p5 = c[2*kc+1][1];
            float p6 = c[2*kc+1][2], p7 = c[2*kc+1][3];
            uint32_t ph[4], pl[4];
            ph[0] = packbf(p0, p1); ph[1] = packbf(p2, p3);
            ph[2] = packbf(p4, p5); ph[3] = packbf(p6, p7);
            {
                __nv_bfloat162* hp = (__nv_bfloat162*)ph;
                float2 f0 = __bfloat1622float2(hp[0]);
                float2 f1 = __bfloat1622float2(hp[1]);
                float2 f2 = __bfloat1622float2(hp[2]);
                float2 f3 = __bfloat1622float2(hp[3]);
                pl[0] = packbf(p0 - f0.x, p1 - f0.y);
                pl[1] = packbf(p2 - f1.x, p3 - f1.y);
                pl[2] = packbf(p4 - f2.x, p5 - f2.y);
                pl[3] = packbf(p6 - f3.x, p7 - f3.y);
            }
#pragma unroll
            for (int j = 0; j < 16; j++) {
                int rv = (j * 8 + g) * FLDV + kc * 8 + tg;
                uint32_t bhf[2] = { wVh[rv], wVh[rv + 4] };
                uint32_t blf[2] = { wVl[rv], wVl[rv + 4] };
                BMMA(acc[j], ph, bhf);
                BMMA(acc[j], ph, blf);
                BMMA(acc[j], pl, bhf);
            }
        }
    }

    // ---- normalize + write bf16 hi/lo (b,s,h,d) ----
    float inva = 1.0f / l_a, invb = 1.0f / l_b;
    int rowa = m0 + rowbase + g, rowb = rowa + 8;
#pragma unroll
    for (int j = 0; j < 16; j++) {
        int col = j * 8 + 2 * tg;
        float o0 = acc[j][0] * inva, o1 = acc[j][1] * inva;
        float o2 = acc[j][2] * invb, o3 = acc[j][3] * invb;
        uint32_t h0 = packbf(o0, o1), h1 = packbf(o2, o3);
        float2 f0 = __bfloat1622float2(*(__nv_bfloat162*)&h0);
        float2 f1 = __bfloat1622float2(*(__nv_bfloat162*)&h1);
        uint32_t l0 = packbf(o0 - f0.x, o1 - f0.y);
        uint32_t l1 = packbf(o2 - f1.x, o3 - f1.y);
        size_t da = (((size_t)b * Sc + rowa) * Hc + h) * HDc + col;
        size_t db = (((size_t)b * Sc + rowb) * Hc + h) * HDc + col;
        *(uint32_t*)(atth + da) = h0;
        *(uint32_t*)(attl + da) = l0;
        *(uint32_t*)(atth + db) = h1;
        *(uint32_t*)(attl + db) = l1;
    }
}

// ---------------------------------------------------------------------------
// Launch
// ---------------------------------------------------------------------------
extern "C" void kernel_launch(void* const* d_in, const int* in_sizes, int n_in,
                              void* d_out, int out_size)
{
    const float* x    = (const float*)d_in[0];
    const float* fcos = (const float*)d_in[1];
    const float* fsin = (const float*)d_in[2];
    // d_in[3] = mask (causality handled analytically)
    const float* WAq  = (const float*)d_in[4];
    const float* WAk  = (const float*)d_in[5];
    const float* WAv  = (const float*)d_in[6];
    const float* WBq  = (const float*)d_in[7];
    const float* WBk  = (const float*)d_in[8];
    const float* WBv  = (const float*)d_in[9];
    const float* Wo   = (const float*)d_in[10];
    // d_in[11] = start_pos (0)
    float* out = (float*)d_out;

    __nv_bfloat16 *gxh, *gxl, *gWTh, *gWTl, *gWoTh, *gWoTl;
    __nv_bfloat16 *gqh, *gql, *gkh, *gkl, *gvh, *gvl, *gvTh, *gvTl, *gatth, *gattl;
    float *gproj;
    cudaGetSymbolAddress((void**)&gxh,   g_xh);
    cudaGetSymbolAddress((void**)&gxl,   g_xl);
    cudaGetSymbolAddress((void**)&gWTh,  g_WTh);
    cudaGetSymbolAddress((void**)&gWTl,  g_WTl);
    cudaGetSymbolAddress((void**)&gWoTh, g_WoTh);
    cudaGetSymbolAddress((void**)&gWoTl, g_WoTl);
    cudaGetSymbolAddress((void**)&gproj, g_proj);
    cudaGetSymbolAddress((void**)&gqh,   g_qh);
    cudaGetSymbolAddress((void**)&gql,   g_ql);
    cudaGetSymbolAddress((void**)&gkh,   g_kh);
    cudaGetSymbolAddress((void**)&gkl,   g_kl);
    cudaGetSymbolAddress((void**)&gvh,   g_vh);
    cudaGetSymbolAddress((void**)&gvl,   g_vl);
    cudaGetSymbolAddress((void**)&gvTh,  g_vTh);
    cudaGetSymbolAddress((void**)&gvTl,  g_vTl);
    cudaGetSymbolAddress((void**)&gatth, g_atth);
    cudaGetSymbolAddress((void**)&gattl, g_attl);

    static int smem_set = 0;
    if (!smem_set) {
        cudaFuncSetAttribute(bf16x3_gemm_kernel,
                             cudaFuncAttributeMaxDynamicSharedMemorySize,
                             GSMEM_BYTES);
        cudaFuncSetAttribute(flash_kernel,
                             cudaFuncAttributeMaxDynamicSharedMemorySize,
                             FSMEM_BYTES);
        smem_set = 1;
    }

    const int M = Bc * Sc;   // 4096
    dim3 tsb(32, 8);

    // 0) Split x; transpose+split weights
    {
        long long n4 = (long long)Bc * Sc * Dc / 4;
        split_kernel<<<(unsigned)((n4 + 255) / 256), 256>>>(x, gxh, gxl, n4);
    }
    tsplit_kernel<<<dim3(192/32,  Dc/32), tsb>>>(WAq, Dc, 192,  gWTh, gWTl, OAq, Dc);
    tsplit_kernel<<<dim3(32/32,   Dc/32), tsb>>>(WAk, Dc, 32,   gWTh, gWTl, OAk, Dc);
    tsplit_kernel<<<dim3(32/32,   Dc/32), tsb>>>(WAv, Dc, 32,   gWTh, gWTl, OAv, Dc);
    tsplit_kernel<<<dim3(1536/32, Dc/32), tsb>>>(WBq, Dc, 1536, gWTh, gWTl, OBq, Dc);
    tsplit_kernel<<<dim3(256/32,  Dc/32), tsb>>>(WBk, Dc, 256,  gWTh, gWTl, OBk, Dc);
    tsplit_kernel<<<dim3(256/32,  Dc/32), tsb>>>(WBv, Dc, 256,  gWTh, gWTl, OBv, Dc);
    tsplit_kernel<<<dim3(Dc/32,   Dc/32), tsb>>>(Wo,  Dc, Dc,   gWoTh, gWoTl, 0, Dc);

    // 1) Fused projection GEMM
    {
        dim3 g(NTOT / GBN, M / GBM);
        bf16x3_gemm_kernel<<<g, 256, GSMEM_BYTES>>>(gxh, gxl, gWTh, gWTl,
                                                    gproj, M, NTOT, Dc, NTOT);
    }

    // 2) RoPE on B_q / B_k slices
    {
        long long tq = (long long)Bc * Sc * QRc * (HDc / 2);
        long long tk = (long long)Bc * Sc * Rc  * (HDc / 2);
        rope_kernel<<<(unsigned)((tq + 255) / 256), 256>>>(gproj, OBq, fcos, fsin, QRc, tq);
        rope_kernel<<<(unsigned)((tk + 255) / 256), 256>>>(gproj, OBk, fcos, fsin, Rc,  tk);
    }

    // 3) Rank combine -> bf16 hi/lo q,k,v (scales folded)
    {
        long long tot = (long long)Bc * Sc * Hc * HDc;
        combine_kernel<<<(unsigned)((tot + 255) / 256), 256>>>(gproj,
            gqh, gql, gkh, gkl, gvh, gvl);
    }

    // 3b) V transpose -> (b,h,d,s)
    vtrans_kernel<<<dim3(Sc/32, HDc/32, Bc*Hc), tsb>>>(gvh, gvl, gvTh, gvTl);

    // 4) Flash attention (bf16x3 tensor cores) -> att bf16 hi/lo
    {
        dim3 g(Sc / 64, Bc * Hc);
        flash_kernel<<<g, 128, FSMEM_BYTES>>>(gqh, gql, gkh, gkl, gvTh, gvTl,
                                              gatth, gattl);
    }

    // 5) Output projection -> d_out
    {
        dim3 g(Dc / GBN, M / GBM);
        bf16x3_gemm_kernel<<<g, 256, GSMEM_BYTES>>>(gatth, gattl, gWoTh, gWoTl,
                                                    out, M, Dc, Dc, Dc);
    }
}

// round 10
// speedup vs baseline: 4.6354x; 1.1849x over previous
#include <cuda_runtime.h>
#include <cuda_bf16.h>
#include <cuda_fp16.h>
#include <cstdint>

// Problem constants
#define Bc  2
#define Sc  2048
#define Dc  2048
#define Hc  16
#define HDc 128
#define QRc 12
#define Rc  2

// Fused projection column offsets: [WAq | WAk | WAv | WBq | WBk | WBv]
#define NTOT 2304
#define OAq  0
#define OAk  192
#define OAv  224
#define OBq  256
#define OBk  1792
#define OBv  2048

// ---------------------------------------------------------------------------
// Device scratch (no cudaMalloc allowed).
// ---------------------------------------------------------------------------
__device__ __half g_xh [(size_t)Bc*Sc*Dc];
__device__ __half g_xl [(size_t)Bc*Sc*Dc];
__device__ __half g_WT [(size_t)NTOT*Dc];             // fused proj weights fp16 [N][K]
__device__ __half g_WoT[(size_t)Dc*Dc];               // Wo^T fp16 [N][K]
__device__ float g_proj[(size_t)Bc*Sc*NTOT];
__device__ __nv_bfloat16 g_qh [(size_t)Bc*Sc*Hc*HDc]; // (b,s,h,d), scales folded
__device__ __nv_bfloat16 g_ql [(size_t)Bc*Sc*Hc*HDc];
__device__ __nv_bfloat16 g_kh [(size_t)Bc*Sc*Hc*HDc];
__device__ __nv_bfloat16 g_kl [(size_t)Bc*Sc*Hc*HDc];
__device__ __nv_bfloat16 g_vh [(size_t)Bc*Sc*Hc*HDc];
__device__ __nv_bfloat16 g_vl [(size_t)Bc*Sc*Hc*HDc];
__device__ __nv_bfloat16 g_vTh[(size_t)Bc*Hc*HDc*Sc]; // (b,h,d,s)
__device__ __nv_bfloat16 g_vTl[(size_t)Bc*Hc*HDc*Sc];
__device__ __half g_atth[(size_t)Bc*Sc*Hc*HDc];       // flash out, fp16 hi/lo
__device__ __half g_attl[(size_t)Bc*Sc*Hc*HDc];

// ---------------------------------------------------------------------------
// Helpers
// ---------------------------------------------------------------------------
__device__ __forceinline__ uint32_t s2u(const void* p) {
    return (uint32_t)__cvta_generic_to_shared(p);
}
__device__ __forceinline__ void cp16(uint32_t dst, const void* src) {
    asm volatile("cp.async.cg.shared.global [%0], [%1], 16;\n"
                 :: "r"(dst), "l"(src));
}
__device__ __forceinline__ void bsplit(float f, __nv_bfloat16& h, __nv_bfloat16& l) {
    h = __float2bfloat16_rn(f);
    l = __float2bfloat16_rn(f - __bfloat162float(h));
}
__device__ __forceinline__ void hsplit(float f, __half& h, __half& l) {
    h = __float2half_rn(f);
    l = __float2half_rn(f - __half2float(h));
}
__device__ __forceinline__ uint32_t packbf(float a, float b) {
    __nv_bfloat162 t = __floats2bfloat162_rn(a, b);
    return *(uint32_t*)&t;
}
__device__ __forceinline__ uint32_t packh(float a, float b) {
    __half2 t = __floats2half2_rn(a, b);
    return *(uint32_t*)&t;
}

// bf16 mma (flash)
#define BMMA(d, a, b) asm volatile( \
    "mma.sync.aligned.m16n8k16.row.col.f32.bf16.bf16.f32 " \
    "{%0,%1,%2,%3}, {%4,%5,%6,%7}, {%8,%9}, {%0,%1,%2,%3};" \
    : "+f"((d)[0]), "+f"((d)[1]), "+f"((d)[2]), "+f"((d)[3]) \
    : "r"((a)[0]), "r"((a)[1]), "r"((a)[2]), "r"((a)[3]), \
      "r"((b)[0]), "r"((b)[1]))

// fp16 mma (GEMMs)
#define HMMA(d, a, b) asm volatile( \
    "mma.sync.aligned.m16n8k16.row.col.f32.f16.f16.f32 " \
    "{%0,%1,%2,%3}, {%4,%5,%6,%7}, {%8,%9}, {%0,%1,%2,%3};" \
    : "+f"((d)[0]), "+f"((d)[1]), "+f"((d)[2]), "+f"((d)[3]) \
    : "r"((a)[0]), "r"((a)[1]), "r"((a)[2]), "r"((a)[3]), \
      "r"((b)[0]), "r"((b)[1]))

// ---------------------------------------------------------------------------
// Elementwise split: fp32 -> (hi, lo) fp16. n4 = elements/4.
// ---------------------------------------------------------------------------
__global__ void splith_kernel(const float* __restrict__ src,
                              __half* __restrict__ hi,
                              __half* __restrict__ lo, long long n4)
{
    long long i = (long long)blockIdx.x * blockDim.x + threadIdx.x;
    if (i >= n4) return;
    float4 f = ((const float4*)src)[i];
    __half h0, h1, h2, h3, l0, l1, l2, l3;
    hsplit(f.x, h0, l0); hsplit(f.y, h1, l1);
    hsplit(f.z, h2, l2); hsplit(f.w, h3, l3);
    ((__half2*)hi)[2*i]   = __half2(h0, h1);
    ((__half2*)hi)[2*i+1] = __half2(h2, h3);
    ((__half2*)lo)[2*i]   = __half2(l0, l1);
    ((__half2*)lo)[2*i+1] = __half2(l2, l3);
}

// ---------------------------------------------------------------------------
// Transpose to fp16: W [K][N] fp32 -> fp16 rows (rowOff+n) of [*][ldt].
// ---------------------------------------------------------------------------
__global__ void tsplit_kernel(const float* __restrict__ W, int K, int N,
                              __half* __restrict__ Th, int rowOff, int ldt)
{
    __shared__ float tile[32][33];
    int n0 = blockIdx.x * 32, k0 = blockIdx.y * 32;
    int tx = threadIdx.x, ty = threadIdx.y;
    for (int r = ty; r < 32; r += 8)
        tile[r][tx] = W[(size_t)(k0 + r) * N + n0 + tx];
    __syncthreads();
    for (int r = ty; r < 32; r += 8) {
        int n = n0 + r, k = k0 + tx;
        Th[(size_t)(rowOff + n) * ldt + k] = __float2half_rn(tile[tx][r]);
    }
}

// ---------------------------------------------------------------------------
// fp16x2 tensor-core GEMM: C = (Ah+Al)(MxK) @ Bh^T(NxK)^T, fp32 out.
// A exact (hi+lo fp16), B single fp16 (quantization ~2^-12, random sign).
// Computes Ah*Bh + Al*Bh with fp32 accumulate.
// CTA 256 thr = 8 warps, tile 128x128, K-step 32 halves, warp tile 64x32.
// Requirements: M%128==0, N%128==0, K%32==0.
// ---------------------------------------------------------------------------
#define GBM 128
#define GBN 128
#define GBK 32
#define LDW 20                       // smem words per row (16 data + 4 pad)
#define TW  (128 * LDW)
#define GSMEM_BYTES (2 * 3 * TW * 4) // 61440

__global__ __launch_bounds__(256) void f16x2_gemm_kernel(
    const __half* __restrict__ Ah, const __half* __restrict__ Al,
    const __half* __restrict__ Bh,
    float* __restrict__ C, int M, int N, int K, int ldc)
{
    extern __shared__ uint32_t gs[];

    int m0 = blockIdx.y * GBM;
    int n0 = blockIdx.x * GBN;
    int tid = threadIdx.x, warp = tid >> 5, lane = tid & 31;
    int wm = warp >> 2, wn = warp & 3;      // 2 x 4 warp grid
    int g  = lane >> 2, tg = lane & 3;

    float acc[4][4][4];
#pragma unroll
    for (int i = 0; i < 4; i++)
#pragma unroll
        for (int j = 0; j < 4; j++)
#pragma unroll
            for (int c = 0; c < 4; c++) acc[i][j][c] = 0.f;

    auto stage = [&](int kt, int buf) {
        uint32_t* base = gs + buf * 3 * TW;
        const __half* srcs[3] = {Ah, Al, Bh};
#pragma unroll
        for (int t = 0; t < 3; t++) {
            const __half* S = srcs[t];
            int r0 = (t < 2) ? m0 : n0;
            uint32_t* dst = base + t * TW;
#pragma unroll
            for (int l = 0; l < 2; l++) {
                int v = tid + l * 256;
                int row = v >> 2, cq = v & 3;   // 4 x 16B chunks per row
                cp16(s2u(dst + row * LDW + cq * 4),
                     S + (size_t)(r0 + row) * K + kt + cq * 8);
            }
        }
    };

    stage(0, 0);
    asm volatile("cp.async.commit_group;");

    int buf = 0;
    for (int kt = 0; kt < K; kt += GBK, buf ^= 1) {
        if (kt + GBK < K) {
            stage(kt + GBK, buf ^ 1);
            asm volatile("cp.async.commit_group;");
            asm volatile("cp.async.wait_group 1;");
        } else {
            asm volatile("cp.async.wait_group 0;");
        }
        __syncthreads();

        const uint32_t* cAh = gs + buf * 3 * TW;
        const uint32_t* cAl = cAh + TW;
        const uint32_t* cBh = cAh + 2 * TW;

#pragma unroll
        for (int ks = 0; ks < 2; ks++) {
            int kw = ks * 8;
            uint32_t ah[4][4], al[4][4], bh[4][2];
#pragma unroll
            for (int i = 0; i < 4; i++) {
                int b0 = (wm * 64 + i * 16 + g) * LDW + kw + tg;
                int b1 = b0 + 8 * LDW;
                ah[i][0] = cAh[b0]; ah[i][1] = cAh[b1];
                ah[i][2] = cAh[b0 + 4]; ah[i][3] = cAh[b1 + 4];
                al[i][0] = cAl[b0]; al[i][1] = cAl[b1];
                al[i][2] = cAl[b0 + 4]; al[i][3] = cAl[b1 + 4];
            }
#pragma unroll
            for (int j = 0; j < 4; j++) {
                int bb = (wn * 32 + j * 8 + g) * LDW + kw + tg;
                bh[j][0] = cBh[bb]; bh[j][1] = cBh[bb + 4];
            }
#pragma unroll
            for (int i = 0; i < 4; i++)
#pragma unroll
                for (int j = 0; j < 4; j++) {
                    HMMA(acc[i][j], ah[i], bh[j]);
                    HMMA(acc[i][j], al[i], bh[j]);
                }
        }
        __syncthreads();
    }

#pragma unroll
    for (int i = 0; i < 4; i++) {
        int row = m0 + wm * 64 + i * 16 + g;
#pragma unroll
        for (int j = 0; j < 4; j++) {
            int col = n0 + wn * 32 + j * 8 + 2 * tg;
            *(float2*)(C + (size_t)row * ldc + col) =
                make_float2(acc[i][j][0], acc[i][j][1]);
            *(float2*)(C + (size_t)(row + 8) * ldc + col) =
                make_float2(acc[i][j][2], acc[i][j][3]);
        }
    }
}

// ---------------------------------------------------------------------------
// Interleaved RoPE in-place on a column slice of g_proj.
// ---------------------------------------------------------------------------
__global__ void rope_kernel(float* __restrict__ proj, int colOff,
                            const float* __restrict__ fcos,
                            const float* __restrict__ fsin,
                            int Rdim, long long total)
{
    long long idx = (long long)blockIdx.x * blockDim.x + threadIdx.x;
    if (idx >= total) return;
    int i = (int)(idx % (HDc / 2));
    long long sr = idx / (HDc / 2);
    long long bs = sr / Rdim;
    int r = (int)(sr % Rdim);
    long long s = bs % Sc;
    float c  = fcos[s * (HDc / 2) + i];
    float sn = fsin[s * (HDc / 2) + i];
    float* p = proj + bs * NTOT + colOff + r * HDc + 2 * i;
    float t0 = p[0], t1 = p[1];
    p[0] = t0 * c - t1 * sn;
    p[1] = t0 * sn + t1 * c;
}

// ---------------------------------------------------------------------------
// Rank combine -> q,k,v in bf16 hi/lo (b,s,h,d). Scales folded.
// ---------------------------------------------------------------------------
__global__ void combine_kernel(const float* __restrict__ proj,
                               __nv_bfloat16* __restrict__ qh, __nv_bfloat16* __restrict__ ql,
                               __nv_bfloat16* __restrict__ kh, __nv_bfloat16* __restrict__ kl,
                               __nv_bfloat16* __restrict__ vh, __nv_bfloat16* __restrict__ vl)
{
    long long idx = (long long)blockIdx.x * blockDim.x + threadIdx.x;
    const long long total = (long long)Bc * Sc * Hc * HDc;
    if (idx >= total) return;
    int d = (int)(idx % HDc);
    int h = (int)((idx / HDc) % Hc);
    long long bs = idx / ((long long)HDc * Hc);
    const float* row = proj + bs * NTOT;

    float accq = 0.f;
#pragma unroll
    for (int r = 0; r < QRc; r++)
        accq += row[OAq + h * QRc + r] * row[OBq + r * HDc + d];
    accq *= (1.0f / QRc) * 0.08838834764831845f;   // 1/QR * 1/sqrt(HD)
    __nv_bfloat16 hh, ll;
    bsplit(accq, hh, ll); qh[idx] = hh; ql[idx] = ll;

    float acck = 0.f, accv = 0.f;
#pragma unroll
    for (int r = 0; r < Rc; r++) {
        acck += row[OAk + h * Rc + r] * row[OBk + r * HDc + d];
        accv += row[OAv + h * Rc + r] * row[OBv + r * HDc + d];
    }
    bsplit(acck * (1.0f / Rc), hh, ll); kh[idx] = hh; kl[idx] = ll;
    bsplit(accv * (1.0f / Rc), hh, ll); vh[idx] = hh; vl[idx] = ll;
}

// ---------------------------------------------------------------------------
// V transpose: (b,s,h,d) -> (b,h,d,s), bf16 hi+lo.
// ---------------------------------------------------------------------------
__global__ void vtrans_kernel(const __nv_bfloat16* __restrict__ vh,
                              const __nv_bfloat16* __restrict__ vl,
                              __nv_bfloat16* __restrict__ vTh,
                              __nv_bfloat16* __restrict__ vTl)
{
    __shared__ __nv_bfloat16 th[32][34];
    __shared__ __nv_bfloat16 tl[32][34];
    int s0 = blockIdx.x * 32, d0 = blockIdx.y * 32;
    int bh = blockIdx.z;
    int b = bh / Hc, h = bh % Hc;
    int tx = threadIdx.x, ty = threadIdx.y;
    for (int r = ty; r < 32; r += 8) {
        size_t src = (((size_t)b * Sc + s0 + r) * Hc + h) * HDc + d0 + tx;
        th[r][tx] = vh[src];
        tl[r][tx] = vl[src];
    }
    __syncthreads();
    for (int r = ty; r < 32; r += 8) {
        size_t dst = ((size_t)bh * HDc + d0 + r) * Sc + s0 + tx;
        vTh[dst] = th[tx][r];
        vTl[dst] = tl[tx][r];
    }
}

// ---------------------------------------------------------------------------
// Fused causal flash attention, bf16x3 tensor cores (round-9 validated).
// Only change: epilogue writes fp16 hi/lo for the fp16x2 output GEMM.
// ---------------------------------------------------------------------------
#define FLDQ 68
#define FLDV 36
#define FQW  (64 * FLDQ)
#define FVW  (128 * FLDV)
#define FSMEM_BYTES ((4 * FQW + 2 * FVW) * 4)   // 106496

__global__ __launch_bounds__(128) void flash_kernel(
    const __nv_bfloat16* __restrict__ qh, const __nv_bfloat16* __restrict__ ql,
    const __nv_bfloat16* __restrict__ kh, const __nv_bfloat16* __restrict__ kl,
    const __nv_bfloat16* __restrict__ vTh, const __nv_bfloat16* __restrict__ vTl,
    __half* __restrict__ atth, __half* __restrict__ attl)
{
    extern __shared__ uint32_t fs[];
    uint32_t* wQh = fs;
    uint32_t* wQl = wQh + FQW;
    uint32_t* wKh = wQl + FQW;
    uint32_t* wKl = wKh + FQW;
    uint32_t* wVh = wKl + FQW;
    uint32_t* wVl = wVh + FVW;

    int mt = gridDim.x - 1 - blockIdx.x;
    int m0 = mt * 64;
    int bh = blockIdx.y;
    int b  = bh / Hc, h = bh % Hc;

    int tid  = threadIdx.x;
    int warp = tid >> 5, lane = tid & 31;
    int g = lane >> 2, tg = lane & 3;
    int rowbase = warp * 16;

    // ---- stage Q (once), fully drained ----
#pragma unroll
    for (int l = 0; l < 8; l++) {
        int v = tid + l * 128;
        int row = v >> 4, cq = v & 15;
        size_t src = (((size_t)b * Sc + m0 + row) * Hc + h) * HDc + cq * 8;
        cp16(s2u(wQh + row * FLDQ + cq * 4), qh + src);
        cp16(s2u(wQl + row * FLDQ + cq * 4), ql + src);
    }
    asm volatile("cp.async.commit_group;");
    asm volatile("cp.async.wait_group 0;");
    __syncthreads();

    float acc[16][4];
#pragma unroll
    for (int j = 0; j < 16; j++)
#pragma unroll
        for (int c = 0; c < 4; c++) acc[j][c] = 0.f;
    float m_a = -1e30f, m_b = -1e30f, l_a = 0.f, l_b = 0.f;

    for (int t = 0; t <= mt; t++) {
        int n0 = t * 64;

        __syncthreads();
#pragma unroll
        for (int l = 0; l < 8; l++) {
            int v = tid + l * 128;
            int row = v >> 4, cq = v & 15;
            size_t src = (((size_t)b * Sc + n0 + row) * Hc + h) * HDc + cq * 8;
            cp16(s2u(wKh + row * FLDQ + cq * 4), kh + src);
            cp16(s2u(wKl + row * FLDQ + cq * 4), kl + src);
        }
#pragma unroll
        for (int l = 0; l < 8; l++) {
            int v = tid + l * 128;
            int row = v >> 3, cq = v & 7;
            size_t src = ((size_t)bh * HDc + row) * Sc + n0 + cq * 8;
            cp16(s2u(wVh + row * FLDV + cq * 4), vTh + src);
            cp16(s2u(wVl + row * FLDV + cq * 4), vTl + src);
        }
        asm volatile("cp.async.commit_group;");
        asm volatile("cp.async.wait_group 0;");
        __syncthreads();

        // ---- S = Q K^T (bf16x3) ----
        float c[8][4];
#pragma unroll
        for (int n = 0; n < 8; n++)
#pragma unroll
            for (int i = 0; i < 4; i++) c[n][i] = 0.f;

#pragma unroll
        for (int kk = 0; kk < 8; kk++) {
            uint32_t ah[4], al[4];
            int ra = (rowbase + g) * FLDQ + kk * 8 + tg;
            int rb = (rowbase + g + 8) * FLDQ + kk * 8 + tg;
            ah[0] = wQh[ra]; ah[1] = wQh[rb]; ah[2] = wQh[ra + 4]; ah[3] = wQh[rb + 4];
            al[0] = wQl[ra]; al[1] = wQl[rb]; al[2] = wQl[ra + 4]; al[3] = wQl[rb + 4];
#pragma unroll
            for (int n = 0; n < 8; n++) {
                int rk = (n * 8 + g) * FLDQ + kk * 8 + tg;
                uint32_t bhf[2] = { wKh[rk], wKh[rk + 4] };
                uint32_t blf[2] = { wKl[rk], wKl[rk + 4] };
                BMMA(c[n], ah, bhf);
                BMMA(c[n], ah, blf);
                BMMA(c[n], al, bhf);
            }
        }

        if (t == mt) {
            int ra = rowbase + g, rb = ra + 8;
#pragma unroll
            for (int n = 0; n < 8; n++) {
                int c0 = n * 8 + 2 * tg, c1 = c0 + 1;
                if (c0 > ra) c[n][0] = -1e30f;
                if (c1 > ra) c[n][1] = -1e30f;
                if (c0 > rb) c[n][2] = -1e30f;
                if (c1 > rb) c[n][3] = -1e30f;
            }
        }

        float mxa = -1e30f, mxb = -1e30f;
#pragma unroll
        for (int n = 0; n < 8; n++) {
            mxa = fmaxf(mxa, fmaxf(c[n][0], c[n][1]));
            mxb = fmaxf(mxb, fmaxf(c[n][2], c[n][3]));
        }
        mxa = fmaxf(mxa, __shfl_xor_sync(0xFFFFFFFFu, mxa, 1));
        mxa = fmaxf(mxa, __shfl_xor_sync(0xFFFFFFFFu, mxa, 2));
        mxb = fmaxf(mxb, __shfl_xor_sync(0xFFFFFFFFu, mxb, 1));
        mxb = fmaxf(mxb, __shfl_xor_sync(0xFFFFFFFFu, mxb, 2));

        float mna = fmaxf(m_a, mxa), mnb = fmaxf(m_b, mxb);
        float esa = __expf(m_a - mna), esb = __expf(m_b - mnb);
        m_a = mna; m_b = mnb;

        float suma = 0.f, sumb = 0.f;
#pragma unroll
        for (int n = 0; n < 8; n++) {
            c[n][0] = __expf(c[n][0] - mna);
            c[n][1] = __expf(c[n][1] - mna);
            c[n][2] = __expf(c[n][2] - mnb);
            c[n][3] = __expf(c[n][3] - mnb);
            suma += c[n][0] + c[n][1];
            sumb += c[n][2] + c[n][3];
        }
        suma += __shfl_xor_sync(0xFFFFFFFFu, suma, 1);
        suma += __shfl_xor_sync(0xFFFFFFFFu, suma, 2);
        sumb += __shfl_xor_sync(0xFFFFFFFFu, sumb, 1);
        sumb += __shfl_xor_sync(0xFFFFFFFFu, sumb, 2);
        l_a = l_a * esa + suma;
        l_b = l_b * esb + sumb;

#pragma unroll
        for (int j = 0; j < 16; j++) {
            acc[j][0] *= esa; acc[j][1] *= esa;
            acc[j][2] *= esb; acc[j][3] *= esb;
        }

#pragma unroll
        for (int kc = 0; kc < 4; kc++) {
            float p0 = c[2*kc][0],   p1 = c[2*kc][1];
            float p2 = c[2*kc][2],   p3 = c[2*kc][3];
            float p4 = c[2*kc+1][0], p5 = c[2*kc+1][1];
            float p6 = c[2*kc+1][2], p7 = c[2*kc+1][3];
            uint32_t ph[4], pl[4];
            ph[0] = packbf(p0, p1); ph[1] = packbf(p2, p3);
            ph[2] = packbf(p4, p5); ph[3] = packbf(p6, p7);
            {
                __nv_bfloat162* hp = (__nv_bfloat162*)ph;
                float2 f0 = __bfloat1622float2(hp[0]);
                float2 f1 = __bfloat1622float2(hp[1]);
                float2 f2 = __bfloat1622float2(hp[2]);
                float2 f3 = __bfloat1622float2(hp[3]);
                pl[0] = packbf(p0 - f0.x, p1 - f0.y);
                pl[1] = packbf(p2 - f1.x, p3 - f1.y);
                pl[2] = packbf(p4 - f2.x, p5 - f2.y);
                pl[3] = packbf(p6 - f3.x, p7 - f3.y);
            }
#pragma unroll
            for (int j = 0; j < 16; j++) {
                int rv = (j * 8 + g) * FLDV + kc * 8 + tg;
                uint32_t bhf[2] = { wVh[rv], wVh[rv + 4] };
                uint32_t blf[2] = { wVl[rv], wVl[rv + 4] };
                BMMA(acc[j], ph, bhf);
                BMMA(acc[j], ph, blf);
                BMMA(acc[j], pl, bhf);
            }
        }
    }

    // ---- normalize + write fp16 hi/lo (b,s,h,d) ----
    float inva = 1.0f / l_a, invb = 1.0f / l_b;
    int rowa = m0 + rowbase + g, rowb = rowa + 8;
#pragma unroll
    for (int j = 0; j < 16; j++) {
        int col = j * 8 + 2 * tg;
        float o0 = acc[j][0] * inva, o1 = acc[j][1] * inva;
        float o2 = acc[j][2] * invb, o3 = acc[j][3] * invb;
        uint32_t h0 = packh(o0, o1), h1 = packh(o2, o3);
        float2 f0 = __half22float2(*(__half2*)&h0);
        float2 f1 = __half22float2(*(__half2*)&h1);
        uint32_t l0 = packh(o0 - f0.x, o1 - f0.y);
        uint32_t l1 = packh(o2 - f1.x, o3 - f1.y);
        size_t da = (((size_t)b * Sc + rowa) * Hc + h) * HDc + col;
        size_t db = (((size_t)b * Sc + rowb) * Hc + h) * HDc + col;
        *(uint32_t*)(atth + da) = h0;
        *(uint32_t*)(attl + da) = l0;
        *(uint32_t*)(atth + db) = h1;
        *(uint32_t*)(attl + db) = l1;
    }
}

// ---------------------------------------------------------------------------
// Launch
// ---------------------------------------------------------------------------
extern "C" void kernel_launch(void* const* d_in, const int* in_sizes, int n_in,
                              void* d_out, int out_size)
{
    const float* x    = (const float*)d_in[0];
    const float* fcos = (const float*)d_in[1];
    const float* fsin = (const float*)d_in[2];
    // d_in[3] = mask (causality handled analytically)
    const float* WAq  = (const float*)d_in[4];
    const float* WAk  = (const float*)d_in[5];
    const float* WAv  = (const float*)d_in[6];
    const float* WBq  = (const float*)d_in[7];
    const float* WBk  = (const float*)d_in[8];
    const float* WBv  = (const float*)d_in[9];
    const float* Wo   = (const float*)d_in[10];
    // d_in[11] = start_pos (0)
    float* out = (float*)d_out;

    __half *gxh, *gxl, *gWT, *gWoT, *gatth, *gattl;
    __nv_bfloat16 *gqh, *gql, *gkh, *gkl, *gvh, *gvl, *gvTh, *gvTl;
    float *gproj;
    cudaGetSymbolAddress((void**)&gxh,   g_xh);
    cudaGetSymbolAddress((void**)&gxl,   g_xl);
    cudaGetSymbolAddress((void**)&gWT,   g_WT);
    cudaGetSymbolAddress((void**)&gWoT,  g_WoT);
    cudaGetSymbolAddress((void**)&gproj, g_proj);
    cudaGetSymbolAddress((void**)&gqh,   g_qh);
    cudaGetSymbolAddress((void**)&gql,   g_ql);
    cudaGetSymbolAddress((void**)&gkh,   g_kh);
    cudaGetSymbolAddress((void**)&gkl,   g_kl);
    cudaGetSymbolAddress((void**)&gvh,   g_vh);
    cudaGetSymbolAddress((void**)&gvl,   g_vl);
    cudaGetSymbolAddress((void**)&gvTh,  g_vTh);
    cudaGetSymbolAddress((void**)&gvTl,  g_vTl);
    cudaGetSymbolAddress((void**)&gatth, g_atth);
    cudaGetSymbolAddress((void**)&gattl, g_attl);

    static int smem_set = 0;
    if (!smem_set) {
        cudaFuncSetAttribute(f16x2_gemm_kernel,
                             cudaFuncAttributeMaxDynamicSharedMemorySize,
                             GSMEM_BYTES);
        cudaFuncSetAttribute(flash_kernel,
                             cudaFuncAttributeMaxDynamicSharedMemorySize,
                             FSMEM_BYTES);
        smem_set = 1;
    }

    const int M = Bc * Sc;   // 4096
    dim3 tsb(32, 8);

    // 0) Split x (fp16 hi/lo); transpose weights to fp16
    {
        long long n4 = (long long)Bc * Sc * Dc / 4;
        splith_kernel<<<(unsigned)((n4 + 255) / 256), 256>>>(x, gxh, gxl, n4);
    }
    tsplit_kernel<<<dim3(192/32,  Dc/32), tsb>>>(WAq, Dc, 192,  gWT, OAq, Dc);
    tsplit_kernel<<<dim3(32/32,   Dc/32), tsb>>>(WAk, Dc, 32,   gWT, OAk, Dc);
    tsplit_kernel<<<dim3(32/32,   Dc/32), tsb>>>(WAv, Dc, 32,   gWT, OAv, Dc);
    tsplit_kernel<<<dim3(1536/32, Dc/32), tsb>>>(WBq, Dc, 1536, gWT, OBq, Dc);
    tsplit_kernel<<<dim3(256/32,  Dc/32), tsb>>>(WBk, Dc, 256,  gWT, OBk, Dc);
    tsplit_kernel<<<dim3(256/32,  Dc/32), tsb>>>(WBv, Dc, 256,  gWT, OBv, Dc);
    tsplit_kernel<<<dim3(Dc/32,   Dc/32), tsb>>>(Wo,  Dc, Dc,   gWoT, 0, Dc);

    // 1) Fused projection GEMM (fp16x2)
    {
        dim3 g(NTOT / GBN, M / GBM);
        f16x2_gemm_kernel<<<g, 256, GSMEM_BYTES>>>(gxh, gxl, gWT,
                                                   gproj, M, NTOT, Dc, NTOT);
    }

    // 2) RoPE on B_q / B_k slices
    {
        long long tq = (long long)Bc * Sc * QRc * (HDc / 2);
        long long tk = (long long)Bc * Sc * Rc  * (HDc / 2);
        rope_kernel<<<(unsigned)((tq + 255) / 256), 256>>>(gproj, OBq, fcos, fsin, QRc, tq);
        rope_kernel<<<(unsigned)((tk + 255) / 256), 256>>>(gproj, OBk, fcos, fsin, Rc,  tk);
    }

    // 3) Rank combine -> bf16 hi/lo q,k,v (scales folded)
    {
        long long tot = (long long)Bc * Sc * Hc * HDc;
        combine_kernel<<<(unsigned)((tot + 255) / 256), 256>>>(gproj,
            gqh, gql, gkh, gkl, gvh, gvl);
    }

    // 3b) V transpose -> (b,h,d,s)
    vtrans_kernel<<<dim3(Sc/32, HDc/32, Bc*Hc), tsb>>>(gvh, gvl, gvTh, gvTl);

    // 4) Flash attention (bf16x3) -> att fp16 hi/lo
    {
        dim3 g(Sc / 64, Bc * Hc);
        flash_kernel<<<g, 128, FSMEM_BYTES>>>(gqh, gql, gkh, gkl, gvTh, gvTl,
                                              gatth, gattl);
    }

    // 5) Output projection (fp16x2) -> d_out
    {
        dim3 g(Dc / GBN, M / GBM);
        f16x2_gemm_kernel<<<g, 256, GSMEM_BYTES>>>(gatth, gattl, gWoT,
                                                   out, M, Dc, Dc, Dc);
    }
}

// round 11
// speedup vs baseline: 5.2607x; 1.1349x over previous
#include <cuda_runtime.h>
#include <cuda_bf16.h>
#include <cuda_fp16.h>
#include <cstdint>

// Problem constants
#define Bc  2
#define Sc  2048
#define Dc  2048
#define Hc  16
#define HDc 128
#define QRc 12
#define Rc  2

// Fused projection column offsets: [WAq | WAk | WAv | WBq | WBk | WBv]
#define NTOT 2304
#define OAq  0
#define OAk  192
#define OAv  224
#define OBq  256
#define OBk  1792
#define OBv  2048

// ---------------------------------------------------------------------------
// Device scratch (no cudaMalloc allowed).
// ---------------------------------------------------------------------------
__device__ __half g_xh [(size_t)Bc*Sc*Dc];
__device__ __half g_xl [(size_t)Bc*Sc*Dc];
__device__ __half g_WT [(size_t)NTOT*Dc];             // fused proj weights fp16 [N][K]
__device__ __half g_WoT[(size_t)Dc*Dc];               // Wo^T fp16 [N][K]
__device__ float g_proj[(size_t)Bc*Sc*NTOT];
__device__ __half g_qh [(size_t)Bc*Sc*Hc*HDc];        // (b,s,h,d), scales folded
__device__ __half g_ql [(size_t)Bc*Sc*Hc*HDc];
__device__ __half g_k  [(size_t)Bc*Sc*Hc*HDc];        // single fp16
__device__ __half g_vh [(size_t)Bc*Sc*Hc*HDc];
__device__ __half g_vl [(size_t)Bc*Sc*Hc*HDc];
__device__ __half g_vTh[(size_t)Bc*Hc*HDc*Sc];        // (b,h,d,s)
__device__ __half g_vTl[(size_t)Bc*Hc*HDc*Sc];
__device__ __half g_atth[(size_t)Bc*Sc*Hc*HDc];       // flash out, fp16 hi/lo
__device__ __half g_attl[(size_t)Bc*Sc*Hc*HDc];

// ---------------------------------------------------------------------------
// Helpers
// ---------------------------------------------------------------------------
__device__ __forceinline__ uint32_t s2u(const void* p) {
    return (uint32_t)__cvta_generic_to_shared(p);
}
__device__ __forceinline__ void cp16(uint32_t dst, const void* src) {
    asm volatile("cp.async.cg.shared.global [%0], [%1], 16;\n"
                 :: "r"(dst), "l"(src));
}
__device__ __forceinline__ void hsplit(float f, __half& h, __half& l) {
    h = __float2half_rn(f);
    l = __float2half_rn(f - __half2float(h));
}
__device__ __forceinline__ uint32_t packh(float a, float b) {
    __half2 t = __floats2half2_rn(a, b);
    return *(uint32_t*)&t;
}

// fp16 mma
#define HMMA(d, a, b) asm volatile( \
    "mma.sync.aligned.m16n8k16.row.col.f32.f16.f16.f32 " \
    "{%0,%1,%2,%3}, {%4,%5,%6,%7}, {%8,%9}, {%0,%1,%2,%3};" \
    : "+f"((d)[0]), "+f"((d)[1]), "+f"((d)[2]), "+f"((d)[3]) \
    : "r"((a)[0]), "r"((a)[1]), "r"((a)[2]), "r"((a)[3]), \
      "r"((b)[0]), "r"((b)[1]))

// ---------------------------------------------------------------------------
// Elementwise split: fp32 -> (hi, lo) fp16. n4 = elements/4.
// ---------------------------------------------------------------------------
__global__ void splith_kernel(const float* __restrict__ src,
                              __half* __restrict__ hi,
                              __half* __restrict__ lo, long long n4)
{
    long long i = (long long)blockIdx.x * blockDim.x + threadIdx.x;
    if (i >= n4) return;
    float4 f = ((const float4*)src)[i];
    __half h0, h1, h2, h3, l0, l1, l2, l3;
    hsplit(f.x, h0, l0); hsplit(f.y, h1, l1);
    hsplit(f.z, h2, l2); hsplit(f.w, h3, l3);
    ((__half2*)hi)[2*i]   = __half2(h0, h1);
    ((__half2*)hi)[2*i+1] = __half2(h2, h3);
    ((__half2*)lo)[2*i]   = __half2(l0, l1);
    ((__half2*)lo)[2*i+1] = __half2(l2, l3);
}

// ---------------------------------------------------------------------------
// Transpose to fp16: W [K][N] fp32 -> fp16 rows (rowOff+n) of [*][ldt].
// ---------------------------------------------------------------------------
__global__ void tsplit_kernel(const float* __restrict__ W, int K, int N,
                              __half* __restrict__ Th, int rowOff, int ldt)
{
    __shared__ float tile[32][33];
    int n0 = blockIdx.x * 32, k0 = blockIdx.y * 32;
    int tx = threadIdx.x, ty = threadIdx.y;
    for (int r = ty; r < 32; r += 8)
        tile[r][tx] = W[(size_t)(k0 + r) * N + n0 + tx];
    __syncthreads();
    for (int r = ty; r < 32; r += 8) {
        int n = n0 + r, k = k0 + tx;
        Th[(size_t)(rowOff + n) * ldt + k] = __float2half_rn(tile[tx][r]);
    }
}

// ---------------------------------------------------------------------------
// fp16x2 tensor-core GEMM (validated round 10, unchanged).
// ---------------------------------------------------------------------------
#define GBM 128
#define GBN 128
#define GBK 32
#define LDW 20
#define TW  (128 * LDW)
#define GSMEM_BYTES (2 * 3 * TW * 4) // 61440

__global__ __launch_bounds__(256) void f16x2_gemm_kernel(
    const __half* __restrict__ Ah, const __half* __restrict__ Al,
    const __half* __restrict__ Bh,
    float* __restrict__ C, int M, int N, int K, int ldc)
{
    extern __shared__ uint32_t gs[];

    int m0 = blockIdx.y * GBM;
    int n0 = blockIdx.x * GBN;
    int tid = threadIdx.x, warp = tid >> 5, lane = tid & 31;
    int wm = warp >> 2, wn = warp & 3;
    int g  = lane >> 2, tg = lane & 3;

    float acc[4][4][4];
#pragma unroll
    for (int i = 0; i < 4; i++)
#pragma unroll
        for (int j = 0; j < 4; j++)
#pragma unroll
            for (int c = 0; c < 4; c++) acc[i][j][c] = 0.f;

    auto stage = [&](int kt, int buf) {
        uint32_t* base = gs + buf * 3 * TW;
        const __half* srcs[3] = {Ah, Al, Bh};
#pragma unroll
        for (int t = 0; t < 3; t++) {
            const __half* S = srcs[t];
            int r0 = (t < 2) ? m0 : n0;
            uint32_t* dst = base + t * TW;
#pragma unroll
            for (int l = 0; l < 2; l++) {
                int v = tid + l * 256;
                int row = v >> 2, cq = v & 3;
                cp16(s2u(dst + row * LDW + cq * 4),
                     S + (size_t)(r0 + row) * K + kt + cq * 8);
            }
        }
    };

    stage(0, 0);
    asm volatile("cp.async.commit_group;");

    int buf = 0;
    for (int kt = 0; kt < K; kt += GBK, buf ^= 1) {
        if (kt + GBK < K) {
            stage(kt + GBK, buf ^ 1);
            asm volatile("cp.async.commit_group;");
            asm volatile("cp.async.wait_group 1;");
        } else {
            asm volatile("cp.async.wait_group 0;");
        }
        __syncthreads();

        const uint32_t* cAh = gs + buf * 3 * TW;
        const uint32_t* cAl = cAh + TW;
        const uint32_t* cBh = cAh + 2 * TW;

#pragma unroll
        for (int ks = 0; ks < 2; ks++) {
            int kw = ks * 8;
            uint32_t ah[4][4], al[4][4], bh[4][2];
#pragma unroll
            for (int i = 0; i < 4; i++) {
                int b0 = (wm * 64 + i * 16 + g) * LDW + kw + tg;
                int b1 = b0 + 8 * LDW;
                ah[i][0] = cAh[b0]; ah[i][1] = cAh[b1];
                ah[i][2] = cAh[b0 + 4]; ah[i][3] = cAh[b1 + 4];
                al[i][0] = cAl[b0]; al[i][1] = cAl[b1];
                al[i][2] = cAl[b0 + 4]; al[i][3] = cAl[b1 + 4];
            }
#pragma unroll
            for (int j = 0; j < 4; j++) {
                int bb = (wn * 32 + j * 8 + g) * LDW + kw + tg;
                bh[j][0] = cBh[bb]; bh[j][1] = cBh[bb + 4];
            }
#pragma unroll
            for (int i = 0; i < 4; i++)
#pragma unroll
                for (int j = 0; j < 4; j++) {
                    HMMA(acc[i][j], ah[i], bh[j]);
                    HMMA(acc[i][j], al[i], bh[j]);
                }
        }
        __syncthreads();
    }

#pragma unroll
    for (int i = 0; i < 4; i++) {
        int row = m0 + wm * 64 + i * 16 + g;
#pragma unroll
        for (int j = 0; j < 4; j++) {
            int col = n0 + wn * 32 + j * 8 + 2 * tg;
            *(float2*)(C + (size_t)row * ldc + col) =
                make_float2(acc[i][j][0], acc[i][j][1]);
            *(float2*)(C + (size_t)(row + 8) * ldc + col) =
                make_float2(acc[i][j][2], acc[i][j][3]);
        }
    }
}

// ---------------------------------------------------------------------------
// Interleaved RoPE in-place on a column slice of g_proj.
// ---------------------------------------------------------------------------
__global__ void rope_kernel(float* __restrict__ proj, int colOff,
                            const float* __restrict__ fcos,
                            const float* __restrict__ fsin,
                            int Rdim, long long total)
{
    long long idx = (long long)blockIdx.x * blockDim.x + threadIdx.x;
    if (idx >= total) return;
    int i = (int)(idx % (HDc / 2));
    long long sr = idx / (HDc / 2);
    long long bs = sr / Rdim;
    int r = (int)(sr % Rdim);
    long long s = bs % Sc;
    float c  = fcos[s * (HDc / 2) + i];
    float sn = fsin[s * (HDc / 2) + i];
    float* p = proj + bs * NTOT + colOff + r * HDc + 2 * i;
    float t0 = p[0], t1 = p[1];
    p[0] = t0 * c - t1 * sn;
    p[1] = t0 * sn + t1 * c;
}

// ---------------------------------------------------------------------------
// Rank combine -> q (fp16 hi/lo), k (single fp16), v (fp16 hi/lo), (b,s,h,d).
// Scales folded; q also carries 1/sqrt(HD).
// ---------------------------------------------------------------------------
__global__ void combine_kernel(const float* __restrict__ proj,
                               __half* __restrict__ qh, __half* __restrict__ ql,
                               __half* __restrict__ k,
                               __half* __restrict__ vh, __half* __restrict__ vl)
{
    long long idx = (long long)blockIdx.x * blockDim.x + threadIdx.x;
    const long long total = (long long)Bc * Sc * Hc * HDc;
    if (idx >= total) return;
    int d = (int)(idx % HDc);
    int h = (int)((idx / HDc) % Hc);
    long long bs = idx / ((long long)HDc * Hc);
    const float* row = proj + bs * NTOT;

    float accq = 0.f;
#pragma unroll
    for (int r = 0; r < QRc; r++)
        accq += row[OAq + h * QRc + r] * row[OBq + r * HDc + d];
    accq *= (1.0f / QRc) * 0.08838834764831845f;   // 1/QR * 1/sqrt(HD)
    __half hh, ll;
    hsplit(accq, hh, ll); qh[idx] = hh; ql[idx] = ll;

    float acck = 0.f, accv = 0.f;
#pragma unroll
    for (int r = 0; r < Rc; r++) {
        acck += row[OAk + h * Rc + r] * row[OBk + r * HDc + d];
        accv += row[OAv + h * Rc + r] * row[OBv + r * HDc + d];
    }
    k[idx] = __float2half_rn(acck * (1.0f / Rc));
    hsplit(accv * (1.0f / Rc), hh, ll); vh[idx] = hh; vl[idx] = ll;
}

// ---------------------------------------------------------------------------
// V transpose: (b,s,h,d) -> (b,h,d,s), fp16 hi+lo.
// ---------------------------------------------------------------------------
__global__ void vtrans_kernel(const __half* __restrict__ vh,
                              const __half* __restrict__ vl,
                              __half* __restrict__ vTh,
                              __half* __restrict__ vTl)
{
    __shared__ __half th[32][34];
    __shared__ __half tl[32][34];
    int s0 = blockIdx.x * 32, d0 = blockIdx.y * 32;
    int bh = blockIdx.z;
    int b = bh / Hc, h = bh % Hc;
    int tx = threadIdx.x, ty = threadIdx.y;
    for (int r = ty; r < 32; r += 8) {
        size_t src = (((size_t)b * Sc + s0 + r) * Hc + h) * HDc + d0 + tx;
        th[r][tx] = vh[src];
        tl[r][tx] = vl[src];
    }
    __syncthreads();
    for (int r = ty; r < 32; r += 8) {
        size_t dst = ((size_t)bh * HDc + d0 + r) * Sc + s0 + tx;
        vTh[dst] = th[tx][r];
        vTl[dst] = tl[tx][r];
    }
}

// ---------------------------------------------------------------------------
// Fused causal flash attention, fp16x2 tensor cores.
// CTA: 128 threads (4 warps). Tile 64 q-rows x 64 keys, HD=128.
// S  = (Qh + Ql) * K      (K single fp16, 2 mmas)
// PV = P * (Vh + Vl)      (P single fp16, 2 mmas)
// smem: Qh/Ql [64][68w], K [64][68w], Vh/Vl [128][36w] = 89088 B.
// ---------------------------------------------------------------------------
#define FLDQ 68
#define FLDV 36
#define FQW  (64 * FLDQ)             // 4352 words
#define FVW  (128 * FLDV)            // 4608 words
#define FSMEM_BYTES ((3 * FQW + 2 * FVW) * 4)   // 89088

__global__ __launch_bounds__(128) void flash_kernel(
    const __half* __restrict__ qh, const __half* __restrict__ ql,
    const __half* __restrict__ kk_,
    const __half* __restrict__ vTh, const __half* __restrict__ vTl,
    __half* __restrict__ atth, __half* __restrict__ attl)
{
    extern __shared__ uint32_t fs[];
    uint32_t* wQh = fs;
    uint32_t* wQl = wQh + FQW;
    uint32_t* wK  = wQl + FQW;
    uint32_t* wVh = wK + FQW;
    uint32_t* wVl = wVh + FVW;

    int mt = gridDim.x - 1 - blockIdx.x;     // long blocks first
    int m0 = mt * 64;
    int bh = blockIdx.y;
    int b  = bh / Hc, h = bh % Hc;

    int tid  = threadIdx.x;
    int warp = tid >> 5, lane = tid & 31;
    int g = lane >> 2, tg = lane & 3;
    int rowbase = warp * 16;

    // ---- stage Q (once), fully drained ----
#pragma unroll
    for (int l = 0; l < 8; l++) {
        int v = tid + l * 128;                // 1024 chunks: 64 rows x 16
        int row = v >> 4, cq = v & 15;
        size_t src = (((size_t)b * Sc + m0 + row) * Hc + h) * HDc + cq * 8;
        cp16(s2u(wQh + row * FLDQ + cq * 4), qh + src);
        cp16(s2u(wQl + row * FLDQ + cq * 4), ql + src);
    }
    asm volatile("cp.async.commit_group;");
    asm volatile("cp.async.wait_group 0;");
    __syncthreads();

    float acc[16][4];
#pragma unroll
    for (int j = 0; j < 16; j++)
#pragma unroll
        for (int c = 0; c < 4; c++) acc[j][c] = 0.f;
    float m_a = -1e30f, m_b = -1e30f, l_a = 0.f, l_b = 0.f;

    for (int t = 0; t <= mt; t++) {
        int n0 = t * 64;

        __syncthreads();                     // previous iter done with K/V smem
        // ---- stage K tile (single fp16) ----
#pragma unroll
        for (int l = 0; l < 8; l++) {
            int v = tid + l * 128;
            int row = v >> 4, cq = v & 15;
            size_t src = (((size_t)b * Sc + n0 + row) * Hc + h) * HDc + cq * 8;
            cp16(s2u(wK + row * FLDQ + cq * 4), kk_ + src);
        }
        // ---- stage V tile (transposed source, hi/lo) ----
#pragma unroll
        for (int l = 0; l < 8; l++) {
            int v = tid + l * 128;            // 1024 chunks: 128 rows x 8
            int row = v >> 3, cq = v & 7;
            size_t src = ((size_t)bh * HDc + row) * Sc + n0 + cq * 8;
            cp16(s2u(wVh + row * FLDV + cq * 4), vTh + src);
            cp16(s2u(wVl + row * FLDV + cq * 4), vTl + src);
        }
        asm volatile("cp.async.commit_group;");
        asm volatile("cp.async.wait_group 0;");
        __syncthreads();

        // ---- S = (Qh + Ql) K^T, 8 n-tiles of n8, 2 mmas each ----
        float c[8][4];
#pragma unroll
        for (int n = 0; n < 8; n++)
#pragma unroll
            for (int i = 0; i < 4; i++) c[n][i] = 0.f;

#pragma unroll
        for (int kk = 0; kk < 8; kk++) {
            uint32_t ah[4], al[4];
            int ra = (rowbase + g) * FLDQ + kk * 8 + tg;
            int rb = (rowbase + g + 8) * FLDQ + kk * 8 + tg;
            ah[0] = wQh[ra]; ah[1] = wQh[rb]; ah[2] = wQh[ra + 4]; ah[3] = wQh[rb + 4];
            al[0] = wQl[ra]; al[1] = wQl[rb]; al[2] = wQl[ra + 4]; al[3] = wQl[rb + 4];
#pragma unroll
            for (int n = 0; n < 8; n++) {
                int rk = (n * 8 + g) * FLDQ + kk * 8 + tg;
                uint32_t bf[2] = { wK[rk], wK[rk + 4] };
                HMMA(c[n], ah, bf);
                HMMA(c[n], al, bf);
            }
        }

        // ---- causal mask on the diagonal tile ----
        if (t == mt) {
            int ra = rowbase + g, rb = ra + 8;
#pragma unroll
            for (int n = 0; n < 8; n++) {
                int c0 = n * 8 + 2 * tg, c1 = c0 + 1;
                if (c0 > ra) c[n][0] = -1e30f;
                if (c1 > ra) c[n][1] = -1e30f;
                if (c0 > rb) c[n][2] = -1e30f;
                if (c1 > rb) c[n][3] = -1e30f;
            }
        }

        // ---- online softmax (rows g and g+8 of this warp) ----
        float mxa = -1e30f, mxb = -1e30f;
#pragma unroll
        for (int n = 0; n < 8; n++) {
            mxa = fmaxf(mxa, fmaxf(c[n][0], c[n][1]));
            mxb = fmaxf(mxb, fmaxf(c[n][2], c[n][3]));
        }
        mxa = fmaxf(mxa, __shfl_xor_sync(0xFFFFFFFFu, mxa, 1));
        mxa = fmaxf(mxa, __shfl_xor_sync(0xFFFFFFFFu, mxa, 2));
        mxb = fmaxf(mxb, __shfl_xor_sync(0xFFFFFFFFu, mxb, 1));
        mxb = fmaxf(mxb, __shfl_xor_sync(0xFFFFFFFFu, mxb, 2));

        float mna = fmaxf(m_a, mxa), mnb = fmaxf(m_b, mxb);
        float esa = __expf(m_a - mna), esb = __expf(m_b - mnb);
        m_a = mna; m_b = mnb;

        float suma = 0.f, sumb = 0.f;
#pragma unroll
        for (int n = 0; n < 8; n++) {
            c[n][0] = __expf(c[n][0] - mna);
            c[n][1] = __expf(c[n][1] - mna);
            c[n][2] = __expf(c[n][2] - mnb);
            c[n][3] = __expf(c[n][3] - mnb);
            suma += c[n][0] + c[n][1];
            sumb += c[n][2] + c[n][3];
        }
        suma += __shfl_xor_sync(0xFFFFFFFFu, suma, 1);
        suma += __shfl_xor_sync(0xFFFFFFFFu, suma, 2);
        sumb += __shfl_xor_sync(0xFFFFFFFFu, sumb, 1);
        sumb += __shfl_xor_sync(0xFFFFFFFFu, sumb, 2);
        l_a = l_a * esa + suma;
        l_b = l_b * esb + sumb;

#pragma unroll
        for (int j = 0; j < 16; j++) {
            acc[j][0] *= esa; acc[j][1] *= esa;
            acc[j][2] *= esb; acc[j][3] *= esb;
        }

        // ---- PV: P (single fp16) @ (Vh + Vl), 2 mmas per n-tile ----
#pragma unroll
        for (int kc = 0; kc < 4; kc++) {
            uint32_t ph[4];
            ph[0] = packh(c[2*kc][0],   c[2*kc][1]);
            ph[1] = packh(c[2*kc][2],   c[2*kc][3]);
            ph[2] = packh(c[2*kc+1][0], c[2*kc+1][1]);
            ph[3] = packh(c[2*kc+1][2], c[2*kc+1][3]);
#pragma unroll
            for (int j = 0; j < 16; j++) {
                int rv = (j * 8 + g) * FLDV + kc * 8 + tg;
                uint32_t bhf[2] = { wVh[rv], wVh[rv + 4] };
                uint32_t blf[2] = { wVl[rv], wVl[rv + 4] };
                HMMA(acc[j], ph, bhf);
                HMMA(acc[j], ph, blf);
            }
        }
    }

    // ---- normalize + write fp16 hi/lo (b,s,h,d) ----
    float inva = 1.0f / l_a, invb = 1.0f / l_b;
    int rowa = m0 + rowbase + g, rowb = rowa + 8;
#pragma unroll
    for (int j = 0; j < 16; j++) {
        int col = j * 8 + 2 * tg;
        float o0 = acc[j][0] * inva, o1 = acc[j][1] * inva;
        float o2 = acc[j][2] * invb, o3 = acc[j][3] * invb;
        uint32_t h0 = packh(o0, o1), h1 = packh(o2, o3);
        float2 f0 = __half22float2(*(__half2*)&h0);
        float2 f1 = __half22float2(*(__half2*)&h1);
        uint32_t l0 = packh(o0 - f0.x, o1 - f0.y);
        uint32_t l1 = packh(o2 - f1.x, o3 - f1.y);
        size_t da = (((size_t)b * Sc + rowa) * Hc + h) * HDc + col;
        size_t db = (((size_t)b * Sc + rowb) * Hc + h) * HDc + col;
        *(uint32_t*)(atth + da) = h0;
        *(uint32_t*)(attl + da) = l0;
        *(uint32_t*)(atth + db) = h1;
        *(uint32_t*)(attl + db) = l1;
    }
}

// ---------------------------------------------------------------------------
// Launch
// ---------------------------------------------------------------------------
extern "C" void kernel_launch(void* const* d_in, const int* in_sizes, int n_in,
                              void* d_out, int out_size)
{
    const float* x    = (const float*)d_in[0];
    const float* fcos = (const float*)d_in[1];
    const float* fsin = (const float*)d_in[2];
    // d_in[3] = mask (causality handled analytically)
    const float* WAq  = (const float*)d_in[4];
    const float* WAk  = (const float*)d_in[5];
    const float* WAv  = (const float*)d_in[6];
    const float* WBq  = (const float*)d_in[7];
    const float* WBk  = (const float*)d_in[8];
    const float* WBv  = (const float*)d_in[9];
    const float* Wo   = (const float*)d_in[10];
    // d_in[11] = start_pos (0)
    float* out = (float*)d_out;

    __half *gxh, *gxl, *gWT, *gWoT, *gatth, *gattl;
    __half *gqh, *gql, *gk, *gvh, *gvl, *gvTh, *gvTl;
    float *gproj;
    cudaGetSymbolAddress((void**)&gxh,   g_xh);
    cudaGetSymbolAddress((void**)&gxl,   g_xl);
    cudaGetSymbolAddress((void**)&gWT,   g_WT);
    cudaGetSymbolAddress((void**)&gWoT,  g_WoT);
    cudaGetSymbolAddress((void**)&gproj, g_proj);
    cudaGetSymbolAddress((void**)&gqh,   g_qh);
    cudaGetSymbolAddress((void**)&gql,   g_ql);
    cudaGetSymbolAddress((void**)&gk,    g_k);
    cudaGetSymbolAddress((void**)&gvh,   g_vh);
    cudaGetSymbolAddress((void**)&gvl,   g_vl);
    cudaGetSymbolAddress((void**)&gvTh,  g_vTh);
    cudaGetSymbolAddress((void**)&gvTl,  g_vTl);
    cudaGetSymbolAddress((void**)&gatth, g_atth);
    cudaGetSymbolAddress((void**)&gattl, g_attl);

    static int smem_set = 0;
    if (!smem_set) {
        cudaFuncSetAttribute(f16x2_gemm_kernel,
                             cudaFuncAttributeMaxDynamicSharedMemorySize,
                             GSMEM_BYTES);
        cudaFuncSetAttribute(flash_kernel,
                             cudaFuncAttributeMaxDynamicSharedMemorySize,
                             FSMEM_BYTES);
        smem_set = 1;
    }

    const int M = Bc * Sc;   // 4096
    dim3 tsb(32, 8);

    // 0) Split x (fp16 hi/lo); transpose weights to fp16
    {
        long long n4 = (long long)Bc * Sc * Dc / 4;
        splith_kernel<<<(unsigned)((n4 + 255) / 256), 256>>>(x, gxh, gxl, n4);
    }
    tsplit_kernel<<<dim3(192/32,  Dc/32), tsb>>>(WAq, Dc, 192,  gWT, OAq, Dc);
    tsplit_kernel<<<dim3(32/32,   Dc/32), tsb>>>(WAk, Dc, 32,   gWT, OAk, Dc);
    tsplit_kernel<<<dim3(32/32,   Dc/32), tsb>>>(WAv, Dc, 32,   gWT, OAv, Dc);
    tsplit_kernel<<<dim3(1536/32, Dc/32), tsb>>>(WBq, Dc, 1536, gWT, OBq, Dc);
    tsplit_kernel<<<dim3(256/32,  Dc/32), tsb>>>(WBk, Dc, 256,  gWT, OBk, Dc);
    tsplit_kernel<<<dim3(256/32,  Dc/32), tsb>>>(WBv, Dc, 256,  gWT, OBv, Dc);
    tsplit_kernel<<<dim3(Dc/32,   Dc/32), tsb>>>(Wo,  Dc, Dc,   gWoT, 0, Dc);

    // 1) Fused projection GEMM (fp16x2)
    {
        dim3 g(NTOT / GBN, M / GBM);
        f16x2_gemm_kernel<<<g, 256, GSMEM_BYTES>>>(gxh, gxl, gWT,
                                                   gproj, M, NTOT, Dc, NTOT);
    }

    // 2) RoPE on B_q / B_k slices
    {
        long long tq = (long long)Bc * Sc * QRc * (HDc / 2);
        long long tk = (long long)Bc * Sc * Rc  * (HDc / 2);
        rope_kernel<<<(unsigned)((tq + 255) / 256), 256>>>(gproj, OBq, fcos, fsin, QRc, tq);
        rope_kernel<<<(unsigned)((tk + 255) / 256), 256>>>(gproj, OBk, fcos, fsin, Rc,  tk);
    }

    // 3) Rank combine -> fp16 q(hi/lo), k(single), v(hi/lo)
    {
        long long tot = (long long)Bc * Sc * Hc * HDc;
        combine_kernel<<<(unsigned)((tot + 255) / 256), 256>>>(gproj,
            gqh, gql, gk, gvh, gvl);
    }

    // 3b) V transpose -> (b,h,d,s)
    vtrans_kernel<<<dim3(Sc/32, HDc/32, Bc*Hc), tsb>>>(gvh, gvl, gvTh, gvTl);

    // 4) Flash attention (fp16x2) -> att fp16 hi/lo
    {
        dim3 g(Sc / 64, Bc * Hc);
        flash_kernel<<<g, 128, FSMEM_BYTES>>>(gqh, gql, gk, gvTh, gvTl,
                                              gatth, gattl);
    }

    // 5) Output projection (fp16x2) -> d_out
    {
        dim3 g(Dc / GBN, M / GBM);
        f16x2_gemm_kernel<<<g, 256, GSMEM_BYTES>>>(gatth, gattl, gWoT,
                                                   out, M, Dc, Dc, Dc);
    }
}

// round 12
// speedup vs baseline: 6.6413x; 1.2624x over previous
#include <cuda_runtime.h>
#include <cuda_bf16.h>
#include <cuda_fp16.h>
#include <cstdint>

// Problem constants
#define Bc  2
#define Sc  2048
#define Dc  2048
#define Hc  16
#define HDc 128
#define QRc 12
#define Rc  2

// Fused projection column offsets: [WAq | WAk | WAv | WBq | WBk | WBv]
#define NTOT 2304
#define OAq  0
#define OAk  192
#define OAv  224
#define OBq  256
#define OBk  1792
#define OBv  2048

// ---------------------------------------------------------------------------
// Device scratch (no cudaMalloc allowed).
// ---------------------------------------------------------------------------
__device__ __half g_x  [(size_t)Bc*Sc*Dc];            // x as fp16
__device__ __half g_WT [(size_t)NTOT*Dc];             // fused proj weights fp16 [N][K]
__device__ __half g_WoT[(size_t)Dc*Dc];               // Wo^T fp16 [N][K]
__device__ float g_proj[(size_t)Bc*Sc*NTOT];
__device__ __half g_qh [(size_t)Bc*Sc*Hc*HDc];        // (b,s,h,d), scales folded
__device__ __half g_ql [(size_t)Bc*Sc*Hc*HDc];
__device__ __half g_k  [(size_t)Bc*Sc*Hc*HDc];        // single fp16
__device__ __half g_vh [(size_t)Bc*Sc*Hc*HDc];
__device__ __half g_vl [(size_t)Bc*Sc*Hc*HDc];
__device__ __half g_vTh[(size_t)Bc*Hc*HDc*Sc];        // (b,h,d,s)
__device__ __half g_vTl[(size_t)Bc*Hc*HDc*Sc];
__device__ __half g_att[(size_t)Bc*Sc*Hc*HDc];        // flash out, single fp16

// ---------------------------------------------------------------------------
// Helpers
// ---------------------------------------------------------------------------
__device__ __forceinline__ uint32_t s2u(const void* p) {
    return (uint32_t)__cvta_generic_to_shared(p);
}
__device__ __forceinline__ void cp16(uint32_t dst, const void* src) {
    asm volatile("cp.async.cg.shared.global [%0], [%1], 16;\n"
                 :: "r"(dst), "l"(src));
}
__device__ __forceinline__ void hsplit(float f, __half& h, __half& l) {
    h = __float2half_rn(f);
    l = __float2half_rn(f - __half2float(h));
}
__device__ __forceinline__ uint32_t packh(float a, float b) {
    __half2 t = __floats2half2_rn(a, b);
    return *(uint32_t*)&t;
}

// fp16 mma
#define HMMA(d, a, b) asm volatile( \
    "mma.sync.aligned.m16n8k16.row.col.f32.f16.f16.f32 " \
    "{%0,%1,%2,%3}, {%4,%5,%6,%7}, {%8,%9}, {%0,%1,%2,%3};" \
    : "+f"((d)[0]), "+f"((d)[1]), "+f"((d)[2]), "+f"((d)[3]) \
    : "r"((a)[0]), "r"((a)[1]), "r"((a)[2]), "r"((a)[3]), \
      "r"((b)[0]), "r"((b)[1]))

// ---------------------------------------------------------------------------
// Elementwise convert: fp32 -> fp16. n4 = elements/4.
// ---------------------------------------------------------------------------
__global__ void cvt_kernel(const float* __restrict__ src,
                           __half* __restrict__ dst, long long n4)
{
    long long i = (long long)blockIdx.x * blockDim.x + threadIdx.x;
    if (i >= n4) return;
    float4 f = ((const float4*)src)[i];
    ((__half2*)dst)[2*i]   = __floats2half2_rn(f.x, f.y);
    ((__half2*)dst)[2*i+1] = __floats2half2_rn(f.z, f.w);
}

// ---------------------------------------------------------------------------
// Transpose to fp16: W [K][N] fp32 -> fp16 rows (rowOff+n) of [*][ldt].
// ---------------------------------------------------------------------------
__global__ void tsplit_kernel(const float* __restrict__ W, int K, int N,
                              __half* __restrict__ Th, int rowOff, int ldt)
{
    __shared__ float tile[32][33];
    int n0 = blockIdx.x * 32, k0 = blockIdx.y * 32;
    int tx = threadIdx.x, ty = threadIdx.y;
    for (int r = ty; r < 32; r += 8)
        tile[r][tx] = W[(size_t)(k0 + r) * N + n0 + tx];
    __syncthreads();
    for (int r = ty; r < 32; r += 8) {
        int n = n0 + r, k = k0 + tx;
        Th[(size_t)(rowOff + n) * ldt + k] = __float2half_rn(tile[tx][r]);
    }
}

// ---------------------------------------------------------------------------
// Single-mma fp16 tensor-core GEMM: C = A(MxK) @ B^T(NxK)^T, fp32 out.
// Both operands single fp16 (each quantization ~2^-12 relative).
// CTA 256 thr = 8 warps, tile 128x128, K-step 32 halves, warp tile 64x32.
// Requirements: M%128==0, N%128==0, K%32==0.
// ---------------------------------------------------------------------------
#define GBM 128
#define GBN 128
#define GBK 32
#define LDW 20                       // smem words per row (16 data + 4 pad)
#define TW  (128 * LDW)
#define GSMEM_BYTES (2 * 2 * TW * 4) // 40960

__global__ __launch_bounds__(256) void f16_gemm_kernel(
    const __half* __restrict__ Ah, const __half* __restrict__ Bh,
    float* __restrict__ C, int M, int N, int K, int ldc)
{
    extern __shared__ uint32_t gs[];

    int m0 = blockIdx.y * GBM;
    int n0 = blockIdx.x * GBN;
    int tid = threadIdx.x, warp = tid >> 5, lane = tid & 31;
    int wm = warp >> 2, wn = warp & 3;      // 2 x 4 warp grid
    int g  = lane >> 2, tg = lane & 3;

    float acc[4][4][4];
#pragma unroll
    for (int i = 0; i < 4; i++)
#pragma unroll
        for (int j = 0; j < 4; j++)
#pragma unroll
            for (int c = 0; c < 4; c++) acc[i][j][c] = 0.f;

    auto stage = [&](int kt, int buf) {
        uint32_t* base = gs + buf * 2 * TW;
        const __half* srcs[2] = {Ah, Bh};
#pragma unroll
        for (int t = 0; t < 2; t++) {
            const __half* S = srcs[t];
            int r0 = (t < 1) ? m0 : n0;
            uint32_t* dst = base + t * TW;
#pragma unroll
            for (int l = 0; l < 2; l++) {
                int v = tid + l * 256;
                int row = v >> 2, cq = v & 3;   // 4 x 16B chunks per row
                cp16(s2u(dst + row * LDW + cq * 4),
                     S + (size_t)(r0 + row) * K + kt + cq * 8);
            }
        }
    };

    stage(0, 0);
    asm volatile("cp.async.commit_group;");

    int buf = 0;
    for (int kt = 0; kt < K; kt += GBK, buf ^= 1) {
        if (kt + GBK < K) {
            stage(kt + GBK, buf ^ 1);
            asm volatile("cp.async.commit_group;");
            asm volatile("cp.async.wait_group 1;");
        } else {
            asm volatile("cp.async.wait_group 0;");
        }
        __syncthreads();

        const uint32_t* cA = gs + buf * 2 * TW;
        const uint32_t* cB = cA + TW;

#pragma unroll
        for (int ks = 0; ks < 2; ks++) {
            int kw = ks * 8;
            uint32_t ah[4][4], bh[4][2];
#pragma unroll
            for (int i = 0; i < 4; i++) {
                int b0 = (wm * 64 + i * 16 + g) * LDW + kw + tg;
                int b1 = b0 + 8 * LDW;
                ah[i][0] = cA[b0]; ah[i][1] = cA[b1];
                ah[i][2] = cA[b0 + 4]; ah[i][3] = cA[b1 + 4];
            }
#pragma unroll
            for (int j = 0; j < 4; j++) {
                int bb = (wn * 32 + j * 8 + g) * LDW + kw + tg;
                bh[j][0] = cB[bb]; bh[j][1] = cB[bb + 4];
            }
#pragma unroll
            for (int i = 0; i < 4; i++)
#pragma unroll
                for (int j = 0; j < 4; j++)
                    HMMA(acc[i][j], ah[i], bh[j]);
        }
        __syncthreads();
    }

#pragma unroll
    for (int i = 0; i < 4; i++) {
        int row = m0 + wm * 64 + i * 16 + g;
#pragma unroll
        for (int j = 0; j < 4; j++) {
            int col = n0 + wn * 32 + j * 8 + 2 * tg;
            *(float2*)(C + (size_t)row * ldc + col) =
                make_float2(acc[i][j][0], acc[i][j][1]);
            *(float2*)(C + (size_t)(row + 8) * ldc + col) =
                make_float2(acc[i][j][2], acc[i][j][3]);
        }
    }
}

// ---------------------------------------------------------------------------
// Interleaved RoPE in-place on a column slice of g_proj.
// ---------------------------------------------------------------------------
__global__ void rope_kernel(float* __restrict__ proj, int colOff,
                            const float* __restrict__ fcos,
                            const float* __restrict__ fsin,
                            int Rdim, long long total)
{
    long long idx = (long long)blockIdx.x * blockDim.x + threadIdx.x;
    if (idx >= total) return;
    int i = (int)(idx % (HDc / 2));
    long long sr = idx / (HDc / 2);
    long long bs = sr / Rdim;
    int r = (int)(sr % Rdim);
    long long s = bs % Sc;
    float c  = fcos[s * (HDc / 2) + i];
    float sn = fsin[s * (HDc / 2) + i];
    float* p = proj + bs * NTOT + colOff + r * HDc + 2 * i;
    float t0 = p[0], t1 = p[1];
    p[0] = t0 * c - t1 * sn;
    p[1] = t0 * sn + t1 * c;
}

// ---------------------------------------------------------------------------
// Rank combine -> q (fp16 hi/lo), k (single fp16), v (fp16 hi/lo), (b,s,h,d).
// Scales folded; q also carries 1/sqrt(HD).
// ---------------------------------------------------------------------------
__global__ void combine_kernel(const float* __restrict__ proj,
                               __half* __restrict__ qh, __half* __restrict__ ql,
                               __half* __restrict__ k,
                               __half* __restrict__ vh, __half* __restrict__ vl)
{
    long long idx = (long long)blockIdx.x * blockDim.x + threadIdx.x;
    const long long total = (long long)Bc * Sc * Hc * HDc;
    if (idx >= total) return;
    int d = (int)(idx % HDc);
    int h = (int)((idx / HDc) % Hc);
    long long bs = idx / ((long long)HDc * Hc);
    const float* row = proj + bs * NTOT;

    float accq = 0.f;
#pragma unroll
    for (int r = 0; r < QRc; r++)
        accq += row[OAq + h * QRc + r] * row[OBq + r * HDc + d];
    accq *= (1.0f / QRc) * 0.08838834764831845f;   // 1/QR * 1/sqrt(HD)
    __half hh, ll;
    hsplit(accq, hh, ll); qh[idx] = hh; ql[idx] = ll;

    float acck = 0.f, accv = 0.f;
#pragma unroll
    for (int r = 0; r < Rc; r++) {
        acck += row[OAk + h * Rc + r] * row[OBk + r * HDc + d];
        accv += row[OAv + h * Rc + r] * row[OBv + r * HDc + d];
    }
    k[idx] = __float2half_rn(acck * (1.0f / Rc));
    hsplit(accv * (1.0f / Rc), hh, ll); vh[idx] = hh; vl[idx] = ll;
}

// ---------------------------------------------------------------------------
// V transpose: (b,s,h,d) -> (b,h,d,s), fp16 hi+lo.
// ---------------------------------------------------------------------------
__global__ void vtrans_kernel(const __half* __restrict__ vh,
                              const __half* __restrict__ vl,
                              __half* __restrict__ vTh,
                              __half* __restrict__ vTl)
{
    __shared__ __half th[32][34];
    __shared__ __half tl[32][34];
    int s0 = blockIdx.x * 32, d0 = blockIdx.y * 32;
    int bh = blockIdx.z;
    int b = bh / Hc, h = bh % Hc;
    int tx = threadIdx.x, ty = threadIdx.y;
    for (int r = ty; r < 32; r += 8) {
        size_t src = (((size_t)b * Sc + s0 + r) * Hc + h) * HDc + d0 + tx;
        th[r][tx] = vh[src];
        tl[r][tx] = vl[src];
    }
    __syncthreads();
    for (int r = ty; r < 32; r += 8) {
        size_t dst = ((size_t)bh * HDc + d0 + r) * Sc + s0 + tx;
        vTh[dst] = th[tx][r];
        vTl[dst] = tl[tx][r];
    }
}

// ---------------------------------------------------------------------------
// Fused causal flash attention, fp16x2 tensor cores (round-11 validated).
// Only change: epilogue writes single fp16 att (out GEMM quantizes A anyway).
// ---------------------------------------------------------------------------
#define FLDQ 68
#define FLDV 36
#define FQW  (64 * FLDQ)             // 4352 words
#define FVW  (128 * FLDV)            // 4608 words
#define FSMEM_BYTES ((3 * FQW + 2 * FVW) * 4)   // 89088

__global__ __launch_bounds__(128) void flash_kernel(
    const __half* __restrict__ qh, const __half* __restrict__ ql,
    const __half* __restrict__ kk_,
    const __half* __restrict__ vTh, const __half* __restrict__ vTl,
    __half* __restrict__ att)
{
    extern __shared__ uint32_t fs[];
    uint32_t* wQh = fs;
    uint32_t* wQl = wQh + FQW;
    uint32_t* wK  = wQl + FQW;
    uint32_t* wVh = wK + FQW;
    uint32_t* wVl = wVh + FVW;

    int mt = gridDim.x - 1 - blockIdx.x;     // long blocks first
    int m0 = mt * 64;
    int bh = blockIdx.y;
    int b  = bh / Hc, h = bh % Hc;

    int tid  = threadIdx.x;
    int warp = tid >> 5, lane = tid & 31;
    int g = lane >> 2, tg = lane & 3;
    int rowbase = warp * 16;

    // ---- stage Q (once), fully drained ----
#pragma unroll
    for (int l = 0; l < 8; l++) {
        int v = tid + l * 128;                // 1024 chunks: 64 rows x 16
        int row = v >> 4, cq = v & 15;
        size_t src = (((size_t)b * Sc + m0 + row) * Hc + h) * HDc + cq * 8;
        cp16(s2u(wQh + row * FLDQ + cq * 4), qh + src);
        cp16(s2u(wQl + row * FLDQ + cq * 4), ql + src);
    }
    asm volatile("cp.async.commit_group;");
    asm volatile("cp.async.wait_group 0;");
    __syncthreads();

    float acc[16][4];
#pragma unroll
    for (int j = 0; j < 16; j++)
#pragma unroll
        for (int c = 0; c < 4; c++) acc[j][c] = 0.f;
    float m_a = -1e30f, m_b = -1e30f, l_a = 0.f, l_b = 0.f;

    for (int t = 0; t <= mt; t++) {
        int n0 = t * 64;

        __syncthreads();                     // previous iter done with K/V smem
        // ---- stage K tile (single fp16) ----
#pragma unroll
        for (int l = 0; l < 8; l++) {
            int v = tid + l * 128;
            int row = v >> 4, cq = v & 15;
            size_t src = (((size_t)b * Sc + n0 + row) * Hc + h) * HDc + cq * 8;
            cp16(s2u(wK + row * FLDQ + cq * 4), kk_ + src);
        }
        // ---- stage V tile (transposed source, hi/lo) ----
#pragma unroll
        for (int l = 0; l < 8; l++) {
            int v = tid + l * 128;            // 1024 chunks: 128 rows x 8
            int row = v >> 3, cq = v & 7;
            size_t src = ((size_t)bh * HDc + row) * Sc + n0 + cq * 8;
            cp16(s2u(wVh + row * FLDV + cq * 4), vTh + src);
            cp16(s2u(wVl + row * FLDV + cq * 4), vTl + src);
        }
        asm volatile("cp.async.commit_group;");
        asm volatile("cp.async.wait_group 0;");
        __syncthreads();

        // ---- S = (Qh + Ql) K^T, 8 n-tiles of n8, 2 mmas each ----
        float c[8][4];
#pragma unroll
        for (int n = 0; n < 8; n++)
#pragma unroll
            for (int i = 0; i < 4; i++) c[n][i] = 0.f;

#pragma unroll
        for (int kk = 0; kk < 8; kk++) {
            uint32_t ah[4], al[4];
            int ra = (rowbase + g) * FLDQ + kk * 8 + tg;
            int rb = (rowbase + g + 8) * FLDQ + kk * 8 + tg;
            ah[0] = wQh[ra]; ah[1] = wQh[rb]; ah[2] = wQh[ra + 4]; ah[3] = wQh[rb + 4];
            al[0] = wQl[ra]; al[1] = wQl[rb]; al[2] = wQl[ra + 4]; al[3] = wQl[rb + 4];
#pragma unroll
            for (int n = 0; n < 8; n++) {
                int rk = (n * 8 + g) * FLDQ + kk * 8 + tg;
                uint32_t bf[2] = { wK[rk], wK[rk + 4] };
                HMMA(c[n], ah, bf);
                HMMA(c[n], al, bf);
            }
        }

        // ---- causal mask on the diagonal tile ----
        if (t == mt) {
            int ra = rowbase + g, rb = ra + 8;
#pragma unroll
            for (int n = 0; n < 8; n++) {
                int c0 = n * 8 + 2 * tg, c1 = c0 + 1;
                if (c0 > ra) c[n][0] = -1e30f;
                if (c1 > ra) c[n][1] = -1e30f;
                if (c0 > rb) c[n][2] = -1e30f;
                if (c1 > rb) c[n][3] = -1e30f;
            }
        }

        // ---- online softmax (rows g and g+8 of this warp) ----
        float mxa = -1e30f, mxb = -1e30f;
#pragma unroll
        for (int n = 0; n < 8; n++) {
            mxa = fmaxf(mxa, fmaxf(c[n][0], c[n][1]));
            mxb = fmaxf(mxb, fmaxf(c[n][2], c[n][3]));
        }
        mxa = fmaxf(mxa, __shfl_xor_sync(0xFFFFFFFFu, mxa, 1));
        mxa = fmaxf(mxa, __shfl_xor_sync(0xFFFFFFFFu, mxa, 2));
        mxb = fmaxf(mxb, __shfl_xor_sync(0xFFFFFFFFu, mxb, 1));
        mxb = fmaxf(mxb, __shfl_xor_sync(0xFFFFFFFFu, mxb, 2));

        float mna = fmaxf(m_a, mxa), mnb = fmaxf(m_b, mxb);
        float esa = __expf(m_a - mna), esb = __expf(m_b - mnb);
        m_a = mna; m_b = mnb;

        float suma = 0.f, sumb = 0.f;
#pragma unroll
        for (int n = 0; n < 8; n++) {
            c[n][0] = __expf(c[n][0] - mna);
            c[n][1] = __expf(c[n][1] - mna);
            c[n][2] = __expf(c[n][2] - mnb);
            c[n][3] = __expf(c[n][3] - mnb);
            suma += c[n][0] + c[n][1];
            sumb += c[n][2] + c[n][3];
        }
        suma += __shfl_xor_sync(0xFFFFFFFFu, suma, 1);
        suma += __shfl_xor_sync(0xFFFFFFFFu, suma, 2);
        sumb += __shfl_xor_sync(0xFFFFFFFFu, sumb, 1);
        sumb += __shfl_xor_sync(0xFFFFFFFFu, sumb, 2);
        l_a = l_a * esa + suma;
        l_b = l_b * esb + sumb;

#pragma unroll
        for (int j = 0; j < 16; j++) {
            acc[j][0] *= esa; acc[j][1] *= esa;
            acc[j][2] *= esb; acc[j][3] *= esb;
        }

        // ---- PV: P (single fp16) @ (Vh + Vl), 2 mmas per n-tile ----
#pragma unroll
        for (int kc = 0; kc < 4; kc++) {
            uint32_t ph[4];
            ph[0] = packh(c[2*kc][0],   c[2*kc][1]);
            ph[1] = packh(c[2*kc][2],   c[2*kc][3]);
            ph[2] = packh(c[2*kc+1][0], c[2*kc+1][1]);
            ph[3] = packh(c[2*kc+1][2], c[2*kc+1][3]);
#pragma unroll
            for (int j = 0; j < 16; j++) {
                int rv = (j * 8 + g) * FLDV + kc * 8 + tg;
                uint32_t bhf[2] = { wVh[rv], wVh[rv + 4] };
                uint32_t blf[2] = { wVl[rv], wVl[rv + 4] };
                HMMA(acc[j], ph, bhf);
                HMMA(acc[j], ph, blf);
            }
        }
    }

    // ---- normalize + write single fp16 (b,s,h,d) ----
    float inva = 1.0f / l_a, invb = 1.0f / l_b;
    int rowa = m0 + rowbase + g, rowb = rowa + 8;
#pragma unroll
    for (int j = 0; j < 16; j++) {
        int col = j * 8 + 2 * tg;
        uint32_t h0 = packh(acc[j][0] * inva, acc[j][1] * inva);
        uint32_t h1 = packh(acc[j][2] * invb, acc[j][3] * invb);
        size_t da = (((size_t)b * Sc + rowa) * Hc + h) * HDc + col;
        size_t db = (((size_t)b * Sc + rowb) * Hc + h) * HDc + col;
        *(uint32_t*)(att + da) = h0;
        *(uint32_t*)(att + db) = h1;
    }
}

// ---------------------------------------------------------------------------
// Launch
// ---------------------------------------------------------------------------
extern "C" void kernel_launch(void* const* d_in, const int* in_sizes, int n_in,
                              void* d_out, int out_size)
{
    const float* x    = (const float*)d_in[0];
    const float* fcos = (const float*)d_in[1];
    const float* fsin = (const float*)d_in[2];
    // d_in[3] = mask (causality handled analytically)
    const float* WAq  = (const float*)d_in[4];
    const float* WAk  = (const float*)d_in[5];
    const float* WAv  = (const float*)d_in[6];
    const float* WBq  = (const float*)d_in[7];
    const float* WBk  = (const float*)d_in[8];
    const float* WBv  = (const float*)d_in[9];
    const float* Wo   = (const float*)d_in[10];
    // d_in[11] = start_pos (0)
    float* out = (float*)d_out;

    __half *gx, *gWT, *gWoT, *gatt;
    __half *gqh, *gql, *gk, *gvh, *gvl, *gvTh, *gvTl;
    float *gproj;
    cudaGetSymbolAddress((void**)&gx,    g_x);
    cudaGetSymbolAddress((void**)&gWT,   g_WT);
    cudaGetSymbolAddress((void**)&gWoT,  g_WoT);
    cudaGetSymbolAddress((void**)&gproj, g_proj);
    cudaGetSymbolAddress((void**)&gqh,   g_qh);
    cudaGetSymbolAddress((void**)&gql,   g_ql);
    cudaGetSymbolAddress((void**)&gk,    g_k);
    cudaGetSymbolAddress((void**)&gvh,   g_vh);
    cudaGetSymbolAddress((void**)&gvl,   g_vl);
    cudaGetSymbolAddress((void**)&gvTh,  g_vTh);
    cudaGetSymbolAddress((void**)&gvTl,  g_vTl);
    cudaGetSymbolAddress((void**)&gatt,  g_att);

    static int smem_set = 0;
    if (!smem_set) {
        cudaFuncSetAttribute(f16_gemm_kernel,
                             cudaFuncAttributeMaxDynamicSharedMemorySize,
                             GSMEM_BYTES);
        cudaFuncSetAttribute(flash_kernel,
                             cudaFuncAttributeMaxDynamicSharedMemorySize,
                             FSMEM_BYTES);
        smem_set = 1;
    }

    const int M = Bc * Sc;   // 4096
    dim3 tsb(32, 8);

    // 0) Convert x to fp16; transpose weights to fp16
    {
        long long n4 = (long long)Bc * Sc * Dc / 4;
        cvt_kernel<<<(unsigned)((n4 + 255) / 256), 256>>>(x, gx, n4);
    }
    tsplit_kernel<<<dim3(192/32,  Dc/32), tsb>>>(WAq, Dc, 192,  gWT, OAq, Dc);
    tsplit_kernel<<<dim3(32/32,   Dc/32), tsb>>>(WAk, Dc, 32,   gWT, OAk, Dc);
    tsplit_kernel<<<dim3(32/32,   Dc/32), tsb>>>(WAv, Dc, 32,   gWT, OAv, Dc);
    tsplit_kernel<<<dim3(1536/32, Dc/32), tsb>>>(WBq, Dc, 1536, gWT, OBq, Dc);
    tsplit_kernel<<<dim3(256/32,  Dc/32), tsb>>>(WBk, Dc, 256,  gWT, OBk, Dc);
    tsplit_kernel<<<dim3(256/32,  Dc/32), tsb>>>(WBv, Dc, 256,  gWT, OBv, Dc);
    tsplit_kernel<<<dim3(Dc/32,   Dc/32), tsb>>>(Wo,  Dc, Dc,   gWoT, 0, Dc);

    // 1) Fused projection GEMM (single-mma fp16)
    {
        dim3 g(NTOT / GBN, M / GBM);
        f16_gemm_kernel<<<g, 256, GSMEM_BYTES>>>(gx, gWT, gproj, M, NTOT, Dc, NTOT);
    }

    // 2) RoPE on B_q / B_k slices
    {
        long long tq = (long long)Bc * Sc * QRc * (HDc / 2);
        long long tk = (long long)Bc * Sc * Rc  * (HDc / 2);
        rope_kernel<<<(unsigned)((tq + 255) / 256), 256>>>(gproj, OBq, fcos, fsin, QRc, tq);
        rope_kernel<<<(unsigned)((tk + 255) / 256), 256>>>(gproj, OBk, fcos, fsin, Rc,  tk);
    }

    // 3) Rank combine -> fp16 q(hi/lo), k(single), v(hi/lo)
    {
        long long tot = (long long)Bc * Sc * Hc * HDc;
        combine_kernel<<<(unsigned)((tot + 255) / 256), 256>>>(gproj,
            gqh, gql, gk, gvh, gvl);
    }

    // 3b) V transpose -> (b,h,d,s)
    vtrans_kernel<<<dim3(Sc/32, HDc/32, Bc*Hc), tsb>>>(gvh, gvl, gvTh, gvTl);

    // 4) Flash attention (fp16x2) -> att single fp16
    {
        dim3 g(Sc / 64, Bc * Hc);
        flash_kernel<<<g, 128, FSMEM_BYTES>>>(gqh, gql, gk, gvTh, gvTl, gatt);
    }

    // 5) Output projection (single-mma fp16) -> d_out
    {
        dim3 g(Dc / GBN, M / GBM);
        f16_gemm_kernel<<<g, 256, GSMEM_BYTES>>>(gatt, gWoT, out, M, Dc, Dc, Dc);
    }
}

// round 13
// speedup vs baseline: 7.7830x; 1.1719x over previous
#include <cuda_runtime.h>
#include <cuda_bf16.h>
#include <cuda_fp16.h>
#include <cstdint>

// Problem constants
#define Bc  2
#define Sc  2048
#define Dc  2048
#define Hc  16
#define HDc 128
#define QRc 12
#define Rc  2

// Fused projection column offsets: [WAq | WAk | WAv | WBq | WBk | WBv]
#define NTOT 2304
#define OAq  0
#define OAk  192
#define OAv  224
#define OBq  256
#define OBk  1792
#define OBv  2048

// ---------------------------------------------------------------------------
// Device scratch (no cudaMalloc allowed).
// ---------------------------------------------------------------------------
__device__ __half g_x  [(size_t)Bc*Sc*Dc];            // x as fp16
__device__ __half g_WT [(size_t)NTOT*Dc];             // fused proj weights fp16 [N][K]
__device__ __half g_WoT[(size_t)Dc*Dc];               // Wo^T fp16 [N][K]
__device__ float g_proj[(size_t)Bc*Sc*NTOT];
__device__ __half g_q  [(size_t)Bc*Sc*Hc*HDc];        // (b,s,h,d), scales folded
__device__ __half g_k  [(size_t)Bc*Sc*Hc*HDc];
__device__ __half g_v  [(size_t)Bc*Sc*Hc*HDc];
__device__ __half g_vT [(size_t)Bc*Hc*HDc*Sc];        // (b,h,d,s)
__device__ __half g_att[(size_t)Bc*Sc*Hc*HDc];        // flash out, fp16

// ---------------------------------------------------------------------------
// Helpers
// ---------------------------------------------------------------------------
__device__ __forceinline__ uint32_t s2u(const void* p) {
    return (uint32_t)__cvta_generic_to_shared(p);
}
__device__ __forceinline__ void cp16(uint32_t dst, const void* src) {
    asm volatile("cp.async.cg.shared.global [%0], [%1], 16;\n"
                 :: "r"(dst), "l"(src));
}
__device__ __forceinline__ uint32_t packh(float a, float b) {
    __half2 t = __floats2half2_rn(a, b);
    return *(uint32_t*)&t;
}

// fp16 mma
#define HMMA(d, a, b) asm volatile( \
    "mma.sync.aligned.m16n8k16.row.col.f32.f16.f16.f32 " \
    "{%0,%1,%2,%3}, {%4,%5,%6,%7}, {%8,%9}, {%0,%1,%2,%3};" \
    : "+f"((d)[0]), "+f"((d)[1]), "+f"((d)[2]), "+f"((d)[3]) \
    : "r"((a)[0]), "r"((a)[1]), "r"((a)[2]), "r"((a)[3]), \
      "r"((b)[0]), "r"((b)[1]))

// ---------------------------------------------------------------------------
// Elementwise convert: fp32 -> fp16. n4 = elements/4.
// ---------------------------------------------------------------------------
__global__ void cvt_kernel(const float* __restrict__ src,
                           __half* __restrict__ dst, long long n4)
{
    long long i = (long long)blockIdx.x * blockDim.x + threadIdx.x;
    if (i >= n4) return;
    float4 f = ((const float4*)src)[i];
    ((__half2*)dst)[2*i]   = __floats2half2_rn(f.x, f.y);
    ((__half2*)dst)[2*i+1] = __floats2half2_rn(f.z, f.w);
}

// ---------------------------------------------------------------------------
// Transpose to fp16: W [K][N] fp32 -> fp16 rows (rowOff+n) of [*][ldt].
// ---------------------------------------------------------------------------
__global__ void tsplit_kernel(const float* __restrict__ W, int K, int N,
                              __half* __restrict__ Th, int rowOff, int ldt)
{
    __shared__ float tile[32][33];
    int n0 = blockIdx.x * 32, k0 = blockIdx.y * 32;
    int tx = threadIdx.x, ty = threadIdx.y;
    for (int r = ty; r < 32; r += 8)
        tile[r][tx] = W[(size_t)(k0 + r) * N + n0 + tx];
    __syncthreads();
    for (int r = ty; r < 32; r += 8) {
        int n = n0 + r, k = k0 + tx;
        Th[(size_t)(rowOff + n) * ldt + k] = __float2half_rn(tile[tx][r]);
    }
}

// ---------------------------------------------------------------------------
// Single-mma fp16 tensor-core GEMM (validated round 12, unchanged).
// ---------------------------------------------------------------------------
#define GBM 128
#define GBN 128
#define GBK 32
#define LDW 20
#define TW  (128 * LDW)
#define GSMEM_BYTES (2 * 2 * TW * 4) // 40960

__global__ __launch_bounds__(256) void f16_gemm_kernel(
    const __half* __restrict__ Ah, const __half* __restrict__ Bh,
    float* __restrict__ C, int M, int N, int K, int ldc)
{
    extern __shared__ uint32_t gs[];

    int m0 = blockIdx.y * GBM;
    int n0 = blockIdx.x * GBN;
    int tid = threadIdx.x, warp = tid >> 5, lane = tid & 31;
    int wm = warp >> 2, wn = warp & 3;
    int g  = lane >> 2, tg = lane & 3;

    float acc[4][4][4];
#pragma unroll
    for (int i = 0; i < 4; i++)
#pragma unroll
        for (int j = 0; j < 4; j++)
#pragma unroll
            for (int c = 0; c < 4; c++) acc[i][j][c] = 0.f;

    auto stage = [&](int kt, int buf) {
        uint32_t* base = gs + buf * 2 * TW;
        const __half* srcs[2] = {Ah, Bh};
#pragma unroll
        for (int t = 0; t < 2; t++) {
            const __half* S = srcs[t];
            int r0 = (t < 1) ? m0 : n0;
            uint32_t* dst = base + t * TW;
#pragma unroll
            for (int l = 0; l < 2; l++) {
                int v = tid + l * 256;
                int row = v >> 2, cq = v & 3;
                cp16(s2u(dst + row * LDW + cq * 4),
                     S + (size_t)(r0 + row) * K + kt + cq * 8);
            }
        }
    };

    stage(0, 0);
    asm volatile("cp.async.commit_group;");

    int buf = 0;
    for (int kt = 0; kt < K; kt += GBK, buf ^= 1) {
        if (kt + GBK < K) {
            stage(kt + GBK, buf ^ 1);
            asm volatile("cp.async.commit_group;");
            asm volatile("cp.async.wait_group 1;");
        } else {
            asm volatile("cp.async.wait_group 0;");
        }
        __syncthreads();

        const uint32_t* cA = gs + buf * 2 * TW;
        const uint32_t* cB = cA + TW;

#pragma unroll
        for (int ks = 0; ks < 2; ks++) {
            int kw = ks * 8;
            uint32_t ah[4][4], bh[4][2];
#pragma unroll
            for (int i = 0; i < 4; i++) {
                int b0 = (wm * 64 + i * 16 + g) * LDW + kw + tg;
                int b1 = b0 + 8 * LDW;
                ah[i][0] = cA[b0]; ah[i][1] = cA[b1];
                ah[i][2] = cA[b0 + 4]; ah[i][3] = cA[b1 + 4];
            }
#pragma unroll
            for (int j = 0; j < 4; j++) {
                int bb = (wn * 32 + j * 8 + g) * LDW + kw + tg;
                bh[j][0] = cB[bb]; bh[j][1] = cB[bb + 4];
            }
#pragma unroll
            for (int i = 0; i < 4; i++)
#pragma unroll
                for (int j = 0; j < 4; j++)
                    HMMA(acc[i][j], ah[i], bh[j]);
        }
        __syncthreads();
    }

#pragma unroll
    for (int i = 0; i < 4; i++) {
        int row = m0 + wm * 64 + i * 16 + g;
#pragma unroll
        for (int j = 0; j < 4; j++) {
            int col = n0 + wn * 32 + j * 8 + 2 * tg;
            *(float2*)(C + (size_t)row * ldc + col) =
                make_float2(acc[i][j][0], acc[i][j][1]);
            *(float2*)(C + (size_t)(row + 8) * ldc + col) =
                make_float2(acc[i][j][2], acc[i][j][3]);
        }
    }
}

// ---------------------------------------------------------------------------
// Interleaved RoPE in-place on a column slice of g_proj.
// ---------------------------------------------------------------------------
__global__ void rope_kernel(float* __restrict__ proj, int colOff,
                            const float* __restrict__ fcos,
                            const float* __restrict__ fsin,
                            int Rdim, long long total)
{
    long long idx = (long long)blockIdx.x * blockDim.x + threadIdx.x;
    if (idx >= total) return;
    int i = (int)(idx % (HDc / 2));
    long long sr = idx / (HDc / 2);
    long long bs = sr / Rdim;
    int r = (int)(sr % Rdim);
    long long s = bs % Sc;
    float c  = fcos[s * (HDc / 2) + i];
    float sn = fsin[s * (HDc / 2) + i];
    float* p = proj + bs * NTOT + colOff + r * HDc + 2 * i;
    float t0 = p[0], t1 = p[1];
    p[0] = t0 * c - t1 * sn;
    p[1] = t0 * sn + t1 * c;
}

// ---------------------------------------------------------------------------
// Rank combine -> q, k, v all single fp16 (b,s,h,d). Scales folded.
// ---------------------------------------------------------------------------
__global__ void combine_kernel(const float* __restrict__ proj,
                               __half* __restrict__ q, __half* __restrict__ k,
                               __half* __restrict__ v)
{
    long long idx = (long long)blockIdx.x * blockDim.x + threadIdx.x;
    const long long total = (long long)Bc * Sc * Hc * HDc;
    if (idx >= total) return;
    int d = (int)(idx % HDc);
    int h = (int)((idx / HDc) % Hc);
    long long bs = idx / ((long long)HDc * Hc);
    const float* row = proj + bs * NTOT;

    float accq = 0.f;
#pragma unroll
    for (int r = 0; r < QRc; r++)
        accq += row[OAq + h * QRc + r] * row[OBq + r * HDc + d];
    q[idx] = __float2half_rn(accq * (1.0f / QRc) * 0.08838834764831845f);

    float acck = 0.f, accv = 0.f;
#pragma unroll
    for (int r = 0; r < Rc; r++) {
        acck += row[OAk + h * Rc + r] * row[OBk + r * HDc + d];
        accv += row[OAv + h * Rc + r] * row[OBv + r * HDc + d];
    }
    k[idx] = __float2half_rn(acck * (1.0f / Rc));
    v[idx] = __float2half_rn(accv * (1.0f / Rc));
}

// ---------------------------------------------------------------------------
// V transpose: (b,s,h,d) -> (b,h,d,s), fp16.
// ---------------------------------------------------------------------------
__global__ void vtrans_kernel(const __half* __restrict__ v,
                              __half* __restrict__ vT)
{
    __shared__ __half th[32][34];
    int s0 = blockIdx.x * 32, d0 = blockIdx.y * 32;
    int bh = blockIdx.z;
    int b = bh / Hc, h = bh % Hc;
    int tx = threadIdx.x, ty = threadIdx.y;
    for (int r = ty; r < 32; r += 8)
        th[r][tx] = v[(((size_t)b * Sc + s0 + r) * Hc + h) * HDc + d0 + tx];
    __syncthreads();
    for (int r = ty; r < 32; r += 8)
        vT[((size_t)bh * HDc + d0 + r) * Sc + s0 + tx] = th[tx][r];
}

// ---------------------------------------------------------------------------
// Fused causal flash attention, single-mma fp16 tensor cores.
// CTA: 128 threads (4 warps). Tile 64 q-rows x 64 keys, HD=128.
// S = Q*K (1 mma), PV = P*V (1 mma). smem 53 KB -> 4 CTAs/SM.
// ---------------------------------------------------------------------------
#define FLDQ 68
#define FLDV 36
#define FQW  (64 * FLDQ)             // 4352 words
#define FVW  (128 * FLDV)            // 4608 words
#define FSMEM_BYTES ((2 * FQW + FVW) * 4)   // 53248

__global__ __launch_bounds__(128) void flash_kernel(
    const __half* __restrict__ q, const __half* __restrict__ kk_,
    const __half* __restrict__ vT, __half* __restrict__ att)
{
    extern __shared__ uint32_t fs[];
    uint32_t* wQ = fs;
    uint32_t* wK = wQ + FQW;
    uint32_t* wV = wK + FQW;

    int mt = gridDim.x - 1 - blockIdx.x;     // long blocks first
    int m0 = mt * 64;
    int bh = blockIdx.y;
    int b  = bh / Hc, h = bh % Hc;

    int tid  = threadIdx.x;
    int warp = tid >> 5, lane = tid & 31;
    int g = lane >> 2, tg = lane & 3;
    int rowbase = warp * 16;

    // ---- stage Q (once), fully drained ----
#pragma unroll
    for (int l = 0; l < 8; l++) {
        int v = tid + l * 128;                // 1024 chunks: 64 rows x 16
        int row = v >> 4, cq = v & 15;
        size_t src = (((size_t)b * Sc + m0 + row) * Hc + h) * HDc + cq * 8;
        cp16(s2u(wQ + row * FLDQ + cq * 4), q + src);
    }
    asm volatile("cp.async.commit_group;");
    asm volatile("cp.async.wait_group 0;");
    __syncthreads();

    float acc[16][4];
#pragma unroll
    for (int j = 0; j < 16; j++)
#pragma unroll
        for (int c = 0; c < 4; c++) acc[j][c] = 0.f;
    float m_a = -1e30f, m_b = -1e30f, l_a = 0.f, l_b = 0.f;

    for (int t = 0; t <= mt; t++) {
        int n0 = t * 64;

        __syncthreads();                     // previous iter done with K/V smem
        // ---- stage K tile ----
#pragma unroll
        for (int l = 0; l < 8; l++) {
            int v = tid + l * 128;
            int row = v >> 4, cq = v & 15;
            size_t src = (((size_t)b * Sc + n0 + row) * Hc + h) * HDc + cq * 8;
            cp16(s2u(wK + row * FLDQ + cq * 4), kk_ + src);
        }
        // ---- stage V tile (transposed source) ----
#pragma unroll
        for (int l = 0; l < 8; l++) {
            int v = tid + l * 128;            // 1024 chunks: 128 rows x 8
            int row = v >> 3, cq = v & 7;
            size_t src = ((size_t)bh * HDc + row) * Sc + n0 + cq * 8;
            cp16(s2u(wV + row * FLDV + cq * 4), vT + src);
        }
        asm volatile("cp.async.commit_group;");
        asm volatile("cp.async.wait_group 0;");
        __syncthreads();

        // ---- S = Q K^T, 8 n-tiles of n8, 1 mma each ----
        float c[8][4];
#pragma unroll
        for (int n = 0; n < 8; n++)
#pragma unroll
            for (int i = 0; i < 4; i++) c[n][i] = 0.f;

#pragma unroll
        for (int kk = 0; kk < 8; kk++) {
            uint32_t ah[4];
            int ra = (rowbase + g) * FLDQ + kk * 8 + tg;
            int rb = (rowbase + g + 8) * FLDQ + kk * 8 + tg;
            ah[0] = wQ[ra]; ah[1] = wQ[rb]; ah[2] = wQ[ra + 4]; ah[3] = wQ[rb + 4];
#pragma unroll
            for (int n = 0; n < 8; n++) {
                int rk = (n * 8 + g) * FLDQ + kk * 8 + tg;
                uint32_t bf[2] = { wK[rk], wK[rk + 4] };
                HMMA(c[n], ah, bf);
            }
        }

        // ---- causal mask on the diagonal tile ----
        if (t == mt) {
            int ra = rowbase + g, rb = ra + 8;
#pragma unroll
            for (int n = 0; n < 8; n++) {
                int c0 = n * 8 + 2 * tg, c1 = c0 + 1;
                if (c0 > ra) c[n][0] = -1e30f;
                if (c1 > ra) c[n][1] = -1e30f;
                if (c0 > rb) c[n][2] = -1e30f;
                if (c1 > rb) c[n][3] = -1e30f;
            }
        }

        // ---- online softmax (rows g and g+8 of this warp) ----
        float mxa = -1e30f, mxb = -1e30f;
#pragma unroll
        for (int n = 0; n < 8; n++) {
            mxa = fmaxf(mxa, fmaxf(c[n][0], c[n][1]));
            mxb = fmaxf(mxb, fmaxf(c[n][2], c[n][3]));
        }
        mxa = fmaxf(mxa, __shfl_xor_sync(0xFFFFFFFFu, mxa, 1));
        mxa = fmaxf(mxa, __shfl_xor_sync(0xFFFFFFFFu, mxa, 2));
        mxb = fmaxf(mxb, __shfl_xor_sync(0xFFFFFFFFu, mxb, 1));
        mxb = fmaxf(mxb, __shfl_xor_sync(0xFFFFFFFFu, mxb, 2));

        float mna = fmaxf(m_a, mxa), mnb = fmaxf(m_b, mxb);
        float esa = __expf(m_a - mna), esb = __expf(m_b - mnb);
        m_a = mna; m_b = mnb;

        float suma = 0.f, sumb = 0.f;
#pragma unroll
        for (int n = 0; n < 8; n++) {
            c[n][0] = __expf(c[n][0] - mna);
            c[n][1] = __expf(c[n][1] - mna);
            c[n][2] = __expf(c[n][2] - mnb);
            c[n][3] = __expf(c[n][3] - mnb);
            suma += c[n][0] + c[n][1];
            sumb += c[n][2] + c[n][3];
        }
        suma += __shfl_xor_sync(0xFFFFFFFFu, suma, 1);
        suma += __shfl_xor_sync(0xFFFFFFFFu, suma, 2);
        sumb += __shfl_xor_sync(0xFFFFFFFFu, sumb, 1);
        sumb += __shfl_xor_sync(0xFFFFFFFFu, sumb, 2);
        l_a = l_a * esa + suma;
        l_b = l_b * esb + sumb;

#pragma unroll
        for (int j = 0; j < 16; j++) {
            acc[j][0] *= esa; acc[j][1] *= esa;
            acc[j][2] *= esb; acc[j][3] *= esb;
        }

        // ---- PV: P (fp16) @ V, 1 mma per n-tile ----
#pragma unroll
        for (int kc = 0; kc < 4; kc++) {
            uint32_t ph[4];
            ph[0] = packh(c[2*kc][0],   c[2*kc][1]);
            ph[1] = packh(c[2*kc][2],   c[2*kc][3]);
            ph[2] = packh(c[2*kc+1][0], c[2*kc+1][1]);
            ph[3] = packh(c[2*kc+1][2], c[2*kc+1][3]);
#pragma unroll
            for (int j = 0; j < 16; j++) {
                int rv = (j * 8 + g) * FLDV + kc * 8 + tg;
                uint32_t bf[2] = { wV[rv], wV[rv + 4] };
                HMMA(acc[j], ph, bf);
            }
        }
    }

    // ---- normalize + write fp16 (b,s,h,d) ----
    float inva = 1.0f / l_a, invb = 1.0f / l_b;
    int rowa = m0 + rowbase + g, rowb = rowa + 8;
#pragma unroll
    for (int j = 0; j < 16; j++) {
        int col = j * 8 + 2 * tg;
        uint32_t h0 = packh(acc[j][0] * inva, acc[j][1] * inva);
        uint32_t h1 = packh(acc[j][2] * invb, acc[j][3] * invb);
        size_t da = (((size_t)b * Sc + rowa) * Hc + h) * HDc + col;
        size_t db = (((size_t)b * Sc + rowb) * Hc + h) * HDc + col;
        *(uint32_t*)(att + da) = h0;
        *(uint32_t*)(att + db) = h1;
    }
}

// ---------------------------------------------------------------------------
// Launch
// ---------------------------------------------------------------------------
extern "C" void kernel_launch(void* const* d_in, const int* in_sizes, int n_in,
                              void* d_out, int out_size)
{
    const float* x    = (const float*)d_in[0];
    const float* fcos = (const float*)d_in[1];
    const float* fsin = (const float*)d_in[2];
    // d_in[3] = mask (causality handled analytically)
    const float* WAq  = (const float*)d_in[4];
    const float* WAk  = (const float*)d_in[5];
    const float* WAv  = (const float*)d_in[6];
    const float* WBq  = (const float*)d_in[7];
    const float* WBk  = (const float*)d_in[8];
    const float* WBv  = (const float*)d_in[9];
    const float* Wo   = (const float*)d_in[10];
    // d_in[11] = start_pos (0)
    float* out = (float*)d_out;

    __half *gx, *gWT, *gWoT, *gatt, *gq, *gk, *gv, *gvT;
    float *gproj;
    cudaGetSymbolAddress((void**)&gx,    g_x);
    cudaGetSymbolAddress((void**)&gWT,   g_WT);
    cudaGetSymbolAddress((void**)&gWoT,  g_WoT);
    cudaGetSymbolAddress((void**)&gproj, g_proj);
    cudaGetSymbolAddress((void**)&gq,    g_q);
    cudaGetSymbolAddress((void**)&gk,    g_k);
    cudaGetSymbolAddress((void**)&gv,    g_v);
    cudaGetSymbolAddress((void**)&gvT,   g_vT);
    cudaGetSymbolAddress((void**)&gatt,  g_att);

    static int smem_set = 0;
    if (!smem_set) {
        cudaFuncSetAttribute(f16_gemm_kernel,
                             cudaFuncAttributeMaxDynamicSharedMemorySize,
                             GSMEM_BYTES);
        cudaFuncSetAttribute(flash_kernel,
                             cudaFuncAttributeMaxDynamicSharedMemorySize,
                             FSMEM_BYTES);
        smem_set = 1;
    }

    const int M = Bc * Sc;   // 4096
    dim3 tsb(32, 8);

    // 0) Convert x to fp16; transpose weights to fp16
    {
        long long n4 = (long long)Bc * Sc * Dc / 4;
        cvt_kernel<<<(unsigned)((n4 + 255) / 256), 256>>>(x, gx, n4);
    }
    tsplit_kernel<<<dim3(192/32,  Dc/32), tsb>>>(WAq, Dc, 192,  gWT, OAq, Dc);
    tsplit_kernel<<<dim3(32/32,   Dc/32), tsb>>>(WAk, Dc, 32,   gWT, OAk, Dc);
    tsplit_kernel<<<dim3(32/32,   Dc/32), tsb>>>(WAv, Dc, 32,   gWT, OAv, Dc);
    tsplit_kernel<<<dim3(1536/32, Dc/32), tsb>>>(WBq, Dc, 1536, gWT, OBq, Dc);
    tsplit_kernel<<<dim3(256/32,  Dc/32), tsb>>>(WBk, Dc, 256,  gWT, OBk, Dc);
    tsplit_kernel<<<dim3(256/32,  Dc/32), tsb>>>(WBv, Dc, 256,  gWT, OBv, Dc);
    tsplit_kernel<<<dim3(Dc/32,   Dc/32), tsb>>>(Wo,  Dc, Dc,   gWoT, 0, Dc);

    // 1) Fused projection GEMM (single-mma fp16)
    {
        dim3 g(NTOT / GBN, M / GBM);
        f16_gemm_kernel<<<g, 256, GSMEM_BYTES>>>(gx, gWT, gproj, M, NTOT, Dc, NTOT);
    }

    // 2) RoPE on B_q / B_k slices
    {
        long long tq = (long long)Bc * Sc * QRc * (HDc / 2);
        long long tk = (long long)Bc * Sc * Rc  * (HDc / 2);
        rope_kernel<<<(unsigned)((tq + 255) / 256), 256>>>(gproj, OBq, fcos, fsin, QRc, tq);
        rope_kernel<<<(unsigned)((tk + 255) / 256), 256>>>(gproj, OBk, fcos, fsin, Rc,  tk);
    }

    // 3) Rank combine -> fp16 q, k, v
    {
        long long tot = (long long)Bc * Sc * Hc * HDc;
        combine_kernel<<<(unsigned)((tot + 255) / 256), 256>>>(gproj, gq, gk, gv);
    }

    // 3b) V transpose -> (b,h,d,s)
    vtrans_kernel<<<dim3(Sc/32, HDc/32, Bc*Hc), tsb>>>(gv, gvT);

    // 4) Flash attention (single-mma fp16) -> att fp16
    {
        dim3 g(Sc / 64, Bc * Hc);
        flash_kernel<<<g, 128, FSMEM_BYTES>>>(gq, gk, gvT, gatt);
    }

    // 5) Output projection (single-mma fp16) -> d_out
    {
        dim3 g(Dc / GBN, M / GBM);
        f16_gemm_kernel<<<g, 256, GSMEM_BYTES>>>(gatt, gWoT, out, M, Dc, Dc, Dc);
    }
}

// round 14
// speedup vs baseline: 7.8369x; 1.0069x over previous
#include <cuda_runtime.h>
#include <cuda_bf16.h>
#include <cuda_fp16.h>
#include <cstdint>

// Problem constants
#define Bc  2
#define Sc  2048
#define Dc  2048
#define Hc  16
#define HDc 128
#define QRc 12
#define Rc  2

// Fused projection column offsets: [WAq | WAk | WAv | WBq | WBk | WBv]
#define NTOT 2304
#define OAq  0
#define OAk  192
#define OAv  224
#define OBq  256
#define OBk  1792
#define OBv  2048

// ---------------------------------------------------------------------------
// Device scratch (no cudaMalloc allowed).
// ---------------------------------------------------------------------------
__device__ __half g_x  [(size_t)Bc*Sc*Dc];
__device__ __half g_WT [(size_t)NTOT*Dc];
__device__ __half g_WoT[(size_t)Dc*Dc];
__device__ float g_proj[(size_t)Bc*Sc*NTOT];
__device__ __half g_q  [(size_t)Bc*Sc*Hc*HDc];
__device__ __half g_k  [(size_t)Bc*Sc*Hc*HDc];
__device__ __half g_v  [(size_t)Bc*Sc*Hc*HDc];
__device__ __half g_vT [(size_t)Bc*Hc*HDc*Sc];
__device__ __half g_att[(size_t)Bc*Sc*Hc*HDc];

// ---------------------------------------------------------------------------
// Helpers
// ---------------------------------------------------------------------------
__device__ __forceinline__ uint32_t s2u(const void* p) {
    return (uint32_t)__cvta_generic_to_shared(p);
}
__device__ __forceinline__ void cp16(uint32_t dst, const void* src) {
    asm volatile("cp.async.cg.shared.global [%0], [%1], 16;\n"
                 :: "r"(dst), "l"(src));
}
__device__ __forceinline__ uint32_t packh(float a, float b) {
    __half2 t = __floats2half2_rn(a, b);
    return *(uint32_t*)&t;
}
// Two fp16 exps in one MUFU op: d = 2^(f16x2 of (a,b))
__device__ __forceinline__ uint32_t ex2h2(float a, float b) {
    uint32_t arg, r;
    asm("cvt.rn.f16x2.f32 %0, %1, %2;" : "=r"(arg) : "f"(b), "f"(a));
    asm("ex2.approx.f16x2 %0, %1;" : "=r"(r) : "r"(arg));
    return r;
}

// fp16 mma
#define HMMA(d, a, b) asm volatile( \
    "mma.sync.aligned.m16n8k16.row.col.f32.f16.f16.f32 " \
    "{%0,%1,%2,%3}, {%4,%5,%6,%7}, {%8,%9}, {%0,%1,%2,%3};" \
    : "+f"((d)[0]), "+f"((d)[1]), "+f"((d)[2]), "+f"((d)[3]) \
    : "r"((a)[0]), "r"((a)[1]), "r"((a)[2]), "r"((a)[3]), \
      "r"((b)[0]), "r"((b)[1]))

// ---------------------------------------------------------------------------
// Elementwise convert: fp32 -> fp16. n4 = elements/4.
// ---------------------------------------------------------------------------
__global__ void cvt_kernel(const float* __restrict__ src,
                           __half* __restrict__ dst, long long n4)
{
    long long i = (long long)blockIdx.x * blockDim.x + threadIdx.x;
    if (i >= n4) return;
    float4 f = ((const float4*)src)[i];
    ((__half2*)dst)[2*i]   = __floats2half2_rn(f.x, f.y);
    ((__half2*)dst)[2*i+1] = __floats2half2_rn(f.z, f.w);
}

// ---------------------------------------------------------------------------
// Merged transpose of ALL weights to fp16 [N][K] rows in one launch.
// Global col-tiles: [WAq|WAk|WAv|WBq|WBk|WBv] -> g_WT rows, [Wo] -> g_WoT.
// grid (136, 64), block (32, 8).
// ---------------------------------------------------------------------------
__global__ void tsplit_all_kernel(const float* __restrict__ W0,
                                  const float* __restrict__ W1,
                                  const float* __restrict__ W2,
                                  const float* __restrict__ W3,
                                  const float* __restrict__ W4,
                                  const float* __restrict__ W5,
                                  const float* __restrict__ W6,
                                  __half* __restrict__ WT,
                                  __half* __restrict__ WoT)
{
    const int segStart[8] = {0, 192, 224, 256, 1792, 2048, 2304, 4352};
    const float* srcs[7]  = {W0, W1, W2, W3, W4, W5, W6};
    const int Ns[7]       = {192, 32, 32, 1536, 256, 256, 2048};

    int cg = blockIdx.x * 32;                // global column
    int seg = 0;
#pragma unroll
    for (int s = 0; s < 6; s++)
        if (cg >= segStart[s + 1]) seg = s + 1;

    const float* W = srcs[seg];
    int N  = Ns[seg];
    int n0 = cg - segStart[seg];             // local column within this weight
    int k0 = blockIdx.y * 32;

    __shared__ float tile[32][33];
    int tx = threadIdx.x, ty = threadIdx.y;
    for (int r = ty; r < 32; r += 8)
        tile[r][tx] = W[(size_t)(k0 + r) * N + n0 + tx];
    __syncthreads();

    if (seg < 6) {
        for (int r = ty; r < 32; r += 8)
            WT[(size_t)(cg + r) * Dc + k0 + tx] = __float2half_rn(tile[tx][r]);
    } else {
        for (int r = ty; r < 32; r += 8)
            WoT[(size_t)(n0 + r) * Dc + k0 + tx] = __float2half_rn(tile[tx][r]);
    }
}

// ---------------------------------------------------------------------------
// Single-mma fp16 tensor-core GEMM (validated round 12, unchanged).
// ---------------------------------------------------------------------------
#define GBM 128
#define GBN 128
#define GBK 32
#define LDW 20
#define TW  (128 * LDW)
#define GSMEM_BYTES (2 * 2 * TW * 4) // 40960

__global__ __launch_bounds__(256) void f16_gemm_kernel(
    const __half* __restrict__ Ah, const __half* __restrict__ Bh,
    float* __restrict__ C, int M, int N, int K, int ldc)
{
    extern __shared__ uint32_t gs[];

    int m0 = blockIdx.y * GBM;
    int n0 = blockIdx.x * GBN;
    int tid = threadIdx.x, warp = tid >> 5, lane = tid & 31;
    int wm = warp >> 2, wn = warp & 3;
    int g  = lane >> 2, tg = lane & 3;

    float acc[4][4][4];
#pragma unroll
    for (int i = 0; i < 4; i++)
#pragma unroll
        for (int j = 0; j < 4; j++)
#pragma unroll
            for (int c = 0; c < 4; c++) acc[i][j][c] = 0.f;

    auto stage = [&](int kt, int buf) {
        uint32_t* base = gs + buf * 2 * TW;
        const __half* srcs[2] = {Ah, Bh};
#pragma unroll
        for (int t = 0; t < 2; t++) {
            const __half* S = srcs[t];
            int r0 = (t < 1) ? m0 : n0;
            uint32_t* dst = base + t * TW;
#pragma unroll
            for (int l = 0; l < 2; l++) {
                int v = tid + l * 256;
                int row = v >> 2, cq = v & 3;
                cp16(s2u(dst + row * LDW + cq * 4),
                     S + (size_t)(r0 + row) * K + kt + cq * 8);
            }
        }
    };

    stage(0, 0);
    asm volatile("cp.async.commit_group;");

    int buf = 0;
    for (int kt = 0; kt < K; kt += GBK, buf ^= 1) {
        if (kt + GBK < K) {
            stage(kt + GBK, buf ^ 1);
            asm volatile("cp.async.commit_group;");
            asm volatile("cp.async.wait_group 1;");
        } else {
            asm volatile("cp.async.wait_group 0;");
        }
        __syncthreads();

        const uint32_t* cA = gs + buf * 2 * TW;
        const uint32_t* cB = cA + TW;

#pragma unroll
        for (int ks = 0; ks < 2; ks++) {
            int kw = ks * 8;
            uint32_t ah[4][4], bh[4][2];
#pragma unroll
            for (int i = 0; i < 4; i++) {
                int b0 = (wm * 64 + i * 16 + g) * LDW + kw + tg;
                int b1 = b0 + 8 * LDW;
                ah[i][0] = cA[b0]; ah[i][1] = cA[b1];
                ah[i][2] = cA[b0 + 4]; ah[i][3] = cA[b1 + 4];
            }
#pragma unroll
            for (int j = 0; j < 4; j++) {
                int bb = (wn * 32 + j * 8 + g) * LDW + kw + tg;
                bh[j][0] = cB[bb]; bh[j][1] = cB[bb + 4];
            }
#pragma unroll
            for (int i = 0; i < 4; i++)
#pragma unroll
                for (int j = 0; j < 4; j++)
                    HMMA(acc[i][j], ah[i], bh[j]);
        }
        __syncthreads();
    }

#pragma unroll
    for (int i = 0; i < 4; i++) {
        int row = m0 + wm * 64 + i * 16 + g;
#pragma unroll
        for (int j = 0; j < 4; j++) {
            int col = n0 + wn * 32 + j * 8 + 2 * tg;
            *(float2*)(C + (size_t)row * ldc + col) =
                make_float2(acc[i][j][0], acc[i][j][1]);
            *(float2*)(C + (size_t)(row + 8) * ldc + col) =
                make_float2(acc[i][j][2], acc[i][j][3]);
        }
    }
}

// ---------------------------------------------------------------------------
// Interleaved RoPE in-place on a column slice of g_proj.
// ---------------------------------------------------------------------------
__global__ void rope_kernel(float* __restrict__ proj, int colOff,
                            const float* __restrict__ fcos,
                            const float* __restrict__ fsin,
                            int Rdim, long long total)
{
    long long idx = (long long)blockIdx.x * blockDim.x + threadIdx.x;
    if (idx >= total) return;
    int i = (int)(idx % (HDc / 2));
    long long sr = idx / (HDc / 2);
    long long bs = sr / Rdim;
    int r = (int)(sr % Rdim);
    long long s = bs % Sc;
    float c  = fcos[s * (HDc / 2) + i];
    float sn = fsin[s * (HDc / 2) + i];
    float* p = proj + bs * NTOT + colOff + r * HDc + 2 * i;
    float t0 = p[0], t1 = p[1];
    p[0] = t0 * c - t1 * sn;
    p[1] = t0 * sn + t1 * c;
}

// ---------------------------------------------------------------------------
// Rank combine -> q, k, v all single fp16 (b,s,h,d). Scales folded.
// ---------------------------------------------------------------------------
__global__ void combine_kernel(const float* __restrict__ proj,
                               __half* __restrict__ q, __half* __restrict__ k,
                               __half* __restrict__ v)
{
    long long idx = (long long)blockIdx.x * blockDim.x + threadIdx.x;
    const long long total = (long long)Bc * Sc * Hc * HDc;
    if (idx >= total) return;
    int d = (int)(idx % HDc);
    int h = (int)((idx / HDc) % Hc);
    long long bs = idx / ((long long)HDc * Hc);
    const float* row = proj + bs * NTOT;

    float accq = 0.f;
#pragma unroll
    for (int r = 0; r < QRc; r++)
        accq += row[OAq + h * QRc + r] * row[OBq + r * HDc + d];
    q[idx] = __float2half_rn(accq * (1.0f / QRc) * 0.08838834764831845f);

    float acck = 0.f, accv = 0.f;
#pragma unroll
    for (int r = 0; r < Rc; r++) {
        acck += row[OAk + h * Rc + r] * row[OBk + r * HDc + d];
        accv += row[OAv + h * Rc + r] * row[OBv + r * HDc + d];
    }
    k[idx] = __float2half_rn(acck * (1.0f / Rc));
    v[idx] = __float2half_rn(accv * (1.0f / Rc));
}

// ---------------------------------------------------------------------------
// V transpose: (b,s,h,d) -> (b,h,d,s), fp16.
// ---------------------------------------------------------------------------
__global__ void vtrans_kernel(const __half* __restrict__ v,
                              __half* __restrict__ vT)
{
    __shared__ __half th[32][34];
    int s0 = blockIdx.x * 32, d0 = blockIdx.y * 32;
    int bh = blockIdx.z;
    int b = bh / Hc, h = bh % Hc;
    int tx = threadIdx.x, ty = threadIdx.y;
    for (int r = ty; r < 32; r += 8)
        th[r][tx] = v[(((size_t)b * Sc + s0 + r) * Hc + h) * HDc + d0 + tx];
    __syncthreads();
    for (int r = ty; r < 32; r += 8)
        vT[((size_t)bh * HDc + d0 + r) * Sc + s0 + tx] = th[tx][r];
}

// ---------------------------------------------------------------------------
// Fused causal flash attention, single-mma fp16 tensor cores.
// Round-14 change: softmax exp via ex2.approx.f16x2 (2 exps / MUFU op);
// P emerges pre-packed for the PV mma; row sums via HADD2.
// ---------------------------------------------------------------------------
#define FLDQ 68
#define FLDV 36
#define FQW  (64 * FLDQ)
#define FVW  (128 * FLDV)
#define FSMEM_BYTES ((2 * FQW + FVW) * 4)   // 53248

__global__ __launch_bounds__(128) void flash_kernel(
    const __half* __restrict__ q, const __half* __restrict__ kk_,
    const __half* __restrict__ vT, __half* __restrict__ att)
{
    extern __shared__ uint32_t fs[];
    uint32_t* wQ = fs;
    uint32_t* wK = wQ + FQW;
    uint32_t* wV = wK + FQW;

    int mt = gridDim.x - 1 - blockIdx.x;     // long blocks first
    int m0 = mt * 64;
    int bh = blockIdx.y;
    int b  = bh / Hc, h = bh % Hc;

    int tid  = threadIdx.x;
    int warp = tid >> 5, lane = tid & 31;
    int g = lane >> 2, tg = lane & 3;
    int rowbase = warp * 16;

    const float L2E = 1.4426950408889634f;

    // ---- stage Q (once), fully drained ----
#pragma unroll
    for (int l = 0; l < 8; l++) {
        int v = tid + l * 128;
        int row = v >> 4, cq = v & 15;
        size_t src = (((size_t)b * Sc + m0 + row) * Hc + h) * HDc + cq * 8;
        cp16(s2u(wQ + row * FLDQ + cq * 4), q + src);
    }
    asm volatile("cp.async.commit_group;");
    asm volatile("cp.async.wait_group 0;");
    __syncthreads();

    float acc[16][4];
#pragma unroll
    for (int j = 0; j < 16; j++)
#pragma unroll
        for (int c = 0; c < 4; c++) acc[j][c] = 0.f;
    float m_a = -1e30f, m_b = -1e30f, l_a = 0.f, l_b = 0.f;

    for (int t = 0; t <= mt; t++) {
        int n0 = t * 64;

        __syncthreads();
#pragma unroll
        for (int l = 0; l < 8; l++) {
            int v = tid + l * 128;
            int row = v >> 4, cq = v & 15;
            size_t src = (((size_t)b * Sc + n0 + row) * Hc + h) * HDc + cq * 8;
            cp16(s2u(wK + row * FLDQ + cq * 4), kk_ + src);
        }
#pragma unroll
        for (int l = 0; l < 8; l++) {
            int v = tid + l * 128;
            int row = v >> 3, cq = v & 7;
            size_t src = ((size_t)bh * HDc + row) * Sc + n0 + cq * 8;
            cp16(s2u(wV + row * FLDV + cq * 4), vT + src);
        }
        asm volatile("cp.async.commit_group;");
        asm volatile("cp.async.wait_group 0;");
        __syncthreads();

        // ---- S = Q K^T, 8 n-tiles of n8, 1 mma each ----
        float c[8][4];
#pragma unroll
        for (int n = 0; n < 8; n++)
#pragma unroll
            for (int i = 0; i < 4; i++) c[n][i] = 0.f;

#pragma unroll
        for (int kk = 0; kk < 8; kk++) {
            uint32_t ah[4];
            int ra = (rowbase + g) * FLDQ + kk * 8 + tg;
            int rb = (rowbase + g + 8) * FLDQ + kk * 8 + tg;
            ah[0] = wQ[ra]; ah[1] = wQ[rb]; ah[2] = wQ[ra + 4]; ah[3] = wQ[rb + 4];
#pragma unroll
            for (int n = 0; n < 8; n++) {
                int rk = (n * 8 + g) * FLDQ + kk * 8 + tg;
                uint32_t bf[2] = { wK[rk], wK[rk + 4] };
                HMMA(c[n], ah, bf);
            }
        }

        // ---- causal mask on the diagonal tile ----
        if (t == mt) {
            int ra = rowbase + g, rb = ra + 8;
#pragma unroll
            for (int n = 0; n < 8; n++) {
                int c0 = n * 8 + 2 * tg, c1 = c0 + 1;
                if (c0 > ra) c[n][0] = -1e30f;
                if (c1 > ra) c[n][1] = -1e30f;
                if (c0 > rb) c[n][2] = -1e30f;
                if (c1 > rb) c[n][3] = -1e30f;
            }
        }

        // ---- online softmax: max in fp32, exp via ex2.f16x2 ----
        float mxa = -1e30f, mxb = -1e30f;
#pragma unroll
        for (int n = 0; n < 8; n++) {
            mxa = fmaxf(mxa, fmaxf(c[n][0], c[n][1]));
            mxb = fmaxf(mxb, fmaxf(c[n][2], c[n][3]));
        }
        mxa = fmaxf(mxa, __shfl_xor_sync(0xFFFFFFFFu, mxa, 1));
        mxa = fmaxf(mxa, __shfl_xor_sync(0xFFFFFFFFu, mxa, 2));
        mxb = fmaxf(mxb, __shfl_xor_sync(0xFFFFFFFFu, mxb, 1));
        mxb = fmaxf(mxb, __shfl_xor_sync(0xFFFFFFFFu, mxb, 2));

        float mna = fmaxf(m_a, mxa), mnb = fmaxf(m_b, mxb);
        float esa = __expf(m_a - mna), esb = __expf(m_b - mnb);
        m_a = mna; m_b = mnb;

        float na = mna * L2E, nb = mnb * L2E;
        uint32_t Pa[8], Pb[8];
        __half2 sa = __floats2half2_rn(0.f, 0.f);
        __half2 sb = sa;
#pragma unroll
        for (int n = 0; n < 8; n++) {
            Pa[n] = ex2h2(fmaf(c[n][0], L2E, -na), fmaf(c[n][1], L2E, -na));
            Pb[n] = ex2h2(fmaf(c[n][2], L2E, -nb), fmaf(c[n][3], L2E, -nb));
            sa = __hadd2(sa, *(__half2*)&Pa[n]);
            sb = __hadd2(sb, *(__half2*)&Pb[n]);
        }
        float2 fa = __half22float2(sa);
        float2 fb = __half22float2(sb);
        float suma = fa.x + fa.y;
        float sumb = fb.x + fb.y;
        suma += __shfl_xor_sync(0xFFFFFFFFu, suma, 1);
        suma += __shfl_xor_sync(0xFFFFFFFFu, suma, 2);
        sumb += __shfl_xor_sync(0xFFFFFFFFu, sumb, 1);
        sumb += __shfl_xor_sync(0xFFFFFFFFu, sumb, 2);
        l_a = l_a * esa + suma;
        l_b = l_b * esb + sumb;

#pragma unroll
        for (int j = 0; j < 16; j++) {
            acc[j][0] *= esa; acc[j][1] *= esa;
            acc[j][2] *= esb; acc[j][3] *= esb;
        }

        // ---- PV: P (pre-packed fp16) @ V, 1 mma per n-tile ----
#pragma unroll
        for (int kc = 0; kc < 4; kc++) {
            uint32_t ph[4] = { Pa[2*kc], Pb[2*kc], Pa[2*kc+1], Pb[2*kc+1] };
#pragma unroll
            for (int j = 0; j < 16; j++) {
                int rv = (j * 8 + g) * FLDV + kc * 8 + tg;
                uint32_t bf[2] = { wV[rv], wV[rv + 4] };
                HMMA(acc[j], ph, bf);
            }
        }
    }

    // ---- normalize + write fp16 (b,s,h,d) ----
    float inva = 1.0f / l_a, invb = 1.0f / l_b;
    int rowa = m0 + rowbase + g, rowb = rowa + 8;
#pragma unroll
    for (int j = 0; j < 16; j++) {
        int col = j * 8 + 2 * tg;
        uint32_t h0 = packh(acc[j][0] * inva, acc[j][1] * inva);
        uint32_t h1 = packh(acc[j][2] * invb, acc[j][3] * invb);
        size_t da = (((size_t)b * Sc + rowa) * Hc + h) * HDc + col;
        size_t db = (((size_t)b * Sc + rowb) * Hc + h) * HDc + col;
        *(uint32_t*)(att + da) = h0;
        *(uint32_t*)(att + db) = h1;
    }
}

// ---------------------------------------------------------------------------
// Launch
// ---------------------------------------------------------------------------
extern "C" void kernel_launch(void* const* d_in, const int* in_sizes, int n_in,
                              void* d_out, int out_size)
{
    const float* x    = (const float*)d_in[0];
    const float* fcos = (const float*)d_in[1];
    const float* fsin = (const float*)d_in[2];
    // d_in[3] = mask (causality handled analytically)
    const float* WAq  = (const float*)d_in[4];
    const float* WAk  = (const float*)d_in[5];
    const float* WAv  = (const float*)d_in[6];
    const float* WBq  = (const float*)d_in[7];
    const float* WBk  = (const float*)d_in[8];
    const float* WBv  = (const float*)d_in[9];
    const float* Wo   = (const float*)d_in[10];
    // d_in[11] = start_pos (0)
    float* out = (float*)d_out;

    __half *gx, *gWT, *gWoT, *gatt, *gq, *gk, *gv, *gvT;
    float *gproj;
    cudaGetSymbolAddress((void**)&gx,    g_x);
    cudaGetSymbolAddress((void**)&gWT,   g_WT);
    cudaGetSymbolAddress((void**)&gWoT,  g_WoT);
    cudaGetSymbolAddress((void**)&gproj, g_proj);
    cudaGetSymbolAddress((void**)&gq,    g_q);
    cudaGetSymbolAddress((void**)&gk,    g_k);
    cudaGetSymbolAddress((void**)&gv,    g_v);
    cudaGetSymbolAddress((void**)&gvT,   g_vT);
    cudaGetSymbolAddress((void**)&gatt,  g_att);

    static int smem_set = 0;
    if (!smem_set) {
        cudaFuncSetAttribute(f16_gemm_kernel,
                             cudaFuncAttributeMaxDynamicSharedMemorySize,
                             GSMEM_BYTES);
        cudaFuncSetAttribute(flash_kernel,
                             cudaFuncAttributeMaxDynamicSharedMemorySize,
                             FSMEM_BYTES);
        smem_set = 1;
    }

    const int M = Bc * Sc;   // 4096
    dim3 tsb(32, 8);

    // 0) Convert x to fp16; transpose ALL weights in one launch
    {
        long long n4 = (long long)Bc * Sc * Dc / 4;
        cvt_kernel<<<(unsigned)((n4 + 255) / 256), 256>>>(x, gx, n4);
    }
    tsplit_all_kernel<<<dim3(136, 64), tsb>>>(WAq, WAk, WAv, WBq, WBk, WBv, Wo,
                                              gWT, gWoT);

    // 1) Fused projection GEMM (single-mma fp16)
    {
        dim3 g(NTOT / GBN, M / GBM);
        f16_gemm_kernel<<<g, 256, GSMEM_BYTES>>>(gx, gWT, gproj, M, NTOT, Dc, NTOT);
    }

    // 2) RoPE on B_q / B_k slices
    {
        long long tq = (long long)Bc * Sc * QRc * (HDc / 2);
        long long tk = (long long)Bc * Sc * Rc  * (HDc / 2);
        rope_kernel<<<(unsigned)((tq + 255) / 256), 256>>>(gproj, OBq, fcos, fsin, QRc, tq);
        rope_kernel<<<(unsigned)((tk + 255) / 256), 256>>>(gproj, OBk, fcos, fsin, Rc,  tk);
    }

    // 3) Rank combine -> fp16 q, k, v
    {
        long long tot = (long long)Bc * Sc * Hc * HDc;
        combine_kernel<<<(unsigned)((tot + 255) / 256), 256>>>(gproj, gq, gk, gv);
    }

    // 3b) V transpose -> (b,h,d,s)
    vtrans_kernel<<<dim3(Sc/32, HDc/32, Bc*Hc), tsb>>>(gv, gvT);

    // 4) Flash attention (single-mma fp16, f16x2 exp) -> att fp16
    {
        dim3 g(Sc / 64, Bc * Hc);
        flash_kernel<<<g, 128, FSMEM_BYTES>>>(gq, gk, gvT, gatt);
    }

    // 5) Output projection (single-mma fp16) -> d_out
    {
        dim3 g(Dc / GBN, M / GBM);
        f16_gemm_kernel<<<g, 256, GSMEM_BYTES>>>(gatt, gWoT, out, M, Dc, Dc, Dc);
    }
}